// round 7
// baseline (speedup 1.0000x reference)
#include <cuda_runtime.h>
#include <cuda_bf16.h>
#include <cstdint>
#include <math.h>

#define BB 64
#define PP 196
#define HH 512
#define EE 512
#define AA 512
#define VV 10000
#define MAXCAP 50
#define TT 49
#define NG 2048   // 4*H

// output layout (float32): scores (B,T,V), caps_s (B,50), decode_lengths (B,), weights (B,T,P), sort_ind (B,)
#define N_SCORES   (BB*TT*VV)
#define OFF_CAPS   (N_SCORES)
#define OFF_DECLEN (OFF_CAPS + BB*MAXCAP)
#define OFF_WEIGHTS (OFF_DECLEN + BB)
#define OFF_SORT   (OFF_WEIGHTS + BB*TT*PP)

#define NCTA 128
#define NTHR 256

// ======================= scratch =======================
__device__ float g_feats[BB*PP*HH];
__device__ float g_encatt[BB*PP*AA];
__device__ float g_embg[BB*TT*NG];
__device__ float g_hall[BB*TT*HH];
__device__ float g_h[BB*HH];
__device__ float g_c[BB*HH];
__device__ float g_att2[BB*AA];
__device__ float g_ctxp[2*BB*HH];
__device__ float g_e[BB*256];
__device__ int   g_sortidx[BB];
__device__ int   g_declen[BB];
__device__ int   g_nbact[TT];
__device__ int   g_act[BB*TT];
__device__ int   g_nact;
__device__ int   g_bcount;
__device__ int   g_bgen;
__device__ int   g_pc[BB];
__device__ int   g_pg[BB];

// bf16 hi/lo packed [rows][1024]: cols 0-511 hi, 512-1023 lo
__device__ __nv_bfloat16 g_feats2[BB*PP*1024];
__device__ __nv_bfloat16 g_embT2[BB*TT*1024];
__device__ __nv_bfloat16 g_hall2[BB*TT*1024];
__device__ __nv_bfloat16 g_Wenc2[AA*1024];
__device__ __nv_bfloat16 g_Wih2[NG*1024];
__device__ __nv_bfloat16 g_Wsc2[VV*1024];

// ======================= helpers =======================
__device__ __forceinline__ void mma16816(float* d, const uint32_t* a, const uint32_t* b) {
    asm volatile("mma.sync.aligned.m16n8k16.row.col.f32.bf16.bf16.f32 "
        "{%0,%1,%2,%3}, {%4,%5,%6,%7}, {%8,%9}, {%0,%1,%2,%3};"
        : "+f"(d[0]), "+f"(d[1]), "+f"(d[2]), "+f"(d[3])
        : "r"(a[0]), "r"(a[1]), "r"(a[2]), "r"(a[3]), "r"(b[0]), "r"(b[1]));
}
__device__ __forceinline__ void ldsm_x4(uint32_t* r, uint32_t saddr) {
    asm volatile("ldmatrix.sync.aligned.m8n8.x4.shared.b16 {%0,%1,%2,%3}, [%4];"
        : "=r"(r[0]), "=r"(r[1]), "=r"(r[2]), "=r"(r[3]) : "r"(saddr));
}
__device__ __forceinline__ void ldsm_x2(uint32_t* r, uint32_t saddr) {
    asm volatile("ldmatrix.sync.aligned.m8n8.x2.shared.b16 {%0,%1}, [%2];"
        : "=r"(r[0]), "=r"(r[1]) : "r"(saddr));
}
__device__ __forceinline__ uint32_t smem_u32(const void* p) {
    return (uint32_t)__cvta_generic_to_shared(p);
}
// store bf16x2 at (r, c even 0..31) in swizzled tile (64B rows, 16B-chunk XOR)
__device__ __forceinline__ void stsw2(char* s, int r, int c, uint32_t v) {
    int byte = r*64 + ((((c >> 3) ^ ((r >> 1) & 3))) << 4) + (c & 7)*2;
    *(uint32_t*)(s + byte) = v;
}
__device__ __forceinline__ void cvt_hilo2(float2 v, uint32_t& hp, uint32_t& lp) {
    __nv_bfloat16 h0 = __float2bfloat16(v.x), h1 = __float2bfloat16(v.y);
    float l0 = v.x - __bfloat162float(h0), l1 = v.y - __bfloat162float(h1);
    __nv_bfloat16 b0 = __float2bfloat16(l0), b1 = __float2bfloat16(l1);
    hp = (uint32_t)__bfloat16_as_ushort(h0) | ((uint32_t)__bfloat16_as_ushort(h1) << 16);
    lp = (uint32_t)__bfloat16_as_ushort(b0) | ((uint32_t)__bfloat16_as_ushort(b1) << 16);
}

// ======================= prep kernels =======================
__global__ void k_sort(const int* __restrict__ caplens, const int* __restrict__ caps,
                       float* __restrict__ out) {
    __shared__ int s_sort[BB];
    if (threadIdx.x == 0) {
        int cl[BB];
        for (int i = 0; i < BB; i++) cl[i] = caplens[i];
        int r = 0;
        for (int v = MAXCAP; v >= 0 && r < BB; v--)
            for (int i = 0; i < BB; i++)
                if (cl[i] == v) { g_sortidx[r] = i; s_sort[r] = i; r++; }
        int na = 0;
        int dls[BB];
        for (int b = 0; b < BB; b++) {
            int dl = cl[g_sortidx[b]] - 1;
            dls[b] = dl;
            g_declen[b] = dl;
            out[OFF_DECLEN + b] = (float)dl;
            out[OFF_SORT + b]   = (float)g_sortidx[b];
            for (int t = 0; t < dl; t++) g_act[na++] = b*TT + t;
        }
        g_nact = na;
        for (int t = 0; t < TT; t++) {
            int c = 0;
            for (int b = 0; b < BB; b++) if (dls[b] > t) c++;
            g_nbact[t] = c;
        }
    }
    __syncthreads();
    int b = threadIdx.x;
    int src = s_sort[b];
    for (int t = 0; t < MAXCAP; t++)
        out[OFF_CAPS + b*MAXCAP + t] = (float)caps[src*MAXCAP + t];
}

// fused gather + hi/lo conversion (pairwise) + zero + init
#define P0 (BB*PP*256)
#define P1 (BB*TT*256)
#define P2 (AA*256)
#define P3 (NG*256)
#define P4 (VV*256)
#define Z5 (N_SCORES/4)
#define Z6 (BB*TT*PP/4)
#define Z7 (BB*HH)
#define Z8 130
__global__ void k_cvt_all(const float* __restrict__ imf, const int* __restrict__ caps,
                          const float* __restrict__ emb, const float* __restrict__ W_enc,
                          const float* __restrict__ W_ih, const float* __restrict__ W_score,
                          float* __restrict__ out)
{
    const int total = P0+P1+P2+P3+P4+Z5+Z6+Z7+Z8;
    for (int i = blockIdx.x*blockDim.x + threadIdx.x; i < total; i += gridDim.x*blockDim.x) {
        int x = i;
        if (x < P0) {
            int r = x >> 8, c2 = x & 255, k = c2*2;
            int b = r / PP, p = r - b*PP;
            float2 v = *(const float2*)(imf + ((size_t)g_sortidx[b]*PP + p)*512 + k);
            *(float2*)(g_feats + (size_t)r*512 + k) = v;
            uint32_t hp, lp; cvt_hilo2(v, hp, lp);
            ((uint32_t*)g_feats2)[(size_t)r*512 + c2] = hp;
            ((uint32_t*)g_feats2)[(size_t)r*512 + 256 + c2] = lp;
            continue;
        }
        x -= P0;
        if (x < P1) {
            int r = x >> 8, c2 = x & 255, k = c2*2;
            int b = r / TT, t = r - b*TT;
            int tok = caps[g_sortidx[b]*MAXCAP + t];
            float2 v = *(const float2*)(emb + (size_t)tok*512 + k);
            uint32_t hp, lp; cvt_hilo2(v, hp, lp);
            ((uint32_t*)g_embT2)[(size_t)r*512 + c2] = hp;
            ((uint32_t*)g_embT2)[(size_t)r*512 + 256 + c2] = lp;
            continue;
        }
        x -= P1;
        if (x < P2) {
            int r = x >> 8, c2 = x & 255, k = c2*2;
            float2 v = *(const float2*)(W_enc + (size_t)r*512 + k);
            uint32_t hp, lp; cvt_hilo2(v, hp, lp);
            ((uint32_t*)g_Wenc2)[(size_t)r*512 + c2] = hp;
            ((uint32_t*)g_Wenc2)[(size_t)r*512 + 256 + c2] = lp;
            continue;
        }
        x -= P2;
        if (x < P3) {
            int r = x >> 8, c2 = x & 255, k = c2*2;
            float2 v = *(const float2*)(W_ih + (size_t)r*1024 + k);
            uint32_t hp, lp; cvt_hilo2(v, hp, lp);
            ((uint32_t*)g_Wih2)[(size_t)r*512 + c2] = hp;
            ((uint32_t*)g_Wih2)[(size_t)r*512 + 256 + c2] = lp;
            continue;
        }
        x -= P3;
        if (x < P4) {
            int r = x >> 8, c2 = x & 255, k = c2*2;
            float2 v = *(const float2*)(W_score + (size_t)r*512 + k);
            uint32_t hp, lp; cvt_hilo2(v, hp, lp);
            ((uint32_t*)g_Wsc2)[(size_t)r*512 + c2] = hp;
            ((uint32_t*)g_Wsc2)[(size_t)r*512 + 256 + c2] = lp;
            continue;
        }
        x -= P4;
        if (x < Z5) {
            ((float4*)out)[x] = make_float4(0.f, 0.f, 0.f, 0.f);
            continue;
        }
        x -= Z5;
        if (x < Z6) {
            ((float4*)(out + OFF_WEIGHTS))[x] = make_float4(0.f, 0.f, 0.f, 0.f);
            continue;
        }
        x -= Z6;
        if (x < Z7) { g_h[x] = 0.f; g_c[x] = 0.f; continue; }
        x -= Z7;
        if (x < 64) { g_pc[x] = 0; g_pg[x] = 0; continue; }
        if (x == 64) { g_bcount = 0; continue; }
        if (x == 65) { g_bgen = 0; continue; }
    }
}

// ======================= mma.sync bf16x3 GEMM body (ldmatrix + double buffer) ==========
__device__ __forceinline__ void hgemm_body(
    int bm, int bn,
    const __nv_bfloat16* __restrict__ A2, const __nv_bfloat16* __restrict__ B2,
    int M, int N, int ldc,
    const float* __restrict__ bias1, const float* __restrict__ bias2,
    float* __restrict__ C, const int* __restrict__ rowmap, int use_nact,
    __nv_bfloat16 (*As)[128*32], __nv_bfloat16 (*Bs)[128*32])
{
    int tid = threadIdx.x;
    int Ml = use_nact ? g_nact : M;
    if (bm*128 >= Ml) return;

    int lrow = tid >> 1;
    int lc0 = (tid & 1) * 2;
    int gm = bm*128 + lrow;
    const uint4* arow = nullptr;
    if (gm < Ml) { int r = rowmap ? rowmap[gm] : gm; arow = (const uint4*)(A2 + (size_t)r*1024); }
    int gn = bn*128 + lrow;
    const uint4* brow = (gn < N) ? (const uint4*)(B2 + (size_t)gn*1024) : nullptr;

    int swz = (lrow >> 1) & 3;
    uint4* aswp[2] = {(uint4*)(As[0] + lrow*32), (uint4*)(As[1] + lrow*32)};
    uint4* bswp[2] = {(uint4*)(Bs[0] + lrow*32), (uint4*)(Bs[1] + lrow*32)};
    int c0 = lc0 ^ swz, c1 = (lc0+1) ^ swz;

    int lane = tid & 31, wid = tid >> 5;
    int wm = (wid >> 2) * 64;
    int wn = (wid & 3) * 32;
    int gq = lane >> 2, tg = lane & 3;

    int rA = wm + (lane & 15);
    int swzA = (rA >> 1) & 3;
    int hiA = lane >> 4;
    int rB = wn + (lane & 7);
    int swzB = (rB >> 1) & 3;
    int hiB = (lane >> 3) & 1;
    uint32_t aS[2] = {smem_u32(As[0]) + rA*64, smem_u32(As[1]) + rA*64};
    uint32_t bS[2] = {smem_u32(Bs[0]) + rB*64, smem_u32(Bs[1]) + rB*64};

    float acc[4][4][4];
#pragma unroll
    for (int mt = 0; mt < 4; mt++)
#pragma unroll
        for (int nt = 0; nt < 4; nt++)
#pragma unroll
            for (int r = 0; r < 4; r++) acc[mt][nt][r] = 0.f;

    const uint4 z = make_uint4(0,0,0,0);
    const int kau4[3] = {0, 0, 64};
    const int kbu4[3] = {0, 64, 0};
    uint4 pa0 = arow ? arow[lc0]   : z;
    uint4 pa1 = arow ? arow[lc0+1] : z;
    uint4 pb0 = brow ? brow[lc0]   : z;
    uint4 pb1 = brow ? brow[lc0+1] : z;
    aswp[0][c0] = pa0; aswp[0][c1] = pa1;
    bswp[0][c0] = pb0; bswp[0][c1] = pb1;
    __syncthreads();

    for (int ci = 0; ci < 48; ci++) {
        int cur = ci & 1;
        if (ci + 1 < 48) {
            int term = (ci+1) >> 4, kc = (ci+1) & 15;
            int ab = kau4[term] + kc*4, bb = kbu4[term] + kc*4;
            pa0 = arow ? arow[ab + lc0]   : z;
            pa1 = arow ? arow[ab + lc0+1] : z;
            pb0 = brow ? brow[bb + lc0]   : z;
            pb1 = brow ? brow[bb + lc0+1] : z;
        }
#pragma unroll
        for (int kk = 0; kk < 2; kk++) {
            uint32_t cA = (uint32_t)(((2*kk + hiA) ^ swzA) << 4);
            uint32_t cB = (uint32_t)(((2*kk + hiB) ^ swzB) << 4);
            uint32_t afr[4][4];
#pragma unroll
            for (int mt = 0; mt < 4; mt++)
                ldsm_x4(afr[mt], aS[cur] + mt*1024 + cA);
            uint32_t bfr[4][2];
#pragma unroll
            for (int nt = 0; nt < 4; nt++)
                ldsm_x2(bfr[nt], bS[cur] + nt*512 + cB);
#pragma unroll
            for (int mt = 0; mt < 4; mt++)
#pragma unroll
                for (int nt = 0; nt < 4; nt++)
                    mma16816(acc[mt][nt], afr[mt], bfr[nt]);
        }
        if (ci + 1 < 48) {
            int nxt = cur ^ 1;
            aswp[nxt][c0] = pa0; aswp[nxt][c1] = pa1;
            bswp[nxt][c0] = pb0; bswp[nxt][c1] = pb1;
        }
        __syncthreads();
    }

#pragma unroll
    for (int mt = 0; mt < 4; mt++) {
        int m0 = bm*128 + wm + mt*16 + gq;
        int m1 = m0 + 8;
        size_t row0 = 0, row1 = 0;
        bool v0 = m0 < Ml, v1 = m1 < Ml;
        if (v0) row0 = (size_t)(rowmap ? rowmap[m0] : m0);
        if (v1) row1 = (size_t)(rowmap ? rowmap[m1] : m1);
#pragma unroll
        for (int nt = 0; nt < 4; nt++) {
            int col = bn*128 + wn + nt*8 + tg*2;
            if (col >= N) continue;
            float bx = bias1[col], by = bias1[col+1];
            if (bias2) { bx += bias2[col]; by += bias2[col+1]; }
            if (v0) {
                float2 o = make_float2(acc[mt][nt][0] + bx, acc[mt][nt][1] + by);
                *(float2*)(C + row0*(size_t)ldc + col) = o;
            }
            if (v1) {
                float2 o = make_float2(acc[mt][nt][2] + bx, acc[mt][nt][3] + by);
                *(float2*)(C + row1*(size_t)ldc + col) = o;
            }
        }
    }
}

__global__ __launch_bounds__(256)
void k_gemm_pair(const float* __restrict__ b_enc, const float* __restrict__ b_ih,
                 const float* __restrict__ b_hh)
{
    __shared__ __align__(16) __nv_bfloat16 As[2][128*32];
    __shared__ __align__(16) __nv_bfloat16 Bs[2][128*32];
    int idx = blockIdx.x;
    if (idx < 392) {
        hgemm_body(idx >> 2, idx & 3, g_feats2, g_Wenc2, BB*PP, AA, AA,
                   b_enc, nullptr, g_encatt, nullptr, 0, As, Bs);
    } else {
        idx -= 392;
        hgemm_body(idx >> 4, idx & 15, g_embT2, g_Wih2, BB*TT, NG, NG,
                   b_ih, b_hh, g_embg, g_act, 1, As, Bs);
    }
}

__global__ __launch_bounds__(256)
void k_gemm_scores(const float* __restrict__ b_score, float* __restrict__ out)
{
    __shared__ __align__(16) __nv_bfloat16 As[2][128*32];
    __shared__ __align__(16) __nv_bfloat16 Bs[2][128*32];
    hgemm_body(blockIdx.x, blockIdx.y, g_hall2, g_Wsc2, BB*TT, VV, VV,
               b_score, nullptr, out, g_act, 1, As, Bs);
}

__global__ void k_cvt_hall() {
    int i = blockIdx.x*blockDim.x + threadIdx.x;
    if (i >= BB*TT*256) return;
    int r = i >> 8, c2 = i & 255, k = c2*2;
    float2 v = *(const float2*)(g_hall + (size_t)r*512 + k);
    uint32_t hp, lp; cvt_hilo2(v, hp, lp);
    ((uint32_t*)g_hall2)[(size_t)r*512 + c2] = hp;
    ((uint32_t*)g_hall2)[(size_t)r*512 + 256 + c2] = lp;
}

// ======================= fused persistent recurrence =======================
// smem byte offsets
#define WHH_OFF  0
#define WIHC_OFF 32768
#define WDEC_OFF 65536
#define HT_OFF   81920
#define PART_OFF 147456
#define GH_OFF   155648
#define SM_TOTAL 159744

// sense-reversing grid barrier (replay-safe: count self-resets, any gen works)
__device__ __forceinline__ void gridbar() {
    __syncthreads();
    if (threadIdx.x == 0) {
        int* cp = &g_bcount; int* gp = &g_bgen;
        int gen;
        asm volatile("ld.acquire.gpu.global.s32 %0, [%1];" : "=r"(gen) : "l"(gp) : "memory");
        int old;
        asm volatile("atom.release.gpu.global.add.s32 %0, [%1], 1;" : "=r"(old) : "l"(cp) : "memory");
        if (old == NCTA-1) {
            asm volatile("st.relaxed.gpu.global.s32 [%0], 0;" :: "l"(cp) : "memory");
            asm volatile("st.release.gpu.global.s32 [%0], %1;" :: "l"(gp), "r"(gen+1) : "memory");
        } else {
            int v;
            do {
                asm volatile("ld.acquire.gpu.global.s32 %0, [%1];" : "=r"(v) : "l"(gp) : "memory");
            } while (v == gen);
        }
    }
    __syncthreads();
}

// 2-CTA pair barrier, same protocol
__device__ __forceinline__ void pairbar(int b) {
    __syncthreads();
    if (threadIdx.x == 0) {
        int* cp = &g_pc[b]; int* gp = &g_pg[b];
        int gen;
        asm volatile("ld.acquire.gpu.global.s32 %0, [%1];" : "=r"(gen) : "l"(gp) : "memory");
        int old;
        asm volatile("atom.release.gpu.global.add.s32 %0, [%1], 1;" : "=r"(old) : "l"(cp) : "memory");
        if (old == 1) {
            asm volatile("st.relaxed.gpu.global.s32 [%0], 0;" :: "l"(cp) : "memory");
            asm volatile("st.release.gpu.global.s32 [%0], %1;" :: "l"(gp), "r"(gen+1) : "memory");
        } else {
            int v;
            do {
                asm volatile("ld.acquire.gpu.global.s32 %0, [%1];" : "=r"(v) : "l"(gp) : "memory");
            } while (v == gen);
        }
    }
    __syncthreads();
}

// stage 32 rows of fp32[512] (L2-coherent reads) into hi/lo swizzled tiles
__device__ __forceinline__ void stage32h(int b0, char* HTp, int tid) {
    for (int i = tid; i < 32*256; i += NTHR) {
        int r = i >> 8, kp = i & 255, k = kp*2;
        float2 v = __ldcg((const float2*)(g_h + (size_t)(b0+r)*512 + k));
        uint32_t hp, lp;
        cvt_hilo2(v, hp, lp);
        int kt = k >> 5, c = k & 31;
        stsw2(HTp + kt*2048, r, c, hp);
        stsw2(HTp + (16+kt)*2048, r, c, lp);
    }
}
__device__ __forceinline__ void stage32ctx(int b0, char* HTp, int tid) {
    for (int i = tid; i < 32*256; i += NTHR) {
        int r = i >> 8, kp = i & 255, k = kp*2;
        size_t off = (size_t)(b0+r)*512 + k;
        float2 v0 = __ldcg((const float2*)(g_ctxp + off));
        float2 v1 = __ldcg((const float2*)(g_ctxp + (size_t)BB*512 + off));
        float2 v = make_float2(v0.x + v1.x, v0.y + v1.y);
        uint32_t hp, lp;
        cvt_hilo2(v, hp, lp);
        int kt = k >> 5, c = k & 31;
        stsw2(HTp + kt*2048, r, c, hp);
        stsw2(HTp + (16+kt)*2048, r, c, lp);
    }
}

// gates mma (ldmatrix): M=32, N=16, K=512, 3 hi/lo terms -> part[2][32][16]
__device__ __forceinline__ void gates_mma(uint32_t htA, uint32_t wbB, float* part,
                                          int wid, int lane) {
    int gq = lane >> 2, tg = lane & 3;
    int mh = (wid & 1)*16, nh = ((wid >> 1) & 1)*8, ks = wid >> 2;
    int rA = mh + (lane & 15);
    int swzA = (rA >> 1) & 3;
    int hiA = lane >> 4;
    int rB = nh + (lane & 7);
    int swzB = (rB >> 1) & 3;
    int hiB = (lane >> 3) & 1;
    uint32_t aL = htA + rA*64;
    uint32_t bL = wbB + rB*64;
    float acc[4] = {0.f, 0.f, 0.f, 0.f};
    for (int kt = ks*8; kt < ks*8 + 8; kt++) {
        uint32_t ah = aL + kt*2048;
        uint32_t bh = bL + kt*1024;
#pragma unroll
        for (int kk = 0; kk < 2; kk++) {
            uint32_t cA = (uint32_t)(((2*kk + hiA) ^ swzA) << 4);
            uint32_t cB = (uint32_t)(((2*kk + hiB) ^ swzB) << 4);
            uint32_t Ah[4], Al[4], Bh[2], Bl[2];
            ldsm_x4(Ah, ah + cA);
            ldsm_x4(Al, ah + 32768 + cA);
            ldsm_x2(Bh, bh + cB);
            ldsm_x2(Bl, bh + 16384 + cB);
            mma16816(acc, Ah, Bh);
            mma16816(acc, Ah, Bl);
            mma16816(acc, Al, Bh);
        }
    }
    int m0 = mh + gq, n0 = nh + tg*2;
    part[ks*512 + m0*16 + n0]       = acc[0];
    part[ks*512 + m0*16 + n0+1]     = acc[1];
    part[ks*512 + (m0+8)*16 + n0]   = acc[2];
    part[ks*512 + (m0+8)*16 + n0+1] = acc[3];
}

// att2 mma (ldmatrix): M=32, N=8 (4 real + 4 zero), K=512 -> part2[4][32][8]
__device__ __forceinline__ void att2_mma(uint32_t htA, uint32_t wdB, float* part2,
                                         int wid, int lane) {
    int gq = lane >> 2, tg = lane & 3;
    int mh = (wid & 1)*16, ks = wid >> 1;
    int rA = mh + (lane & 15);
    int swzA = (rA >> 1) & 3;
    int hiA = lane >> 4;
    int rB = lane & 7;
    int swzB = (rB >> 1) & 3;
    int hiB = (lane >> 3) & 1;
    uint32_t aL = htA + rA*64;
    uint32_t bL = wdB + rB*64;
    float acc[4] = {0.f, 0.f, 0.f, 0.f};
    for (int kt = ks*4; kt < ks*4 + 4; kt++) {
        uint32_t ah = aL + kt*2048;
        uint32_t bh = bL + kt*512;
#pragma unroll
        for (int kk = 0; kk < 2; kk++) {
            uint32_t cA = (uint32_t)(((2*kk + hiA) ^ swzA) << 4);
            uint32_t cB = (uint32_t)(((2*kk + hiB) ^ swzB) << 4);
            uint32_t Ah[4], Al[4], Bh[2], Bl[2];
            ldsm_x4(Ah, ah + cA);
            ldsm_x4(Al, ah + 32768 + cA);
            ldsm_x2(Bh, bh + cB);
            ldsm_x2(Bl, bh + 8192 + cB);
            mma16816(acc, Ah, Bh);
            mma16816(acc, Ah, Bl);
            mma16816(acc, Al, Bh);
        }
    }
    int m0 = mh + gq, n0 = tg*2;
    part2[ks*256 + m0*8 + n0]       = acc[0];
    part2[ks*256 + m0*8 + n0+1]     = acc[1];
    part2[ks*256 + (m0+8)*8 + n0]   = acc[2];
    part2[ks*256 + (m0+8)*8 + n0+1] = acc[3];
}

__global__ __launch_bounds__(NTHR)
void k_recur(const float* __restrict__ W_dec, const float* __restrict__ W_hh,
             const float* __restrict__ W_ih,
             const float* __restrict__ b_dec, const float* __restrict__ W_full,
             const float* __restrict__ b_full, float* __restrict__ out)
{
    extern __shared__ float sm[];
    char* smc = (char*)sm;
    __shared__ int sdl[BB];
    __shared__ int snb[TT];
    int tid = threadIdx.x, lane = tid & 31, wid = tid >> 5;
    int j = blockIdx.x;
    int bb = j & 63, half = j >> 6;

    if (tid < BB) sdl[tid] = g_declen[tid];
    if (tid >= 64 && tid < 64 + TT) snb[tid - 64] = g_nbact[tid - 64];

    // convert weight slices to swizzled bf16 hi/lo tiles (once)
    for (int i = tid; i < 16*256; i += NTHR) {
        int r = i >> 8, kp = i & 255, k = kp*2;
        int gr = 512*(r >> 2) + j*4 + (r & 3);
        float2 w1 = *(const float2*)(W_hh + (size_t)gr*512 + k);
        float2 w2 = *(const float2*)(W_ih + (size_t)gr*1024 + 512 + k);
        uint32_t hp, lp;
        int kt = k >> 5, c = k & 31;
        cvt_hilo2(w1, hp, lp);
        stsw2(smc + WHH_OFF + kt*1024, r, c, hp);
        stsw2(smc + WHH_OFF + (16+kt)*1024, r, c, lp);
        cvt_hilo2(w2, hp, lp);
        stsw2(smc + WIHC_OFF + kt*1024, r, c, hp);
        stsw2(smc + WIHC_OFF + (16+kt)*1024, r, c, lp);
    }
    for (int i = tid; i < 8*256; i += NTHR) {
        int r = i >> 8, kp = i & 255, k = kp*2;
        float2 w = (r < 4) ? *(const float2*)(W_dec + (size_t)(j*4+r)*512 + k)
                           : make_float2(0.f, 0.f);
        uint32_t hp, lp;
        cvt_hilo2(w, hp, lp);
        int kt = k >> 5, c = k & 31;
        stsw2(smc + WDEC_OFF + kt*512, r, c, hp);
        stsw2(smc + WDEC_OFF + (16+kt)*512, r, c, lp);
    }
    __syncthreads();

    float* part  = (float*)(smc + PART_OFF);
    float* part2 = part + 1024;
    float* gh    = (float*)(smc + GH_OFF);
    uint32_t htS  = smem_u32(smc + HT_OFF);
    uint32_t whhS = smem_u32(smc + WHH_OFF);
    uint32_t wihS = smem_u32(smc + WIHC_OFF);
    uint32_t wdS  = smem_u32(smc + WDEC_OFF);

    for (int t = 0; t < TT; t++) {
        int npb = (snb[t] + 31) >> 5;
        // ---- Phase A: gates_h + att2 (mma) ----
        for (int pb = 0; pb < npb; pb++) {
            int b0 = pb*32;
            stage32h(b0, smc + HT_OFF, tid);
            __syncthreads();
            gates_mma(htS, whhS, part, wid, lane);
            att2_mma(htS, wdS, part2, wid, lane);
            __syncthreads();
            for (int o = tid; o < 512; o += NTHR)
                gh[(b0 + (o >> 4))*16 + (o & 15)] = part[o] + part[512 + o];
            if (tid < 128) {
                int m = tid >> 2, q = tid & 3;
                float s = part2[m*8+q] + part2[256 + m*8+q] + part2[512 + m*8+q] + part2[768 + m*8+q];
                g_att2[(b0+m)*512 + j*4 + q] = s;
            }
            __syncthreads();
        }
        gridbar();

        // ---- Phase B: attention (pair-split across all 128 CTAs) ----
        if (t < sdl[bb]) {
            float* s_e   = (float*)(smc + HT_OFF);
            float* s_red = s_e + 224;
            float* rbuf  = s_e + 512;
            float* wout = out + OFF_WEIGHTS + (size_t)(bb*TT + t)*PP;
            // register-cached att2 + W_full
            float att2r[16], wfr[16];
#pragma unroll
            for (int k = 0; k < 16; k++) {
                int a = lane + 32*k;
                att2r[k] = __ldcg(&g_att2[bb*512 + a]) + b_dec[a];
                wfr[k]   = W_full[a];
            }
            // e for my half of p
            const float* ea = g_encatt + ((size_t)bb*PP + half*98)*AA;
            for (int p = wid; p < 98; p += 8) {
                const float* row = ea + (size_t)p*AA;
                float sum = 0.f;
#pragma unroll
                for (int k = 0; k < 16; k++)
                    sum += fmaxf(row[lane + 32*k] + att2r[k], 0.f) * wfr[k];
#pragma unroll
                for (int o = 16; o; o >>= 1) sum += __shfl_xor_sync(0xffffffffu, sum, o);
                if (lane == 0) g_e[bb*256 + half*98 + p] = sum + b_full[0];
            }
            pairbar(bb);
            if (tid < PP) s_e[tid] = __ldcg(&g_e[bb*256 + tid]);
            __syncthreads();
            // softmax (196), redundant in both pair CTAs
            float m = -1e30f;
            if (tid < PP) m = s_e[tid];
#pragma unroll
            for (int o = 16; o; o >>= 1) m = fmaxf(m, __shfl_xor_sync(0xffffffffu, m, o));
            if (lane == 0) s_red[wid] = m;
            __syncthreads();
            float mx = s_red[0];
#pragma unroll
            for (int i = 1; i < 8; i++) mx = fmaxf(mx, s_red[i]);
            float ev = 0.f;
            if (tid < PP) ev = expf(s_e[tid] - mx);
            float sv = ev;
#pragma unroll
            for (int o = 16; o; o >>= 1) sv += __shfl_xor_sync(0xffffffffu, sv, o);
            __syncthreads();
            if (lane == 0) s_red[wid] = sv;
            __syncthreads();
            float tot = 0.f;
#pragma unroll
            for (int i = 0; i < 8; i++) tot += s_red[i];
            float inv = 1.f / tot;
            if (tid < PP) {
                float al = ev * inv;
                s_e[tid] = al;
                if (half == 0) wout[tid] = al;
            }
            __syncthreads();
            // ctx over my half of p
            int hq = tid & 63, pc2 = tid >> 6;
            const float4* fb4 = (const float4*)(g_feats + ((size_t)bb*PP + half*98)*HH);
            float4 a0 = make_float4(0,0,0,0), a1 = make_float4(0,0,0,0);
            for (int p = pc2; p < 98; p += 4) {
                float al = s_e[half*98 + p];
                float4 v0 = fb4[p*128 + hq*2];
                float4 v1 = fb4[p*128 + hq*2 + 1];
                a0.x = fmaf(al, v0.x, a0.x); a0.y = fmaf(al, v0.y, a0.y);
                a0.z = fmaf(al, v0.z, a0.z); a0.w = fmaf(al, v0.w, a0.w);
                a1.x = fmaf(al, v1.x, a1.x); a1.y = fmaf(al, v1.y, a1.y);
                a1.z = fmaf(al, v1.z, a1.z); a1.w = fmaf(al, v1.w, a1.w);
            }
            float* rb = rbuf + pc2*512 + hq*8;
            rb[0]=a0.x; rb[1]=a0.y; rb[2]=a0.z; rb[3]=a0.w;
            rb[4]=a1.x; rb[5]=a1.y; rb[6]=a1.z; rb[7]=a1.w;
            __syncthreads();
            for (int o = tid; o < 512; o += NTHR) {
                float s = rbuf[o] + rbuf[512+o] + rbuf[1024+o] + rbuf[1536+o];
                g_ctxp[(size_t)half*BB*512 + bb*512 + o] = s;
            }
        }
        gridbar();

        // ---- Phase C: gates_ctx (mma) + combine + LSTM ----
        for (int pb = 0; pb < npb; pb++) {
            int b0 = pb*32;
            stage32ctx(b0, smc + HT_OFF, tid);
            __syncthreads();
            gates_mma(htS, wihS, part, wid, lane);
            __syncthreads();
            for (int o = tid; o < 512; o += NTHR) {
                int m = o >> 4, n = o & 15;
                int b = b0 + m;
                int gr = 512*(n >> 2) + j*4 + (n & 3);
                gh[b*16 + n] += part[o] + part[512 + o] + g_embg[(size_t)(b*TT + t)*NG + gr];
            }
            __syncthreads();
        }
        {
            int b = tid >> 2, q = tid & 3;
            if (t < sdl[b]) {
                float gi = gh[b*16 + q];
                float gf = gh[b*16 + 4 + q];
                float gg = gh[b*16 + 8 + q];
                float go = gh[b*16 + 12 + q];
                float ig = 1.f / (1.f + expf(-gi));
                float fg = 1.f / (1.f + expf(-gf));
                float gv = tanhf(gg);
                float og = 1.f / (1.f + expf(-go));
                int kc = j*4 + q;
                float c_new = fg * g_c[b*512 + kc] + ig * gv;
                float h_new = og * tanhf(c_new);
                g_hall[(size_t)(b*TT + t)*512 + kc] = h_new;
                g_h[b*512 + kc] = h_new;
                g_c[b*512 + kc] = c_new;
            }
        }
        gridbar();
    }
}

// ======================= launch =======================
extern "C" void kernel_launch(void* const* d_in, const int* in_sizes, int n_in,
                              void* d_out, int out_size) {
    const float* imf     = (const float*)d_in[0];
    const int*   caps    = (const int*)  d_in[1];
    const int*   caplens = (const int*)  d_in[2];
    const float* emb     = (const float*)d_in[3];
    const float* W_ih    = (const float*)d_in[4];
    const float* W_hh    = (const float*)d_in[5];
    const float* b_ih    = (const float*)d_in[6];
    const float* b_hh    = (const float*)d_in[7];
    const float* W_enc   = (const float*)d_in[8];
    const float* b_enc   = (const float*)d_in[9];
    const float* W_dec   = (const float*)d_in[10];
    const float* b_dec   = (const float*)d_in[11];
    const float* W_full  = (const float*)d_in[12];
    const float* b_full  = (const float*)d_in[13];
    const float* W_score = (const float*)d_in[14];
    const float* b_score = (const float*)d_in[15];
    float* out = (float*)d_out;

    cudaFuncSetAttribute(k_recur, cudaFuncAttributeMaxDynamicSharedMemorySize, SM_TOTAL);

    // 1: sort + caps/declen/sortind outputs
    k_sort<<<1, BB>>>(caplens, caps, out);
    // 2: fused gathers + bf16 hi/lo conversions + zeroing + init
    k_cvt_all<<<1024, 256>>>(imf, caps, emb, W_enc, W_ih, W_score, out);
    // 3: fused enc_att + G_emb tensor-core GEMMs
    k_gemm_pair<<<792, 256>>>(b_enc, b_ih, b_hh);
    // 4: persistent recurrence
    k_recur<<<NCTA, NTHR, SM_TOTAL>>>(W_dec, W_hh, W_ih, b_dec, W_full, b_full, out);
    // 5: h history conversion
    k_cvt_hall<<<(BB*TT*256 + 255)/256, 256>>>();
    // 6: scores GEMM
    k_gemm_scores<<<dim3((BB*TT + 127)/128, (VV + 127)/128), 256>>>(b_score, out);
}

// round 8
// speedup vs baseline: 1.1631x; 1.1631x over previous
#include <cuda_runtime.h>
#include <cuda_bf16.h>
#include <cstdint>
#include <math.h>

#define BB 64
#define PP 196
#define HH 512
#define EE 512
#define AA 512
#define VV 10000
#define MAXCAP 50
#define TT 49
#define NG 2048   // 4*H

// output layout (float32): scores (B,T,V), caps_s (B,50), decode_lengths (B,), weights (B,T,P), sort_ind (B,)
#define N_SCORES   (BB*TT*VV)
#define OFF_CAPS   (N_SCORES)
#define OFF_DECLEN (OFF_CAPS + BB*MAXCAP)
#define OFF_WEIGHTS (OFF_DECLEN + BB)
#define OFF_SORT   (OFF_WEIGHTS + BB*TT*PP)

#define NCTA 128
#define NTHR 256

// ======================= scratch =======================
__device__ float g_feats[BB*PP*HH];
__device__ float g_encatt[BB*PP*AA];
__device__ float g_embg[BB*TT*NG];
__device__ float g_hall[BB*TT*HH];
__device__ float g_h[BB*HH];
__device__ float g_c[BB*HH];
__device__ float g_att2[BB*AA];
__device__ float g_ctx[BB*HH];
__device__ int   g_sortidx[BB];
__device__ int   g_declen[BB];
__device__ int   g_nbact[TT];
__device__ int   g_act[BB*TT];
__device__ int   g_nact;
__device__ int   g_bc4[4];
__device__ int   g_broot;
__device__ int   g_bgen;

// bf16 hi/lo packed [rows][1024]: cols 0-511 hi, 512-1023 lo
__device__ __nv_bfloat16 g_feats2[BB*PP*1024];
__device__ __nv_bfloat16 g_embT2[BB*TT*1024];
__device__ __nv_bfloat16 g_hall2[BB*TT*1024];
__device__ __nv_bfloat16 g_Wenc2[AA*1024];
__device__ __nv_bfloat16 g_Wih2[NG*1024];
__device__ __nv_bfloat16 g_Wsc2[VV*1024];

// ======================= helpers =======================
__device__ __forceinline__ void mma16816(float* d, const uint32_t* a, const uint32_t* b) {
    asm volatile("mma.sync.aligned.m16n8k16.row.col.f32.bf16.bf16.f32 "
        "{%0,%1,%2,%3}, {%4,%5,%6,%7}, {%8,%9}, {%0,%1,%2,%3};"
        : "+f"(d[0]), "+f"(d[1]), "+f"(d[2]), "+f"(d[3])
        : "r"(a[0]), "r"(a[1]), "r"(a[2]), "r"(a[3]), "r"(b[0]), "r"(b[1]));
}
__device__ __forceinline__ void ldsm_x4(uint32_t* r, uint32_t saddr) {
    asm volatile("ldmatrix.sync.aligned.m8n8.x4.shared.b16 {%0,%1,%2,%3}, [%4];"
        : "=r"(r[0]), "=r"(r[1]), "=r"(r[2]), "=r"(r[3]) : "r"(saddr));
}
__device__ __forceinline__ void ldsm_x2(uint32_t* r, uint32_t saddr) {
    asm volatile("ldmatrix.sync.aligned.m8n8.x2.shared.b16 {%0,%1}, [%2];"
        : "=r"(r[0]), "=r"(r[1]) : "r"(saddr));
}
__device__ __forceinline__ uint32_t smem_u32(const void* p) {
    return (uint32_t)__cvta_generic_to_shared(p);
}
// store bf16x2 at (r, c even 0..31) in swizzled tile (64B rows, 16B-chunk XOR)
__device__ __forceinline__ void stsw2(char* s, int r, int c, uint32_t v) {
    int byte = r*64 + ((((c >> 3) ^ ((r >> 1) & 3))) << 4) + (c & 7)*2;
    *(uint32_t*)(s + byte) = v;
}
__device__ __forceinline__ void cvt_hilo2(float2 v, uint32_t& hp, uint32_t& lp) {
    __nv_bfloat16 h0 = __float2bfloat16(v.x), h1 = __float2bfloat16(v.y);
    float l0 = v.x - __bfloat162float(h0), l1 = v.y - __bfloat162float(h1);
    __nv_bfloat16 b0 = __float2bfloat16(l0), b1 = __float2bfloat16(l1);
    hp = (uint32_t)__bfloat16_as_ushort(h0) | ((uint32_t)__bfloat16_as_ushort(h1) << 16);
    lp = (uint32_t)__bfloat16_as_ushort(b0) | ((uint32_t)__bfloat16_as_ushort(b1) << 16);
}

// ======================= prep kernels =======================
__global__ void k_sort(const int* __restrict__ caplens, const int* __restrict__ caps,
                       float* __restrict__ out) {
    __shared__ int s_sort[BB];
    if (threadIdx.x == 0) {
        int cl[BB];
        for (int i = 0; i < BB; i++) cl[i] = caplens[i];
        int r = 0;
        for (int v = MAXCAP; v >= 0 && r < BB; v--)
            for (int i = 0; i < BB; i++)
                if (cl[i] == v) { g_sortidx[r] = i; s_sort[r] = i; r++; }
        int na = 0;
        int dls[BB];
        for (int b = 0; b < BB; b++) {
            int dl = cl[g_sortidx[b]] - 1;
            dls[b] = dl;
            g_declen[b] = dl;
            out[OFF_DECLEN + b] = (float)dl;
            out[OFF_SORT + b]   = (float)g_sortidx[b];
            for (int t = 0; t < dl; t++) g_act[na++] = b*TT + t;
        }
        g_nact = na;
        for (int t = 0; t < TT; t++) {
            int c = 0;
            for (int b = 0; b < BB; b++) if (dls[b] > t) c++;
            g_nbact[t] = c;
        }
    }
    __syncthreads();
    int b = threadIdx.x;
    int src = s_sort[b];
    for (int t = 0; t < MAXCAP; t++)
        out[OFF_CAPS + b*MAXCAP + t] = (float)caps[src*MAXCAP + t];
}

// fused gather + hi/lo conversion (pairwise) + zero + init
#define P0 (BB*PP*256)
#define P1 (BB*TT*256)
#define P2 (AA*256)
#define P3 (NG*256)
#define P4 (VV*256)
#define Z5 (N_SCORES/4)
#define Z6 (BB*TT*PP/4)
#define Z7 (BB*HH)
#define Z8 8
__global__ void k_cvt_all(const float* __restrict__ imf, const int* __restrict__ caps,
                          const float* __restrict__ emb, const float* __restrict__ W_enc,
                          const float* __restrict__ W_ih, const float* __restrict__ W_score,
                          float* __restrict__ out)
{
    const int total = P0+P1+P2+P3+P4+Z5+Z6+Z7+Z8;
    for (int i = blockIdx.x*blockDim.x + threadIdx.x; i < total; i += gridDim.x*blockDim.x) {
        int x = i;
        if (x < P0) {
            int r = x >> 8, c2 = x & 255, k = c2*2;
            int b = r / PP, p = r - b*PP;
            float2 v = *(const float2*)(imf + ((size_t)g_sortidx[b]*PP + p)*512 + k);
            *(float2*)(g_feats + (size_t)r*512 + k) = v;
            uint32_t hp, lp; cvt_hilo2(v, hp, lp);
            ((uint32_t*)g_feats2)[(size_t)r*512 + c2] = hp;
            ((uint32_t*)g_feats2)[(size_t)r*512 + 256 + c2] = lp;
            continue;
        }
        x -= P0;
        if (x < P1) {
            int r = x >> 8, c2 = x & 255, k = c2*2;
            int b = r / TT, t = r - b*TT;
            int tok = caps[g_sortidx[b]*MAXCAP + t];
            float2 v = *(const float2*)(emb + (size_t)tok*512 + k);
            uint32_t hp, lp; cvt_hilo2(v, hp, lp);
            ((uint32_t*)g_embT2)[(size_t)r*512 + c2] = hp;
            ((uint32_t*)g_embT2)[(size_t)r*512 + 256 + c2] = lp;
            continue;
        }
        x -= P1;
        if (x < P2) {
            int r = x >> 8, c2 = x & 255, k = c2*2;
            float2 v = *(const float2*)(W_enc + (size_t)r*512 + k);
            uint32_t hp, lp; cvt_hilo2(v, hp, lp);
            ((uint32_t*)g_Wenc2)[(size_t)r*512 + c2] = hp;
            ((uint32_t*)g_Wenc2)[(size_t)r*512 + 256 + c2] = lp;
            continue;
        }
        x -= P2;
        if (x < P3) {
            int r = x >> 8, c2 = x & 255, k = c2*2;
            float2 v = *(const float2*)(W_ih + (size_t)r*1024 + k);
            uint32_t hp, lp; cvt_hilo2(v, hp, lp);
            ((uint32_t*)g_Wih2)[(size_t)r*512 + c2] = hp;
            ((uint32_t*)g_Wih2)[(size_t)r*512 + 256 + c2] = lp;
            continue;
        }
        x -= P3;
        if (x < P4) {
            int r = x >> 8, c2 = x & 255, k = c2*2;
            float2 v = *(const float2*)(W_score + (size_t)r*512 + k);
            uint32_t hp, lp; cvt_hilo2(v, hp, lp);
            ((uint32_t*)g_Wsc2)[(size_t)r*512 + c2] = hp;
            ((uint32_t*)g_Wsc2)[(size_t)r*512 + 256 + c2] = lp;
            continue;
        }
        x -= P4;
        if (x < Z5) {
            ((float4*)out)[x] = make_float4(0.f, 0.f, 0.f, 0.f);
            continue;
        }
        x -= Z5;
        if (x < Z6) {
            ((float4*)(out + OFF_WEIGHTS))[x] = make_float4(0.f, 0.f, 0.f, 0.f);
            continue;
        }
        x -= Z6;
        if (x < Z7) { g_h[x] = 0.f; g_c[x] = 0.f; continue; }
        x -= Z7;
        if (x < 4) { g_bc4[x] = 0; continue; }
        if (x == 4) { g_broot = 0; continue; }
        if (x == 5) { g_bgen = 0; continue; }
    }
}

// ======================= mma.sync bf16x3 GEMM body (ldmatrix + double buffer) ==========
__device__ __forceinline__ void hgemm_body(
    int bm, int bn,
    const __nv_bfloat16* __restrict__ A2, const __nv_bfloat16* __restrict__ B2,
    int M, int N, int ldc,
    const float* __restrict__ bias1, const float* __restrict__ bias2,
    float* __restrict__ C, const int* __restrict__ rowmap, int use_nact,
    __nv_bfloat16 (*As)[128*32], __nv_bfloat16 (*Bs)[128*32])
{
    int tid = threadIdx.x;
    int Ml = use_nact ? g_nact : M;
    if (bm*128 >= Ml) return;

    int lrow = tid >> 1;
    int lc0 = (tid & 1) * 2;
    int gm = bm*128 + lrow;
    const uint4* arow = nullptr;
    if (gm < Ml) { int r = rowmap ? rowmap[gm] : gm; arow = (const uint4*)(A2 + (size_t)r*1024); }
    int gn = bn*128 + lrow;
    const uint4* brow = (gn < N) ? (const uint4*)(B2 + (size_t)gn*1024) : nullptr;

    int swz = (lrow >> 1) & 3;
    uint4* aswp[2] = {(uint4*)(As[0] + lrow*32), (uint4*)(As[1] + lrow*32)};
    uint4* bswp[2] = {(uint4*)(Bs[0] + lrow*32), (uint4*)(Bs[1] + lrow*32)};
    int c0 = lc0 ^ swz, c1 = (lc0+1) ^ swz;

    int lane = tid & 31, wid = tid >> 5;
    int wm = (wid >> 2) * 64;
    int wn = (wid & 3) * 32;
    int gq = lane >> 2, tg = lane & 3;

    int rA = wm + (lane & 15);
    int swzA = (rA >> 1) & 3;
    int hiA = lane >> 4;
    int rB = wn + (lane & 7);
    int swzB = (rB >> 1) & 3;
    int hiB = (lane >> 3) & 1;
    uint32_t aS[2] = {smem_u32(As[0]) + rA*64, smem_u32(As[1]) + rA*64};
    uint32_t bS[2] = {smem_u32(Bs[0]) + rB*64, smem_u32(Bs[1]) + rB*64};

    float acc[4][4][4];
#pragma unroll
    for (int mt = 0; mt < 4; mt++)
#pragma unroll
        for (int nt = 0; nt < 4; nt++)
#pragma unroll
            for (int r = 0; r < 4; r++) acc[mt][nt][r] = 0.f;

    const uint4 z = make_uint4(0,0,0,0);
    const int kau4[3] = {0, 0, 64};
    const int kbu4[3] = {0, 64, 0};
    uint4 pa0 = arow ? arow[lc0]   : z;
    uint4 pa1 = arow ? arow[lc0+1] : z;
    uint4 pb0 = brow ? brow[lc0]   : z;
    uint4 pb1 = brow ? brow[lc0+1] : z;
    aswp[0][c0] = pa0; aswp[0][c1] = pa1;
    bswp[0][c0] = pb0; bswp[0][c1] = pb1;
    __syncthreads();

    for (int ci = 0; ci < 48; ci++) {
        int cur = ci & 1;
        if (ci + 1 < 48) {
            int term = (ci+1) >> 4, kc = (ci+1) & 15;
            int ab = kau4[term] + kc*4, bb = kbu4[term] + kc*4;
            pa0 = arow ? arow[ab + lc0]   : z;
            pa1 = arow ? arow[ab + lc0+1] : z;
            pb0 = brow ? brow[bb + lc0]   : z;
            pb1 = brow ? brow[bb + lc0+1] : z;
        }
#pragma unroll
        for (int kk = 0; kk < 2; kk++) {
            uint32_t cA = (uint32_t)(((2*kk + hiA) ^ swzA) << 4);
            uint32_t cB = (uint32_t)(((2*kk + hiB) ^ swzB) << 4);
            uint32_t afr[4][4];
#pragma unroll
            for (int mt = 0; mt < 4; mt++)
                ldsm_x4(afr[mt], aS[cur] + mt*1024 + cA);
            uint32_t bfr[4][2];
#pragma unroll
            for (int nt = 0; nt < 4; nt++)
                ldsm_x2(bfr[nt], bS[cur] + nt*512 + cB);
#pragma unroll
            for (int mt = 0; mt < 4; mt++)
#pragma unroll
                for (int nt = 0; nt < 4; nt++)
                    mma16816(acc[mt][nt], afr[mt], bfr[nt]);
        }
        if (ci + 1 < 48) {
            int nxt = cur ^ 1;
            aswp[nxt][c0] = pa0; aswp[nxt][c1] = pa1;
            bswp[nxt][c0] = pb0; bswp[nxt][c1] = pb1;
        }
        __syncthreads();
    }

#pragma unroll
    for (int mt = 0; mt < 4; mt++) {
        int m0 = bm*128 + wm + mt*16 + gq;
        int m1 = m0 + 8;
        size_t row0 = 0, row1 = 0;
        bool v0 = m0 < Ml, v1 = m1 < Ml;
        if (v0) row0 = (size_t)(rowmap ? rowmap[m0] : m0);
        if (v1) row1 = (size_t)(rowmap ? rowmap[m1] : m1);
#pragma unroll
        for (int nt = 0; nt < 4; nt++) {
            int col = bn*128 + wn + nt*8 + tg*2;
            if (col >= N) continue;
            float bx = bias1[col], by = bias1[col+1];
            if (bias2) { bx += bias2[col]; by += bias2[col+1]; }
            if (v0) {
                float2 o = make_float2(acc[mt][nt][0] + bx, acc[mt][nt][1] + by);
                *(float2*)(C + row0*(size_t)ldc + col) = o;
            }
            if (v1) {
                float2 o = make_float2(acc[mt][nt][2] + bx, acc[mt][nt][3] + by);
                *(float2*)(C + row1*(size_t)ldc + col) = o;
            }
        }
    }
}

__global__ __launch_bounds__(256)
void k_gemm_pair(const float* __restrict__ b_enc, const float* __restrict__ b_ih,
                 const float* __restrict__ b_hh)
{
    __shared__ __align__(16) __nv_bfloat16 As[2][128*32];
    __shared__ __align__(16) __nv_bfloat16 Bs[2][128*32];
    int idx = blockIdx.x;
    if (idx < 392) {
        hgemm_body(idx >> 2, idx & 3, g_feats2, g_Wenc2, BB*PP, AA, AA,
                   b_enc, nullptr, g_encatt, nullptr, 0, As, Bs);
    } else {
        idx -= 392;
        hgemm_body(idx >> 4, idx & 15, g_embT2, g_Wih2, BB*TT, NG, NG,
                   b_ih, b_hh, g_embg, g_act, 1, As, Bs);
    }
}

__global__ __launch_bounds__(256)
void k_gemm_scores(const float* __restrict__ b_score, float* __restrict__ out)
{
    __shared__ __align__(16) __nv_bfloat16 As[2][128*32];
    __shared__ __align__(16) __nv_bfloat16 Bs[2][128*32];
    hgemm_body(blockIdx.x, blockIdx.y, g_hall2, g_Wsc2, BB*TT, VV, VV,
               b_score, nullptr, out, g_act, 1, As, Bs);
}

__global__ void k_cvt_hall() {
    int i = blockIdx.x*blockDim.x + threadIdx.x;
    if (i >= BB*TT*256) return;
    int r = i >> 8, c2 = i & 255, k = c2*2;
    float2 v = *(const float2*)(g_hall + (size_t)r*512 + k);
    uint32_t hp, lp; cvt_hilo2(v, hp, lp);
    ((uint32_t*)g_hall2)[(size_t)r*512 + c2] = hp;
    ((uint32_t*)g_hall2)[(size_t)r*512 + 256 + c2] = lp;
}

// ======================= fused persistent recurrence =======================
// smem byte offsets
#define WHH_OFF  0
#define WIHC_OFF 32768
#define WDEC_OFF 65536
#define HT_OFF   81920
#define PART_OFF 147456
#define GH_OFF   155648
#define SM_TOTAL 159744

// tree sense-reversing grid barrier (replay-safe; 4 sub-counters + root)
__device__ __forceinline__ void gridbar(int j) {
    __syncthreads();
    if (threadIdx.x == 0) {
        int* cp = &g_bc4[j & 3];
        int* rp = &g_broot;
        int* gp = &g_bgen;
        int gen;
        asm volatile("ld.acquire.gpu.global.s32 %0, [%1];" : "=r"(gen) : "l"(gp) : "memory");
        int old;
        asm volatile("atom.release.gpu.global.add.s32 %0, [%1], 1;" : "=r"(old) : "l"(cp) : "memory");
        if (old == (NCTA/4) - 1) {
            asm volatile("st.relaxed.gpu.global.s32 [%0], 0;" :: "l"(cp) : "memory");
            int old2;
            asm volatile("atom.release.gpu.global.add.s32 %0, [%1], 1;" : "=r"(old2) : "l"(rp) : "memory");
            if (old2 == 3) {
                asm volatile("st.relaxed.gpu.global.s32 [%0], 0;" :: "l"(rp) : "memory");
                asm volatile("st.release.gpu.global.s32 [%0], %1;" :: "l"(gp), "r"(gen+1) : "memory");
            }
        }
        if (1) {
            int v;
            do {
                asm volatile("ld.acquire.gpu.global.s32 %0, [%1];" : "=r"(v) : "l"(gp) : "memory");
            } while (v == gen);
        }
    }
    __syncthreads();
}

// stage 32 rows of fp32[512] (L2-coherent reads) into hi/lo swizzled tiles
__device__ __forceinline__ void stage32(const float* __restrict__ src, int b0, char* HTp, int tid) {
    for (int i = tid; i < 32*256; i += NTHR) {
        int r = i >> 8, kp = i & 255, k = kp*2;
        float2 v = __ldcg((const float2*)(src + (size_t)(b0+r)*512 + k));
        uint32_t hp, lp;
        cvt_hilo2(v, hp, lp);
        int kt = k >> 5, c = k & 31;
        stsw2(HTp + kt*2048, r, c, hp);
        stsw2(HTp + (16+kt)*2048, r, c, lp);
    }
}

// gates mma (ldmatrix): M=32, N=16, K=512, 3 hi/lo terms -> part[2][32][16]
__device__ __forceinline__ void gates_mma(uint32_t htA, uint32_t wbB, float* part,
                                          int wid, int lane) {
    int gq = lane >> 2, tg = lane & 3;
    int mh = (wid & 1)*16, nh = ((wid >> 1) & 1)*8, ks = wid >> 2;
    int rA = mh + (lane & 15);
    int swzA = (rA >> 1) & 3;
    int hiA = lane >> 4;
    int rB = nh + (lane & 7);
    int swzB = (rB >> 1) & 3;
    int hiB = (lane >> 3) & 1;
    uint32_t aL = htA + rA*64;
    uint32_t bL = wbB + rB*64;
    float acc[4] = {0.f, 0.f, 0.f, 0.f};
    for (int kt = ks*8; kt < ks*8 + 8; kt++) {
        uint32_t ah = aL + kt*2048;
        uint32_t bh = bL + kt*1024;
#pragma unroll
        for (int kk = 0; kk < 2; kk++) {
            uint32_t cA = (uint32_t)(((2*kk + hiA) ^ swzA) << 4);
            uint32_t cB = (uint32_t)(((2*kk + hiB) ^ swzB) << 4);
            uint32_t Ah[4], Al[4], Bh[2], Bl[2];
            ldsm_x4(Ah, ah + cA);
            ldsm_x4(Al, ah + 32768 + cA);
            ldsm_x2(Bh, bh + cB);
            ldsm_x2(Bl, bh + 16384 + cB);
            mma16816(acc, Ah, Bh);
            mma16816(acc, Ah, Bl);
            mma16816(acc, Al, Bh);
        }
    }
    int m0 = mh + gq, n0 = nh + tg*2;
    part[ks*512 + m0*16 + n0]       = acc[0];
    part[ks*512 + m0*16 + n0+1]     = acc[1];
    part[ks*512 + (m0+8)*16 + n0]   = acc[2];
    part[ks*512 + (m0+8)*16 + n0+1] = acc[3];
}

// att2 mma (ldmatrix): M=32, N=8 (4 real + 4 zero), K=512 -> part2[4][32][8]
__device__ __forceinline__ void att2_mma(uint32_t htA, uint32_t wdB, float* part2,
                                         int wid, int lane) {
    int gq = lane >> 2, tg = lane & 3;
    int mh = (wid & 1)*16, ks = wid >> 1;
    int rA = mh + (lane & 15);
    int swzA = (rA >> 1) & 3;
    int hiA = lane >> 4;
    int rB = lane & 7;
    int swzB = (rB >> 1) & 3;
    int hiB = (lane >> 3) & 1;
    uint32_t aL = htA + rA*64;
    uint32_t bL = wdB + rB*64;
    float acc[4] = {0.f, 0.f, 0.f, 0.f};
    for (int kt = ks*4; kt < ks*4 + 4; kt++) {
        uint32_t ah = aL + kt*2048;
        uint32_t bh = bL + kt*512;
#pragma unroll
        for (int kk = 0; kk < 2; kk++) {
            uint32_t cA = (uint32_t)(((2*kk + hiA) ^ swzA) << 4);
            uint32_t cB = (uint32_t)(((2*kk + hiB) ^ swzB) << 4);
            uint32_t Ah[4], Al[4], Bh[2], Bl[2];
            ldsm_x4(Ah, ah + cA);
            ldsm_x4(Al, ah + 32768 + cA);
            ldsm_x2(Bh, bh + cB);
            ldsm_x2(Bl, bh + 8192 + cB);
            mma16816(acc, Ah, Bh);
            mma16816(acc, Ah, Bl);
            mma16816(acc, Al, Bh);
        }
    }
    int m0 = mh + gq, n0 = tg*2;
    part2[ks*256 + m0*8 + n0]       = acc[0];
    part2[ks*256 + m0*8 + n0+1]     = acc[1];
    part2[ks*256 + (m0+8)*8 + n0]   = acc[2];
    part2[ks*256 + (m0+8)*8 + n0+1] = acc[3];
}

__global__ __launch_bounds__(NTHR)
void k_recur(const float* __restrict__ W_dec, const float* __restrict__ W_hh,
             const float* __restrict__ W_ih,
             const float* __restrict__ b_dec, const float* __restrict__ W_full,
             const float* __restrict__ b_full, float* __restrict__ out)
{
    extern __shared__ float sm[];
    char* smc = (char*)sm;
    __shared__ int sdl[BB];
    __shared__ int snb[TT];
    int tid = threadIdx.x, lane = tid & 31, wid = tid >> 5;
    int j = blockIdx.x;

    if (tid < BB) sdl[tid] = g_declen[tid];
    if (tid >= 64 && tid < 64 + TT) snb[tid - 64] = g_nbact[tid - 64];

    // convert weight slices to swizzled bf16 hi/lo tiles (once)
    for (int i = tid; i < 16*256; i += NTHR) {
        int r = i >> 8, kp = i & 255, k = kp*2;
        int gr = 512*(r >> 2) + j*4 + (r & 3);
        float2 w1 = *(const float2*)(W_hh + (size_t)gr*512 + k);
        float2 w2 = *(const float2*)(W_ih + (size_t)gr*1024 + 512 + k);
        uint32_t hp, lp;
        int kt = k >> 5, c = k & 31;
        cvt_hilo2(w1, hp, lp);
        stsw2(smc + WHH_OFF + kt*1024, r, c, hp);
        stsw2(smc + WHH_OFF + (16+kt)*1024, r, c, lp);
        cvt_hilo2(w2, hp, lp);
        stsw2(smc + WIHC_OFF + kt*1024, r, c, hp);
        stsw2(smc + WIHC_OFF + (16+kt)*1024, r, c, lp);
    }
    for (int i = tid; i < 8*256; i += NTHR) {
        int r = i >> 8, kp = i & 255, k = kp*2;
        float2 w = (r < 4) ? *(const float2*)(W_dec + (size_t)(j*4+r)*512 + k)
                           : make_float2(0.f, 0.f);
        uint32_t hp, lp;
        cvt_hilo2(w, hp, lp);
        int kt = k >> 5, c = k & 31;
        stsw2(smc + WDEC_OFF + kt*512, r, c, hp);
        stsw2(smc + WDEC_OFF + (16+kt)*512, r, c, lp);
    }
    __syncthreads();

    float* part  = (float*)(smc + PART_OFF);
    float* part2 = part + 1024;
    float* gh    = (float*)(smc + GH_OFF);
    uint32_t htS  = smem_u32(smc + HT_OFF);
    uint32_t whhS = smem_u32(smc + WHH_OFF);
    uint32_t wihS = smem_u32(smc + WIHC_OFF);
    uint32_t wdS  = smem_u32(smc + WDEC_OFF);

    for (int t = 0; t < TT; t++) {
        int npb = (snb[t] + 31) >> 5;
        // ---- Phase A: gates_h + att2 (mma) ----
        for (int pb = 0; pb < npb; pb++) {
            int b0 = pb*32;
            stage32(g_h, b0, smc + HT_OFF, tid);
            __syncthreads();
            gates_mma(htS, whhS, part, wid, lane);
            att2_mma(htS, wdS, part2, wid, lane);
            __syncthreads();
            for (int o = tid; o < 512; o += NTHR)
                gh[(b0 + (o >> 4))*16 + (o & 15)] = part[o] + part[512 + o];
            if (tid < 128) {
                int m = tid >> 2, q = tid & 3;
                float s = part2[m*8+q] + part2[256 + m*8+q] + part2[512 + m*8+q] + part2[768 + m*8+q];
                g_att2[(b0+m)*512 + j*4 + q] = s;
            }
            __syncthreads();
        }
        gridbar(j);

        // ---- Phase B: attention (CTAs 0..63, active only) ----
        if (j < BB && t < sdl[j]) {
            int b = j;
            float* wout = out + OFF_WEIGHTS + (size_t)(b*TT + t)*PP;
            float* s_e   = (float*)(smc + HT_OFF);
            float* s_red = s_e + 224;
            float* rbuf  = s_e + 512;
            // register-cached att2 + W_full
            float att2r[16], wfr[16];
#pragma unroll
            for (int k = 0; k < 16; k++) {
                int a = lane + 32*k;
                att2r[k] = __ldcg(&g_att2[b*512 + a]) + b_dec[a];
                wfr[k]   = W_full[a];
            }
            const float* ea = g_encatt + (size_t)b * PP * AA;
            for (int p = wid; p < PP; p += 8) {
                const float* row = ea + (size_t)p * AA;
                float sum = 0.f;
#pragma unroll
                for (int k = 0; k < 16; k++)
                    sum += fmaxf(row[lane + 32*k] + att2r[k], 0.f) * wfr[k];
#pragma unroll
                for (int o = 16; o; o >>= 1) sum += __shfl_xor_sync(0xffffffffu, sum, o);
                if (lane == 0) s_e[p] = sum + b_full[0];
            }
            __syncthreads();
            float m = -1e30f;
            if (tid < PP) m = s_e[tid];
#pragma unroll
            for (int o = 16; o; o >>= 1) m = fmaxf(m, __shfl_xor_sync(0xffffffffu, m, o));
            if (lane == 0) s_red[wid] = m;
            __syncthreads();
            float mx = s_red[0];
#pragma unroll
            for (int i = 1; i < 8; i++) mx = fmaxf(mx, s_red[i]);
            float ev = 0.f;
            if (tid < PP) ev = expf(s_e[tid] - mx);
            float sv = ev;
#pragma unroll
            for (int o = 16; o; o >>= 1) sv += __shfl_xor_sync(0xffffffffu, sv, o);
            __syncthreads();
            if (lane == 0) s_red[wid] = sv;
            __syncthreads();
            float tot = 0.f;
#pragma unroll
            for (int i = 0; i < 8; i++) tot += s_red[i];
            float inv = 1.f / tot;
            if (tid < PP) {
                float al = ev * inv;
                s_e[tid] = al;
                wout[tid] = al;
            }
            __syncthreads();
            int hq = tid & 63, pc2 = tid >> 6;
            const float4* fb4 = (const float4*)(g_feats + (size_t)b * PP * HH);
            float4 a0 = make_float4(0,0,0,0), a1 = make_float4(0,0,0,0);
            for (int p = pc2; p < PP; p += 4) {
                float al = s_e[p];
                float4 v0 = fb4[p*128 + hq*2];
                float4 v1 = fb4[p*128 + hq*2 + 1];
                a0.x = fmaf(al, v0.x, a0.x); a0.y = fmaf(al, v0.y, a0.y);
                a0.z = fmaf(al, v0.z, a0.z); a0.w = fmaf(al, v0.w, a0.w);
                a1.x = fmaf(al, v1.x, a1.x); a1.y = fmaf(al, v1.y, a1.y);
                a1.z = fmaf(al, v1.z, a1.z); a1.w = fmaf(al, v1.w, a1.w);
            }
            float* rb = rbuf + pc2*512 + hq*8;
            rb[0]=a0.x; rb[1]=a0.y; rb[2]=a0.z; rb[3]=a0.w;
            rb[4]=a1.x; rb[5]=a1.y; rb[6]=a1.z; rb[7]=a1.w;
            __syncthreads();
            for (int o = tid; o < 512; o += NTHR) {
                float s = rbuf[o] + rbuf[512+o] + rbuf[1024+o] + rbuf[1536+o];
                g_ctx[b*512 + o] = s;
            }
        }
        gridbar(j);

        // ---- Phase C: gates_ctx (mma) + combine + LSTM ----
        for (int pb = 0; pb < npb; pb++) {
            int b0 = pb*32;
            stage32(g_ctx, b0, smc + HT_OFF, tid);
            __syncthreads();
            gates_mma(htS, wihS, part, wid, lane);
            __syncthreads();
            for (int o = tid; o < 512; o += NTHR) {
                int m = o >> 4, n = o & 15;
                int b = b0 + m;
                int gr = 512*(n >> 2) + j*4 + (n & 3);
                gh[b*16 + n] += part[o] + part[512 + o] + g_embg[(size_t)(b*TT + t)*NG + gr];
            }
            __syncthreads();
        }
        {
            int b = tid >> 2, q = tid & 3;
            if (t < sdl[b]) {
                float gi = gh[b*16 + q];
                float gf = gh[b*16 + 4 + q];
                float gg = gh[b*16 + 8 + q];
                float go = gh[b*16 + 12 + q];
                float ig = 1.f / (1.f + expf(-gi));
                float fg = 1.f / (1.f + expf(-gf));
                float gv = tanhf(gg);
                float og = 1.f / (1.f + expf(-go));
                int kc = j*4 + q;
                float c_new = fg * g_c[b*512 + kc] + ig * gv;
                float h_new = og * tanhf(c_new);
                g_hall[(size_t)(b*TT + t)*512 + kc] = h_new;
                g_h[b*512 + kc] = h_new;
                g_c[b*512 + kc] = c_new;
            }
        }
        gridbar(j);
    }
}

// ======================= launch =======================
extern "C" void kernel_launch(void* const* d_in, const int* in_sizes, int n_in,
                              void* d_out, int out_size) {
    const float* imf     = (const float*)d_in[0];
    const int*   caps    = (const int*)  d_in[1];
    const int*   caplens = (const int*)  d_in[2];
    const float* emb     = (const float*)d_in[3];
    const float* W_ih    = (const float*)d_in[4];
    const float* W_hh    = (const float*)d_in[5];
    const float* b_ih    = (const float*)d_in[6];
    const float* b_hh    = (const float*)d_in[7];
    const float* W_enc   = (const float*)d_in[8];
    const float* b_enc   = (const float*)d_in[9];
    const float* W_dec   = (const float*)d_in[10];
    const float* b_dec   = (const float*)d_in[11];
    const float* W_full  = (const float*)d_in[12];
    const float* b_full  = (const float*)d_in[13];
    const float* W_score = (const float*)d_in[14];
    const float* b_score = (const float*)d_in[15];
    float* out = (float*)d_out;

    cudaFuncSetAttribute(k_recur, cudaFuncAttributeMaxDynamicSharedMemorySize, SM_TOTAL);

    // 1: sort + caps/declen/sortind outputs
    k_sort<<<1, BB>>>(caplens, caps, out);
    // 2: fused gathers + bf16 hi/lo conversions + zeroing + init
    k_cvt_all<<<1024, 256>>>(imf, caps, emb, W_enc, W_ih, W_score, out);
    // 3: fused enc_att + G_emb tensor-core GEMMs
    k_gemm_pair<<<792, 256>>>(b_enc, b_ih, b_hh);
    // 4: persistent recurrence
    k_recur<<<NCTA, NTHR, SM_TOTAL>>>(W_dec, W_hh, W_ih, b_dec, W_full, b_full, out);
    // 5: h history conversion
    k_cvt_hall<<<(BB*TT*256 + 255)/256, 256>>>();
    // 6: scores GEMM
    k_gemm_scores<<<dim3((BB*TT + 127)/128, (VV + 127)/128), 256>>>(b_score, out);
}

// round 9
// speedup vs baseline: 1.1963x; 1.0286x over previous
#include <cuda_runtime.h>
#include <cuda_bf16.h>
#include <cstdint>
#include <math.h>

#define BB 64
#define PP 196
#define HH 512
#define EE 512
#define AA 512
#define VV 10000
#define MAXCAP 50
#define TT 49
#define NG 2048   // 4*H

// output layout (float32): scores (B,T,V), caps_s (B,50), decode_lengths (B,), weights (B,T,P), sort_ind (B,)
#define N_SCORES   (BB*TT*VV)
#define OFF_CAPS   (N_SCORES)
#define OFF_DECLEN (OFF_CAPS + BB*MAXCAP)
#define OFF_WEIGHTS (OFF_DECLEN + BB)
#define OFF_SORT   (OFF_WEIGHTS + BB*TT*PP)

#define NCTA 128
#define NTHR 256

// ======================= scratch =======================
__device__ float g_feats[BB*PP*HH];
__device__ float g_encatt[BB*PP*AA];
__device__ float g_embg[BB*TT*NG];
__device__ float g_h[BB*HH];
__device__ float g_c[BB*HH];
__device__ float g_att2[BB*AA];
__device__ float g_ctx[BB*HH];
__device__ int   g_sortidx[BB];
__device__ int   g_declen[BB];
__device__ int   g_nbact[TT];
__device__ int   g_act[BB*TT];
__device__ int   g_nact;
__device__ int   g_bars[160];

// bf16 hi/lo packed [rows][1024]: cols 0-511 hi, 512-1023 lo
__device__ __nv_bfloat16 g_feats2[BB*PP*1024];
__device__ __nv_bfloat16 g_embT2[BB*TT*1024];
__device__ __nv_bfloat16 g_hall2[BB*TT*1024];
__device__ __nv_bfloat16 g_Wenc2[AA*1024];
__device__ __nv_bfloat16 g_Wih2[NG*1024];
__device__ __nv_bfloat16 g_Wsc2[VV*1024];

// ======================= helpers =======================
__device__ __forceinline__ void mma16816(float* d, const uint32_t* a, const uint32_t* b) {
    asm volatile("mma.sync.aligned.m16n8k16.row.col.f32.bf16.bf16.f32 "
        "{%0,%1,%2,%3}, {%4,%5,%6,%7}, {%8,%9}, {%0,%1,%2,%3};"
        : "+f"(d[0]), "+f"(d[1]), "+f"(d[2]), "+f"(d[3])
        : "r"(a[0]), "r"(a[1]), "r"(a[2]), "r"(a[3]), "r"(b[0]), "r"(b[1]));
}
__device__ __forceinline__ void ldsm_x4(uint32_t* r, uint32_t saddr) {
    asm volatile("ldmatrix.sync.aligned.m8n8.x4.shared.b16 {%0,%1,%2,%3}, [%4];"
        : "=r"(r[0]), "=r"(r[1]), "=r"(r[2]), "=r"(r[3]) : "r"(saddr));
}
__device__ __forceinline__ void ldsm_x2(uint32_t* r, uint32_t saddr) {
    asm volatile("ldmatrix.sync.aligned.m8n8.x2.shared.b16 {%0,%1}, [%2];"
        : "=r"(r[0]), "=r"(r[1]) : "r"(saddr));
}
__device__ __forceinline__ uint32_t smem_u32(const void* p) {
    return (uint32_t)__cvta_generic_to_shared(p);
}
// store bf16x2 at (r, c even 0..31) in swizzled tile (64B rows, 16B-chunk XOR)
__device__ __forceinline__ void stsw2(char* s, int r, int c, uint32_t v) {
    int byte = r*64 + ((((c >> 3) ^ ((r >> 1) & 3))) << 4) + (c & 7)*2;
    *(uint32_t*)(s + byte) = v;
}
__device__ __forceinline__ void cvt_hilo2(float2 v, uint32_t& hp, uint32_t& lp) {
    __nv_bfloat16 h0 = __float2bfloat16(v.x), h1 = __float2bfloat16(v.y);
    float l0 = v.x - __bfloat162float(h0), l1 = v.y - __bfloat162float(h1);
    __nv_bfloat16 b0 = __float2bfloat16(l0), b1 = __float2bfloat16(l1);
    hp = (uint32_t)__bfloat16_as_ushort(h0) | ((uint32_t)__bfloat16_as_ushort(h1) << 16);
    lp = (uint32_t)__bfloat16_as_ushort(b0) | ((uint32_t)__bfloat16_as_ushort(b1) << 16);
}

// ======================= prep kernels =======================
__global__ void k_sort(const int* __restrict__ caplens, const int* __restrict__ caps,
                       float* __restrict__ out) {
    __shared__ int s_sort[BB];
    if (threadIdx.x == 0) {
        int cl[BB];
        for (int i = 0; i < BB; i++) cl[i] = caplens[i];
        int r = 0;
        for (int v = MAXCAP; v >= 0 && r < BB; v--)
            for (int i = 0; i < BB; i++)
                if (cl[i] == v) { g_sortidx[r] = i; s_sort[r] = i; r++; }
        int na = 0;
        int dls[BB];
        for (int b = 0; b < BB; b++) {
            int dl = cl[g_sortidx[b]] - 1;
            dls[b] = dl;
            g_declen[b] = dl;
            out[OFF_DECLEN + b] = (float)dl;
            out[OFF_SORT + b]   = (float)g_sortidx[b];
            for (int t = 0; t < dl; t++) g_act[na++] = b*TT + t;
        }
        g_nact = na;
        for (int t = 0; t < TT; t++) {
            int c = 0;
            for (int b = 0; b < BB; b++) if (dls[b] > t) c++;
            g_nbact[t] = c;
        }
    }
    __syncthreads();
    int b = threadIdx.x;
    int src = s_sort[b];
    for (int t = 0; t < MAXCAP; t++)
        out[OFF_CAPS + b*MAXCAP + t] = (float)caps[src*MAXCAP + t];
}

// fused gather + hi/lo conversion (pairwise) + zero + init
#define P0 (BB*PP*256)
#define P1 (BB*TT*256)
#define P2 (AA*256)
#define P3 (NG*256)
#define P4 (VV*256)
#define Z5 (N_SCORES/4)
#define Z6 (BB*TT*PP/4)
#define Z7 (BB*HH)
#define Z8 160
__global__ void k_cvt_all(const float* __restrict__ imf, const int* __restrict__ caps,
                          const float* __restrict__ emb, const float* __restrict__ W_enc,
                          const float* __restrict__ W_ih, const float* __restrict__ W_score,
                          float* __restrict__ out)
{
    const int total = P0+P1+P2+P3+P4+Z5+Z6+Z7+Z8;
    for (int i = blockIdx.x*blockDim.x + threadIdx.x; i < total; i += gridDim.x*blockDim.x) {
        int x = i;
        if (x < P0) {
            int r = x >> 8, c2 = x & 255, k = c2*2;
            int b = r / PP, p = r - b*PP;
            float2 v = *(const float2*)(imf + ((size_t)g_sortidx[b]*PP + p)*512 + k);
            *(float2*)(g_feats + (size_t)r*512 + k) = v;
            uint32_t hp, lp; cvt_hilo2(v, hp, lp);
            ((uint32_t*)g_feats2)[(size_t)r*512 + c2] = hp;
            ((uint32_t*)g_feats2)[(size_t)r*512 + 256 + c2] = lp;
            continue;
        }
        x -= P0;
        if (x < P1) {
            int r = x >> 8, c2 = x & 255, k = c2*2;
            int b = r / TT, t = r - b*TT;
            int tok = caps[g_sortidx[b]*MAXCAP + t];
            float2 v = *(const float2*)(emb + (size_t)tok*512 + k);
            uint32_t hp, lp; cvt_hilo2(v, hp, lp);
            ((uint32_t*)g_embT2)[(size_t)r*512 + c2] = hp;
            ((uint32_t*)g_embT2)[(size_t)r*512 + 256 + c2] = lp;
            continue;
        }
        x -= P1;
        if (x < P2) {
            int r = x >> 8, c2 = x & 255, k = c2*2;
            float2 v = *(const float2*)(W_enc + (size_t)r*512 + k);
            uint32_t hp, lp; cvt_hilo2(v, hp, lp);
            ((uint32_t*)g_Wenc2)[(size_t)r*512 + c2] = hp;
            ((uint32_t*)g_Wenc2)[(size_t)r*512 + 256 + c2] = lp;
            continue;
        }
        x -= P2;
        if (x < P3) {
            int r = x >> 8, c2 = x & 255, k = c2*2;
            float2 v = *(const float2*)(W_ih + (size_t)r*1024 + k);
            uint32_t hp, lp; cvt_hilo2(v, hp, lp);
            ((uint32_t*)g_Wih2)[(size_t)r*512 + c2] = hp;
            ((uint32_t*)g_Wih2)[(size_t)r*512 + 256 + c2] = lp;
            continue;
        }
        x -= P3;
        if (x < P4) {
            int r = x >> 8, c2 = x & 255, k = c2*2;
            float2 v = *(const float2*)(W_score + (size_t)r*512 + k);
            uint32_t hp, lp; cvt_hilo2(v, hp, lp);
            ((uint32_t*)g_Wsc2)[(size_t)r*512 + c2] = hp;
            ((uint32_t*)g_Wsc2)[(size_t)r*512 + 256 + c2] = lp;
            continue;
        }
        x -= P4;
        if (x < Z5) {
            ((float4*)out)[x] = make_float4(0.f, 0.f, 0.f, 0.f);
            continue;
        }
        x -= Z5;
        if (x < Z6) {
            ((float4*)(out + OFF_WEIGHTS))[x] = make_float4(0.f, 0.f, 0.f, 0.f);
            continue;
        }
        x -= Z6;
        if (x < Z7) { g_h[x] = 0.f; g_c[x] = 0.f; continue; }
        x -= Z7;
        g_bars[x] = 0;
    }
}

// ======================= mma.sync bf16x3 GEMM body (ldmatrix + double buffer) ==========
__device__ __forceinline__ void hgemm_body(
    int bm, int bn,
    const __nv_bfloat16* __restrict__ A2, const __nv_bfloat16* __restrict__ B2,
    int M, int N, int ldc,
    const float* __restrict__ bias1, const float* __restrict__ bias2,
    float* __restrict__ C, const int* __restrict__ rowmap, int use_nact,
    __nv_bfloat16 (*As)[128*32], __nv_bfloat16 (*Bs)[128*32])
{
    int tid = threadIdx.x;
    int Ml = use_nact ? g_nact : M;
    if (bm*128 >= Ml) return;

    int lrow = tid >> 1;
    int lc0 = (tid & 1) * 2;
    int gm = bm*128 + lrow;
    const uint4* arow = nullptr;
    if (gm < Ml) { int r = rowmap ? rowmap[gm] : gm; arow = (const uint4*)(A2 + (size_t)r*1024); }
    int gn = bn*128 + lrow;
    const uint4* brow = (gn < N) ? (const uint4*)(B2 + (size_t)gn*1024) : nullptr;

    int swz = (lrow >> 1) & 3;
    uint4* aswp[2] = {(uint4*)(As[0] + lrow*32), (uint4*)(As[1] + lrow*32)};
    uint4* bswp[2] = {(uint4*)(Bs[0] + lrow*32), (uint4*)(Bs[1] + lrow*32)};
    int c0 = lc0 ^ swz, c1 = (lc0+1) ^ swz;

    int lane = tid & 31, wid = tid >> 5;
    int wm = (wid >> 2) * 64;
    int wn = (wid & 3) * 32;
    int gq = lane >> 2, tg = lane & 3;

    int rA = wm + (lane & 15);
    int swzA = (rA >> 1) & 3;
    int hiA = lane >> 4;
    int rB = wn + (lane & 7);
    int swzB = (rB >> 1) & 3;
    int hiB = (lane >> 3) & 1;
    uint32_t aS[2] = {smem_u32(As[0]) + rA*64, smem_u32(As[1]) + rA*64};
    uint32_t bS[2] = {smem_u32(Bs[0]) + rB*64, smem_u32(Bs[1]) + rB*64};

    float acc[4][4][4];
#pragma unroll
    for (int mt = 0; mt < 4; mt++)
#pragma unroll
        for (int nt = 0; nt < 4; nt++)
#pragma unroll
            for (int r = 0; r < 4; r++) acc[mt][nt][r] = 0.f;

    const uint4 z = make_uint4(0,0,0,0);
    const int kau4[3] = {0, 0, 64};
    const int kbu4[3] = {0, 64, 0};
    uint4 pa0 = arow ? arow[lc0]   : z;
    uint4 pa1 = arow ? arow[lc0+1] : z;
    uint4 pb0 = brow ? brow[lc0]   : z;
    uint4 pb1 = brow ? brow[lc0+1] : z;
    aswp[0][c0] = pa0; aswp[0][c1] = pa1;
    bswp[0][c0] = pb0; bswp[0][c1] = pb1;
    __syncthreads();

    for (int ci = 0; ci < 48; ci++) {
        int cur = ci & 1;
        if (ci + 1 < 48) {
            int term = (ci+1) >> 4, kc = (ci+1) & 15;
            int ab = kau4[term] + kc*4, bb = kbu4[term] + kc*4;
            pa0 = arow ? arow[ab + lc0]   : z;
            pa1 = arow ? arow[ab + lc0+1] : z;
            pb0 = brow ? brow[bb + lc0]   : z;
            pb1 = brow ? brow[bb + lc0+1] : z;
        }
#pragma unroll
        for (int kk = 0; kk < 2; kk++) {
            uint32_t cA = (uint32_t)(((2*kk + hiA) ^ swzA) << 4);
            uint32_t cB = (uint32_t)(((2*kk + hiB) ^ swzB) << 4);
            uint32_t afr[4][4];
#pragma unroll
            for (int mt = 0; mt < 4; mt++)
                ldsm_x4(afr[mt], aS[cur] + mt*1024 + cA);
            uint32_t bfr[4][2];
#pragma unroll
            for (int nt = 0; nt < 4; nt++)
                ldsm_x2(bfr[nt], bS[cur] + nt*512 + cB);
#pragma unroll
            for (int mt = 0; mt < 4; mt++)
#pragma unroll
                for (int nt = 0; nt < 4; nt++)
                    mma16816(acc[mt][nt], afr[mt], bfr[nt]);
        }
        if (ci + 1 < 48) {
            int nxt = cur ^ 1;
            aswp[nxt][c0] = pa0; aswp[nxt][c1] = pa1;
            bswp[nxt][c0] = pb0; bswp[nxt][c1] = pb1;
        }
        __syncthreads();
    }

#pragma unroll
    for (int mt = 0; mt < 4; mt++) {
        int m0 = bm*128 + wm + mt*16 + gq;
        int m1 = m0 + 8;
        size_t row0 = 0, row1 = 0;
        bool v0 = m0 < Ml, v1 = m1 < Ml;
        if (v0) row0 = (size_t)(rowmap ? rowmap[m0] : m0);
        if (v1) row1 = (size_t)(rowmap ? rowmap[m1] : m1);
#pragma unroll
        for (int nt = 0; nt < 4; nt++) {
            int col = bn*128 + wn + nt*8 + tg*2;
            if (col >= N) continue;
            float bx = bias1[col], by = bias1[col+1];
            if (bias2) { bx += bias2[col]; by += bias2[col+1]; }
            if (v0) {
                float2 o = make_float2(acc[mt][nt][0] + bx, acc[mt][nt][1] + by);
                *(float2*)(C + row0*(size_t)ldc + col) = o;
            }
            if (v1) {
                float2 o = make_float2(acc[mt][nt][2] + bx, acc[mt][nt][3] + by);
                *(float2*)(C + row1*(size_t)ldc + col) = o;
            }
        }
    }
}

__global__ __launch_bounds__(256)
void k_gemm_pair(const float* __restrict__ b_enc, const float* __restrict__ b_ih,
                 const float* __restrict__ b_hh)
{
    __shared__ __align__(16) __nv_bfloat16 As[2][128*32];
    __shared__ __align__(16) __nv_bfloat16 Bs[2][128*32];
    int idx = blockIdx.x;
    if (idx < 392) {
        hgemm_body(idx >> 2, idx & 3, g_feats2, g_Wenc2, BB*PP, AA, AA,
                   b_enc, nullptr, g_encatt, nullptr, 0, As, Bs);
    } else {
        idx -= 392;
        hgemm_body(idx >> 4, idx & 15, g_embT2, g_Wih2, BB*TT, NG, NG,
                   b_ih, b_hh, g_embg, g_act, 1, As, Bs);
    }
}

__global__ __launch_bounds__(256)
void k_gemm_scores(const float* __restrict__ b_score, float* __restrict__ out)
{
    __shared__ __align__(16) __nv_bfloat16 As[2][128*32];
    __shared__ __align__(16) __nv_bfloat16 Bs[2][128*32];
    hgemm_body(blockIdx.x, blockIdx.y, g_hall2, g_Wsc2, BB*TT, VV, VV,
               b_score, nullptr, out, g_act, 1, As, Bs);
}

// ======================= fused persistent recurrence =======================
// smem byte offsets
#define WHH_OFF  0
#define WIHC_OFF 32768
#define WDEC_OFF 65536
#define HT_OFF   81920
#define PART_OFF 147456
#define GH_OFF   155648
#define SM_TOTAL 159744

// per-slot flat barrier (replay-safe) with nanosleep-backoff polling
__device__ __forceinline__ void gridbar(int slot) {
    __syncthreads();
    if (threadIdx.x == 0) {
        int* p = &g_bars[slot];
        asm volatile("red.release.gpu.global.add.s32 [%0], 1;" :: "l"(p) : "memory");
        int v;
        unsigned ns = 64;
        while (1) {
            asm volatile("ld.acquire.gpu.global.s32 %0, [%1];" : "=r"(v) : "l"(p) : "memory");
            if (v >= NCTA) break;
            __nanosleep(ns);
            if (ns < 2048) ns <<= 1;
        }
    }
    __syncthreads();
}

// stage 32 rows of fp32[512] (L2-coherent reads) into hi/lo swizzled tiles
__device__ __forceinline__ void stage32(const float* __restrict__ src, int b0, char* HTp, int tid) {
    for (int i = tid; i < 32*256; i += NTHR) {
        int r = i >> 8, kp = i & 255, k = kp*2;
        float2 v = __ldcg((const float2*)(src + (size_t)(b0+r)*512 + k));
        uint32_t hp, lp;
        cvt_hilo2(v, hp, lp);
        int kt = k >> 5, c = k & 31;
        stsw2(HTp + kt*2048, r, c, hp);
        stsw2(HTp + (16+kt)*2048, r, c, lp);
    }
}

// gates mma (ldmatrix): M=32, N=16, K=512, 3 hi/lo terms -> part[2][32][16]
__device__ __forceinline__ void gates_mma(uint32_t htA, uint32_t wbB, float* part,
                                          int wid, int lane) {
    int gq = lane >> 2, tg = lane & 3;
    int mh = (wid & 1)*16, nh = ((wid >> 1) & 1)*8, ks = wid >> 2;
    int rA = mh + (lane & 15);
    int swzA = (rA >> 1) & 3;
    int hiA = lane >> 4;
    int rB = nh + (lane & 7);
    int swzB = (rB >> 1) & 3;
    int hiB = (lane >> 3) & 1;
    uint32_t aL = htA + rA*64;
    uint32_t bL = wbB + rB*64;
    float acc[4] = {0.f, 0.f, 0.f, 0.f};
    for (int kt = ks*8; kt < ks*8 + 8; kt++) {
        uint32_t ah = aL + kt*2048;
        uint32_t bh = bL + kt*1024;
#pragma unroll
        for (int kk = 0; kk < 2; kk++) {
            uint32_t cA = (uint32_t)(((2*kk + hiA) ^ swzA) << 4);
            uint32_t cB = (uint32_t)(((2*kk + hiB) ^ swzB) << 4);
            uint32_t Ah[4], Al[4], Bh[2], Bl[2];
            ldsm_x4(Ah, ah + cA);
            ldsm_x4(Al, ah + 32768 + cA);
            ldsm_x2(Bh, bh + cB);
            ldsm_x2(Bl, bh + 16384 + cB);
            mma16816(acc, Ah, Bh);
            mma16816(acc, Ah, Bl);
            mma16816(acc, Al, Bh);
        }
    }
    int m0 = mh + gq, n0 = nh + tg*2;
    part[ks*512 + m0*16 + n0]       = acc[0];
    part[ks*512 + m0*16 + n0+1]     = acc[1];
    part[ks*512 + (m0+8)*16 + n0]   = acc[2];
    part[ks*512 + (m0+8)*16 + n0+1] = acc[3];
}

// att2 mma (ldmatrix): M=32, N=8 (4 real + 4 zero), K=512 -> part2[4][32][8]
__device__ __forceinline__ void att2_mma(uint32_t htA, uint32_t wdB, float* part2,
                                         int wid, int lane) {
    int gq = lane >> 2, tg = lane & 3;
    int mh = (wid & 1)*16, ks = wid >> 1;
    int rA = mh + (lane & 15);
    int swzA = (rA >> 1) & 3;
    int hiA = lane >> 4;
    int rB = lane & 7;
    int swzB = (rB >> 1) & 3;
    int hiB = (lane >> 3) & 1;
    uint32_t aL = htA + rA*64;
    uint32_t bL = wdB + rB*64;
    float acc[4] = {0.f, 0.f, 0.f, 0.f};
    for (int kt = ks*4; kt < ks*4 + 4; kt++) {
        uint32_t ah = aL + kt*2048;
        uint32_t bh = bL + kt*512;
#pragma unroll
        for (int kk = 0; kk < 2; kk++) {
            uint32_t cA = (uint32_t)(((2*kk + hiA) ^ swzA) << 4);
            uint32_t cB = (uint32_t)(((2*kk + hiB) ^ swzB) << 4);
            uint32_t Ah[4], Al[4], Bh[2], Bl[2];
            ldsm_x4(Ah, ah + cA);
            ldsm_x4(Al, ah + 32768 + cA);
            ldsm_x2(Bh, bh + cB);
            ldsm_x2(Bl, bh + 8192 + cB);
            mma16816(acc, Ah, Bh);
            mma16816(acc, Ah, Bl);
            mma16816(acc, Al, Bh);
        }
    }
    int m0 = mh + gq, n0 = tg*2;
    part2[ks*256 + m0*8 + n0]       = acc[0];
    part2[ks*256 + m0*8 + n0+1]     = acc[1];
    part2[ks*256 + (m0+8)*8 + n0]   = acc[2];
    part2[ks*256 + (m0+8)*8 + n0+1] = acc[3];
}

__global__ __launch_bounds__(NTHR)
void k_recur(const float* __restrict__ W_dec, const float* __restrict__ W_hh,
             const float* __restrict__ W_ih,
             const float* __restrict__ b_dec, const float* __restrict__ W_full,
             const float* __restrict__ b_full, float* __restrict__ out)
{
    extern __shared__ float sm[];
    char* smc = (char*)sm;
    __shared__ int sdl[BB];
    __shared__ int snb[TT];
    int tid = threadIdx.x, lane = tid & 31, wid = tid >> 5;
    int j = blockIdx.x;

    if (tid < BB) sdl[tid] = g_declen[tid];
    if (tid >= 64 && tid < 64 + TT) snb[tid - 64] = g_nbact[tid - 64];

    // convert weight slices to swizzled bf16 hi/lo tiles (once)
    for (int i = tid; i < 16*256; i += NTHR) {
        int r = i >> 8, kp = i & 255, k = kp*2;
        int gr = 512*(r >> 2) + j*4 + (r & 3);
        float2 w1 = *(const float2*)(W_hh + (size_t)gr*512 + k);
        float2 w2 = *(const float2*)(W_ih + (size_t)gr*1024 + 512 + k);
        uint32_t hp, lp;
        int kt = k >> 5, c = k & 31;
        cvt_hilo2(w1, hp, lp);
        stsw2(smc + WHH_OFF + kt*1024, r, c, hp);
        stsw2(smc + WHH_OFF + (16+kt)*1024, r, c, lp);
        cvt_hilo2(w2, hp, lp);
        stsw2(smc + WIHC_OFF + kt*1024, r, c, hp);
        stsw2(smc + WIHC_OFF + (16+kt)*1024, r, c, lp);
    }
    for (int i = tid; i < 8*256; i += NTHR) {
        int r = i >> 8, kp = i & 255, k = kp*2;
        float2 w = (r < 4) ? *(const float2*)(W_dec + (size_t)(j*4+r)*512 + k)
                           : make_float2(0.f, 0.f);
        uint32_t hp, lp;
        cvt_hilo2(w, hp, lp);
        int kt = k >> 5, c = k & 31;
        stsw2(smc + WDEC_OFF + kt*512, r, c, hp);
        stsw2(smc + WDEC_OFF + (16+kt)*512, r, c, lp);
    }
    __syncthreads();

    float* part  = (float*)(smc + PART_OFF);
    float* part2 = part + 1024;
    float* gh    = (float*)(smc + GH_OFF);
    uint32_t htS  = smem_u32(smc + HT_OFF);
    uint32_t whhS = smem_u32(smc + WHH_OFF);
    uint32_t wihS = smem_u32(smc + WIHC_OFF);
    uint32_t wdS  = smem_u32(smc + WDEC_OFF);

    int nbar = 0;
    for (int t = 0; t < TT; t++) {
        int npb = (snb[t] + 31) >> 5;
        // ---- Phase A: gates_h + att2 (mma) ----
        for (int pb = 0; pb < npb; pb++) {
            int b0 = pb*32;
            stage32(g_h, b0, smc + HT_OFF, tid);
            __syncthreads();
            gates_mma(htS, whhS, part, wid, lane);
            att2_mma(htS, wdS, part2, wid, lane);
            __syncthreads();
            for (int o = tid; o < 512; o += NTHR)
                gh[(b0 + (o >> 4))*16 + (o & 15)] = part[o] + part[512 + o];
            if (tid < 128) {
                int m = tid >> 2, q = tid & 3;
                float s = part2[m*8+q] + part2[256 + m*8+q] + part2[512 + m*8+q] + part2[768 + m*8+q];
                g_att2[(b0+m)*512 + j*4 + q] = s;
            }
            __syncthreads();
        }
        gridbar(nbar++);

        // ---- Phase B: attention (CTAs 0..63, active only) ----
        if (j < BB && t < sdl[j]) {
            int b = j;
            float* wout = out + OFF_WEIGHTS + (size_t)(b*TT + t)*PP;
            float* att = (float*)(smc + HT_OFF);
            float* s_att2 = att;
            float* s_wf   = att + 512;
            float* s_e    = att + 1024;
            float* s_red  = att + 1248;
            float* rbuf   = att + 1280;
            for (int a = tid; a < AA; a += NTHR) {
                s_att2[a] = __ldcg(&g_att2[b*512 + a]) + b_dec[a];
                s_wf[a] = W_full[a];
            }
            __syncthreads();
            const float* ea = g_encatt + (size_t)b * PP * AA;
            for (int p = wid; p < PP; p += 8) {
                const float* row = ea + (size_t)p * AA;
                float sum = 0.f;
                for (int a = lane; a < AA; a += 32)
                    sum += fmaxf(row[a] + s_att2[a], 0.f) * s_wf[a];
#pragma unroll
                for (int o = 16; o; o >>= 1) sum += __shfl_xor_sync(0xffffffffu, sum, o);
                if (lane == 0) s_e[p] = sum + b_full[0];
            }
            __syncthreads();
            float m = -1e30f;
            if (tid < PP) m = s_e[tid];
#pragma unroll
            for (int o = 16; o; o >>= 1) m = fmaxf(m, __shfl_xor_sync(0xffffffffu, m, o));
            if (lane == 0) s_red[wid] = m;
            __syncthreads();
            float mx = s_red[0];
#pragma unroll
            for (int i = 1; i < 8; i++) mx = fmaxf(mx, s_red[i]);
            float ev = 0.f;
            if (tid < PP) ev = expf(s_e[tid] - mx);
            float sv = ev;
#pragma unroll
            for (int o = 16; o; o >>= 1) sv += __shfl_xor_sync(0xffffffffu, sv, o);
            __syncthreads();
            if (lane == 0) s_red[wid] = sv;
            __syncthreads();
            float tot = 0.f;
#pragma unroll
            for (int i = 0; i < 8; i++) tot += s_red[i];
            float inv = 1.f / tot;
            if (tid < PP) {
                float al = ev * inv;
                s_e[tid] = al;
                wout[tid] = al;
            }
            __syncthreads();
            int hq = tid & 63, pc2 = tid >> 6;
            const float4* fb4 = (const float4*)(g_feats + (size_t)b * PP * HH);
            float4 a0 = make_float4(0,0,0,0), a1 = make_float4(0,0,0,0);
            for (int p = pc2; p < PP; p += 4) {
                float al = s_e[p];
                float4 v0 = fb4[p*128 + hq*2];
                float4 v1 = fb4[p*128 + hq*2 + 1];
                a0.x = fmaf(al, v0.x, a0.x); a0.y = fmaf(al, v0.y, a0.y);
                a0.z = fmaf(al, v0.z, a0.z); a0.w = fmaf(al, v0.w, a0.w);
                a1.x = fmaf(al, v1.x, a1.x); a1.y = fmaf(al, v1.y, a1.y);
                a1.z = fmaf(al, v1.z, a1.z); a1.w = fmaf(al, v1.w, a1.w);
            }
            float* rb = rbuf + pc2*512 + hq*8;
            rb[0]=a0.x; rb[1]=a0.y; rb[2]=a0.z; rb[3]=a0.w;
            rb[4]=a1.x; rb[5]=a1.y; rb[6]=a1.z; rb[7]=a1.w;
            __syncthreads();
            for (int o = tid; o < 512; o += NTHR) {
                float s = rbuf[o] + rbuf[512+o] + rbuf[1024+o] + rbuf[1536+o];
                g_ctx[b*512 + o] = s;
            }
        }
        gridbar(nbar++);

        // ---- Phase C: gates_ctx (mma) + combine + LSTM ----
        for (int pb = 0; pb < npb; pb++) {
            int b0 = pb*32;
            stage32(g_ctx, b0, smc + HT_OFF, tid);
            __syncthreads();
            gates_mma(htS, wihS, part, wid, lane);
            __syncthreads();
            for (int o = tid; o < 512; o += NTHR) {
                int m = o >> 4, n = o & 15;
                int b = b0 + m;
                int gr = 512*(n >> 2) + j*4 + (n & 3);
                gh[b*16 + n] += part[o] + part[512 + o] + g_embg[(size_t)(b*TT + t)*NG + gr];
            }
            __syncthreads();
        }
        {
            int b = tid >> 2, q = tid & 3;
            if (t < sdl[b]) {
                float gi = gh[b*16 + q];
                float gf = gh[b*16 + 4 + q];
                float gg = gh[b*16 + 8 + q];
                float go = gh[b*16 + 12 + q];
                float ig = 1.f / (1.f + expf(-gi));
                float fg = 1.f / (1.f + expf(-gf));
                float gv = tanhf(gg);
                float og = 1.f / (1.f + expf(-go));
                int kc = j*4 + q;
                float c_new = fg * g_c[b*512 + kc] + ig * gv;
                float h_new = og * tanhf(c_new);
                // write bf16 hi/lo history directly (replaces g_hall + k_cvt_hall)
                __nv_bfloat16 hh = __float2bfloat16(h_new);
                __nv_bfloat16 hl = __float2bfloat16(h_new - __bfloat162float(hh));
                g_hall2[(size_t)(b*TT + t)*1024 + kc]       = hh;
                g_hall2[(size_t)(b*TT + t)*1024 + 512 + kc] = hl;
                g_h[b*512 + kc] = h_new;
                g_c[b*512 + kc] = c_new;
            }
        }
        gridbar(nbar++);
    }
}

// ======================= launch =======================
extern "C" void kernel_launch(void* const* d_in, const int* in_sizes, int n_in,
                              void* d_out, int out_size) {
    const float* imf     = (const float*)d_in[0];
    const int*   caps    = (const int*)  d_in[1];
    const int*   caplens = (const int*)  d_in[2];
    const float* emb     = (const float*)d_in[3];
    const float* W_ih    = (const float*)d_in[4];
    const float* W_hh    = (const float*)d_in[5];
    const float* b_ih    = (const float*)d_in[6];
    const float* b_hh    = (const float*)d_in[7];
    const float* W_enc   = (const float*)d_in[8];
    const float* b_enc   = (const float*)d_in[9];
    const float* W_dec   = (const float*)d_in[10];
    const float* b_dec   = (const float*)d_in[11];
    const float* W_full  = (const float*)d_in[12];
    const float* b_full  = (const float*)d_in[13];
    const float* W_score = (const float*)d_in[14];
    const float* b_score = (const float*)d_in[15];
    float* out = (float*)d_out;

    cudaFuncSetAttribute(k_recur, cudaFuncAttributeMaxDynamicSharedMemorySize, SM_TOTAL);

    // 1: sort + caps/declen/sortind outputs
    k_sort<<<1, BB>>>(caplens, caps, out);
    // 2: fused gathers + bf16 hi/lo conversions + zeroing + init
    k_cvt_all<<<1024, 256>>>(imf, caps, emb, W_enc, W_ih, W_score, out);
    // 3: fused enc_att + G_emb tensor-core GEMMs
    k_gemm_pair<<<792, 256>>>(b_enc, b_ih, b_hh);
    // 4: persistent recurrence (writes g_hall2 directly)
    k_recur<<<NCTA, NTHR, SM_TOTAL>>>(W_dec, W_hh, W_ih, b_dec, W_full, b_full, out);
    // 5: scores GEMM
    k_gemm_scores<<<dim3((BB*TT + 127)/128, (VV + 127)/128), 256>>>(b_score, out);
}

// round 10
// speedup vs baseline: 1.2473x; 1.0427x over previous
#include <cuda_runtime.h>
#include <cuda_bf16.h>
#include <cstdint>
#include <math.h>

#define BB 64
#define PP 196
#define HH 512
#define EE 512
#define AA 512
#define VV 10000
#define MAXCAP 50
#define TT 49
#define NG 2048   // 4*H

// output layout (float32): scores (B,T,V), caps_s (B,50), decode_lengths (B,), weights (B,T,P), sort_ind (B,)
#define N_SCORES   (BB*TT*VV)
#define OFF_CAPS   (N_SCORES)
#define OFF_DECLEN (OFF_CAPS + BB*MAXCAP)
#define OFF_WEIGHTS (OFF_DECLEN + BB)
#define OFF_SORT   (OFF_WEIGHTS + BB*TT*PP)

#define NCTA 128
#define NTHR 256
#define NBAR 152

// ======================= scratch =======================
__device__ float g_feats[BB*PP*HH];
__device__ float g_encatt[BB*PP*AA];
__device__ float g_embg[BB*TT*NG];
__device__ float g_h[BB*HH];
__device__ float g_c[BB*HH];
__device__ float g_att2[BB*AA];
__device__ float g_ctx[BB*HH];
__device__ int   g_sortidx[BB];
__device__ int   g_declen[BB];
__device__ int   g_nbact[TT];
__device__ int   g_act[BB*TT];
__device__ int   g_nact;
// two-level barrier state: 4 leaves per slot on distinct 128B lines + root per slot
__device__ int   g_bleaf[NBAR*4*32];   // leaf (slot,q) at g_bleaf[(slot*4+q)*32]
__device__ int   g_broot[NBAR*32];     // root slot at g_broot[slot*32]

// bf16 hi/lo packed [rows][1024]: cols 0-511 hi, 512-1023 lo
__device__ __nv_bfloat16 g_feats2[BB*PP*1024];
__device__ __nv_bfloat16 g_embT2[BB*TT*1024];
__device__ __nv_bfloat16 g_hall2[BB*TT*1024];
__device__ __nv_bfloat16 g_Wenc2[AA*1024];
__device__ __nv_bfloat16 g_Wih2[NG*1024];
__device__ __nv_bfloat16 g_Wsc2[VV*1024];

// ======================= helpers =======================
__device__ __forceinline__ void mma16816(float* d, const uint32_t* a, const uint32_t* b) {
    asm volatile("mma.sync.aligned.m16n8k16.row.col.f32.bf16.bf16.f32 "
        "{%0,%1,%2,%3}, {%4,%5,%6,%7}, {%8,%9}, {%0,%1,%2,%3};"
        : "+f"(d[0]), "+f"(d[1]), "+f"(d[2]), "+f"(d[3])
        : "r"(a[0]), "r"(a[1]), "r"(a[2]), "r"(a[3]), "r"(b[0]), "r"(b[1]));
}
__device__ __forceinline__ void ldsm_x4(uint32_t* r, uint32_t saddr) {
    asm volatile("ldmatrix.sync.aligned.m8n8.x4.shared.b16 {%0,%1,%2,%3}, [%4];"
        : "=r"(r[0]), "=r"(r[1]), "=r"(r[2]), "=r"(r[3]) : "r"(saddr));
}
__device__ __forceinline__ void ldsm_x2(uint32_t* r, uint32_t saddr) {
    asm volatile("ldmatrix.sync.aligned.m8n8.x2.shared.b16 {%0,%1}, [%2];"
        : "=r"(r[0]), "=r"(r[1]) : "r"(saddr));
}
__device__ __forceinline__ uint32_t smem_u32(const void* p) {
    return (uint32_t)__cvta_generic_to_shared(p);
}
// store bf16x2 at (r, c even 0..31) in swizzled tile (64B rows, 16B-chunk XOR)
__device__ __forceinline__ void stsw2(char* s, int r, int c, uint32_t v) {
    int byte = r*64 + ((((c >> 3) ^ ((r >> 1) & 3))) << 4) + (c & 7)*2;
    *(uint32_t*)(s + byte) = v;
}
__device__ __forceinline__ void cvt_hilo2(float2 v, uint32_t& hp, uint32_t& lp) {
    __nv_bfloat16 h0 = __float2bfloat16(v.x), h1 = __float2bfloat16(v.y);
    float l0 = v.x - __bfloat162float(h0), l1 = v.y - __bfloat162float(h1);
    __nv_bfloat16 b0 = __float2bfloat16(l0), b1 = __float2bfloat16(l1);
    hp = (uint32_t)__bfloat16_as_ushort(h0) | ((uint32_t)__bfloat16_as_ushort(h1) << 16);
    lp = (uint32_t)__bfloat16_as_ushort(b0) | ((uint32_t)__bfloat16_as_ushort(b1) << 16);
}

// ======================= prep kernels =======================
__global__ void k_sort(const int* __restrict__ caplens, const int* __restrict__ caps,
                       float* __restrict__ out) {
    __shared__ int s_sort[BB];
    if (threadIdx.x == 0) {
        int cl[BB];
        for (int i = 0; i < BB; i++) cl[i] = caplens[i];
        int r = 0;
        for (int v = MAXCAP; v >= 0 && r < BB; v--)
            for (int i = 0; i < BB; i++)
                if (cl[i] == v) { g_sortidx[r] = i; s_sort[r] = i; r++; }
        int na = 0;
        int dls[BB];
        for (int b = 0; b < BB; b++) {
            int dl = cl[g_sortidx[b]] - 1;
            dls[b] = dl;
            g_declen[b] = dl;
            out[OFF_DECLEN + b] = (float)dl;
            out[OFF_SORT + b]   = (float)g_sortidx[b];
            for (int t = 0; t < dl; t++) g_act[na++] = b*TT + t;
        }
        g_nact = na;
        for (int t = 0; t < TT; t++) {
            int c = 0;
            for (int b = 0; b < BB; b++) if (dls[b] > t) c++;
            g_nbact[t] = c;
        }
    }
    __syncthreads();
    int b = threadIdx.x;
    int src = s_sort[b];
    for (int t = 0; t < MAXCAP; t++)
        out[OFF_CAPS + b*MAXCAP + t] = (float)caps[src*MAXCAP + t];
}

// fused gather + hi/lo conversion (pairwise) + zero + init
#define P0 (BB*PP*256)
#define P1 (BB*TT*256)
#define P2 (AA*256)
#define P3 (NG*256)
#define P4 (VV*256)
#define Z5 (N_SCORES/4)
#define Z6 (BB*TT*PP/4)
#define Z7 (BB*HH)
#define Z8 (NBAR*4*32 + NBAR*32)
__global__ void k_cvt_all(const float* __restrict__ imf, const int* __restrict__ caps,
                          const float* __restrict__ emb, const float* __restrict__ W_enc,
                          const float* __restrict__ W_ih, const float* __restrict__ W_score,
                          float* __restrict__ out)
{
    const int total = P0+P1+P2+P3+P4+Z5+Z6+Z7+Z8;
    for (int i = blockIdx.x*blockDim.x + threadIdx.x; i < total; i += gridDim.x*blockDim.x) {
        int x = i;
        if (x < P0) {
            int r = x >> 8, c2 = x & 255, k = c2*2;
            int b = r / PP, p = r - b*PP;
            float2 v = *(const float2*)(imf + ((size_t)g_sortidx[b]*PP + p)*512 + k);
            *(float2*)(g_feats + (size_t)r*512 + k) = v;
            uint32_t hp, lp; cvt_hilo2(v, hp, lp);
            ((uint32_t*)g_feats2)[(size_t)r*512 + c2] = hp;
            ((uint32_t*)g_feats2)[(size_t)r*512 + 256 + c2] = lp;
            continue;
        }
        x -= P0;
        if (x < P1) {
            int r = x >> 8, c2 = x & 255, k = c2*2;
            int b = r / TT, t = r - b*TT;
            int tok = caps[g_sortidx[b]*MAXCAP + t];
            float2 v = *(const float2*)(emb + (size_t)tok*512 + k);
            uint32_t hp, lp; cvt_hilo2(v, hp, lp);
            ((uint32_t*)g_embT2)[(size_t)r*512 + c2] = hp;
            ((uint32_t*)g_embT2)[(size_t)r*512 + 256 + c2] = lp;
            continue;
        }
        x -= P1;
        if (x < P2) {
            int r = x >> 8, c2 = x & 255, k = c2*2;
            float2 v = *(const float2*)(W_enc + (size_t)r*512 + k);
            uint32_t hp, lp; cvt_hilo2(v, hp, lp);
            ((uint32_t*)g_Wenc2)[(size_t)r*512 + c2] = hp;
            ((uint32_t*)g_Wenc2)[(size_t)r*512 + 256 + c2] = lp;
            continue;
        }
        x -= P2;
        if (x < P3) {
            int r = x >> 8, c2 = x & 255, k = c2*2;
            float2 v = *(const float2*)(W_ih + (size_t)r*1024 + k);
            uint32_t hp, lp; cvt_hilo2(v, hp, lp);
            ((uint32_t*)g_Wih2)[(size_t)r*512 + c2] = hp;
            ((uint32_t*)g_Wih2)[(size_t)r*512 + 256 + c2] = lp;
            continue;
        }
        x -= P3;
        if (x < P4) {
            int r = x >> 8, c2 = x & 255, k = c2*2;
            float2 v = *(const float2*)(W_score + (size_t)r*512 + k);
            uint32_t hp, lp; cvt_hilo2(v, hp, lp);
            ((uint32_t*)g_Wsc2)[(size_t)r*512 + c2] = hp;
            ((uint32_t*)g_Wsc2)[(size_t)r*512 + 256 + c2] = lp;
            continue;
        }
        x -= P4;
        if (x < Z5) {
            ((float4*)out)[x] = make_float4(0.f, 0.f, 0.f, 0.f);
            continue;
        }
        x -= Z5;
        if (x < Z6) {
            ((float4*)(out + OFF_WEIGHTS))[x] = make_float4(0.f, 0.f, 0.f, 0.f);
            continue;
        }
        x -= Z6;
        if (x < Z7) { g_h[x] = 0.f; g_c[x] = 0.f; continue; }
        x -= Z7;
        if (x < NBAR*4*32) { g_bleaf[x] = 0; continue; }
        x -= NBAR*4*32;
        g_broot[x] = 0;
    }
}

// ======================= mma.sync bf16x3 GEMM body (ldmatrix + double buffer) ==========
__device__ __forceinline__ void hgemm_body(
    int bm, int bn,
    const __nv_bfloat16* __restrict__ A2, const __nv_bfloat16* __restrict__ B2,
    int M, int N, int ldc,
    const float* __restrict__ bias1, const float* __restrict__ bias2,
    float* __restrict__ C, const int* __restrict__ rowmap, int use_nact,
    __nv_bfloat16 (*As)[128*32], __nv_bfloat16 (*Bs)[128*32])
{
    int tid = threadIdx.x;
    int Ml = use_nact ? g_nact : M;
    if (bm*128 >= Ml) return;

    int lrow = tid >> 1;
    int lc0 = (tid & 1) * 2;
    int gm = bm*128 + lrow;
    const uint4* arow = nullptr;
    if (gm < Ml) { int r = rowmap ? rowmap[gm] : gm; arow = (const uint4*)(A2 + (size_t)r*1024); }
    int gn = bn*128 + lrow;
    const uint4* brow = (gn < N) ? (const uint4*)(B2 + (size_t)gn*1024) : nullptr;

    int swz = (lrow >> 1) & 3;
    uint4* aswp[2] = {(uint4*)(As[0] + lrow*32), (uint4*)(As[1] + lrow*32)};
    uint4* bswp[2] = {(uint4*)(Bs[0] + lrow*32), (uint4*)(Bs[1] + lrow*32)};
    int c0 = lc0 ^ swz, c1 = (lc0+1) ^ swz;

    int lane = tid & 31, wid = tid >> 5;
    int wm = (wid >> 2) * 64;
    int wn = (wid & 3) * 32;
    int gq = lane >> 2, tg = lane & 3;

    int rA = wm + (lane & 15);
    int swzA = (rA >> 1) & 3;
    int hiA = lane >> 4;
    int rB = wn + (lane & 7);
    int swzB = (rB >> 1) & 3;
    int hiB = (lane >> 3) & 1;
    uint32_t aS[2] = {smem_u32(As[0]) + rA*64, smem_u32(As[1]) + rA*64};
    uint32_t bS[2] = {smem_u32(Bs[0]) + rB*64, smem_u32(Bs[1]) + rB*64};

    float acc[4][4][4];
#pragma unroll
    for (int mt = 0; mt < 4; mt++)
#pragma unroll
        for (int nt = 0; nt < 4; nt++)
#pragma unroll
            for (int r = 0; r < 4; r++) acc[mt][nt][r] = 0.f;

    const uint4 z = make_uint4(0,0,0,0);
    const int kau4[3] = {0, 0, 64};
    const int kbu4[3] = {0, 64, 0};
    uint4 pa0 = arow ? arow[lc0]   : z;
    uint4 pa1 = arow ? arow[lc0+1] : z;
    uint4 pb0 = brow ? brow[lc0]   : z;
    uint4 pb1 = brow ? brow[lc0+1] : z;
    aswp[0][c0] = pa0; aswp[0][c1] = pa1;
    bswp[0][c0] = pb0; bswp[0][c1] = pb1;
    __syncthreads();

    for (int ci = 0; ci < 48; ci++) {
        int cur = ci & 1;
        if (ci + 1 < 48) {
            int term = (ci+1) >> 4, kc = (ci+1) & 15;
            int ab = kau4[term] + kc*4, bb = kbu4[term] + kc*4;
            pa0 = arow ? arow[ab + lc0]   : z;
            pa1 = arow ? arow[ab + lc0+1] : z;
            pb0 = brow ? brow[bb + lc0]   : z;
            pb1 = brow ? brow[bb + lc0+1] : z;
        }
#pragma unroll
        for (int kk = 0; kk < 2; kk++) {
            uint32_t cA = (uint32_t)(((2*kk + hiA) ^ swzA) << 4);
            uint32_t cB = (uint32_t)(((2*kk + hiB) ^ swzB) << 4);
            uint32_t afr[4][4];
#pragma unroll
            for (int mt = 0; mt < 4; mt++)
                ldsm_x4(afr[mt], aS[cur] + mt*1024 + cA);
            uint32_t bfr[4][2];
#pragma unroll
            for (int nt = 0; nt < 4; nt++)
                ldsm_x2(bfr[nt], bS[cur] + nt*512 + cB);
#pragma unroll
            for (int mt = 0; mt < 4; mt++)
#pragma unroll
                for (int nt = 0; nt < 4; nt++)
                    mma16816(acc[mt][nt], afr[mt], bfr[nt]);
        }
        if (ci + 1 < 48) {
            int nxt = cur ^ 1;
            aswp[nxt][c0] = pa0; aswp[nxt][c1] = pa1;
            bswp[nxt][c0] = pb0; bswp[nxt][c1] = pb1;
        }
        __syncthreads();
    }

#pragma unroll
    for (int mt = 0; mt < 4; mt++) {
        int m0 = bm*128 + wm + mt*16 + gq;
        int m1 = m0 + 8;
        size_t row0 = 0, row1 = 0;
        bool v0 = m0 < Ml, v1 = m1 < Ml;
        if (v0) row0 = (size_t)(rowmap ? rowmap[m0] : m0);
        if (v1) row1 = (size_t)(rowmap ? rowmap[m1] : m1);
#pragma unroll
        for (int nt = 0; nt < 4; nt++) {
            int col = bn*128 + wn + nt*8 + tg*2;
            if (col >= N) continue;
            float bx = bias1[col], by = bias1[col+1];
            if (bias2) { bx += bias2[col]; by += bias2[col+1]; }
            if (v0) {
                float2 o = make_float2(acc[mt][nt][0] + bx, acc[mt][nt][1] + by);
                *(float2*)(C + row0*(size_t)ldc + col) = o;
            }
            if (v1) {
                float2 o = make_float2(acc[mt][nt][2] + bx, acc[mt][nt][3] + by);
                *(float2*)(C + row1*(size_t)ldc + col) = o;
            }
        }
    }
}

__global__ __launch_bounds__(256)
void k_gemm_pair(const float* __restrict__ b_enc, const float* __restrict__ b_ih,
                 const float* __restrict__ b_hh)
{
    __shared__ __align__(16) __nv_bfloat16 As[2][128*32];
    __shared__ __align__(16) __nv_bfloat16 Bs[2][128*32];
    int idx = blockIdx.x;
    if (idx < 392) {
        hgemm_body(idx >> 2, idx & 3, g_feats2, g_Wenc2, BB*PP, AA, AA,
                   b_enc, nullptr, g_encatt, nullptr, 0, As, Bs);
    } else {
        idx -= 392;
        hgemm_body(idx >> 4, idx & 15, g_embT2, g_Wih2, BB*TT, NG, NG,
                   b_ih, b_hh, g_embg, g_act, 1, As, Bs);
    }
}

__global__ __launch_bounds__(256)
void k_gemm_scores(const float* __restrict__ b_score, float* __restrict__ out)
{
    __shared__ __align__(16) __nv_bfloat16 As[2][128*32];
    __shared__ __align__(16) __nv_bfloat16 Bs[2][128*32];
    hgemm_body(blockIdx.x, blockIdx.y, g_hall2, g_Wsc2, BB*TT, VV, VV,
               b_score, nullptr, out, g_act, 1, As, Bs);
}

// ======================= fused persistent recurrence =======================
// smem byte offsets
#define WHH_OFF  0
#define WIHC_OFF 32768
#define WDEC_OFF 65536
#define HT_OFF   81920
#define PART_OFF 147456
#define GH_OFF   155648
#define SM_TOTAL 159744

// two-level per-slot barrier (replay-safe, monotonic): 4 leaves + root, tight spin
__device__ __forceinline__ void gridbar(int slot, int j) {
    __syncthreads();
    if (threadIdx.x == 0) {
        int* leaf = &g_bleaf[(slot*4 + (j & 3))*32];
        int* root = &g_broot[slot*32];
        int old;
        asm volatile("atom.acq_rel.gpu.global.add.s32 %0, [%1], 1;" : "=r"(old) : "l"(leaf) : "memory");
        if (old == (NCTA/4) - 1)
            asm volatile("red.release.gpu.global.add.s32 [%0], 1;" :: "l"(root) : "memory");
        int v;
        do {
            asm volatile("ld.acquire.gpu.global.s32 %0, [%1];" : "=r"(v) : "l"(root) : "memory");
        } while (v < 4);
    }
    __syncthreads();
}

// stage 32 rows of fp32[512] (L2-coherent reads) into hi/lo swizzled tiles
__device__ __forceinline__ void stage32(const float* __restrict__ src, int b0, char* HTp, int tid) {
    for (int i = tid; i < 32*256; i += NTHR) {
        int r = i >> 8, kp = i & 255, k = kp*2;
        float2 v = __ldcg((const float2*)(src + (size_t)(b0+r)*512 + k));
        uint32_t hp, lp;
        cvt_hilo2(v, hp, lp);
        int kt = k >> 5, c = k & 31;
        stsw2(HTp + kt*2048, r, c, hp);
        stsw2(HTp + (16+kt)*2048, r, c, lp);
    }
}

// gates mma (ldmatrix): M=32, N=16, K=512, 3 hi/lo terms -> part[2][32][16]
__device__ __forceinline__ void gates_mma(uint32_t htA, uint32_t wbB, float* part,
                                          int wid, int lane) {
    int gq = lane >> 2, tg = lane & 3;
    int mh = (wid & 1)*16, nh = ((wid >> 1) & 1)*8, ks = wid >> 2;
    int rA = mh + (lane & 15);
    int swzA = (rA >> 1) & 3;
    int hiA = lane >> 4;
    int rB = nh + (lane & 7);
    int swzB = (rB >> 1) & 3;
    int hiB = (lane >> 3) & 1;
    uint32_t aL = htA + rA*64;
    uint32_t bL = wbB + rB*64;
    float acc[4] = {0.f, 0.f, 0.f, 0.f};
    for (int kt = ks*8; kt < ks*8 + 8; kt++) {
        uint32_t ah = aL + kt*2048;
        uint32_t bh = bL + kt*1024;
#pragma unroll
        for (int kk = 0; kk < 2; kk++) {
            uint32_t cA = (uint32_t)(((2*kk + hiA) ^ swzA) << 4);
            uint32_t cB = (uint32_t)(((2*kk + hiB) ^ swzB) << 4);
            uint32_t Ah[4], Al[4], Bh[2], Bl[2];
            ldsm_x4(Ah, ah + cA);
            ldsm_x4(Al, ah + 32768 + cA);
            ldsm_x2(Bh, bh + cB);
            ldsm_x2(Bl, bh + 16384 + cB);
            mma16816(acc, Ah, Bh);
            mma16816(acc, Ah, Bl);
            mma16816(acc, Al, Bh);
        }
    }
    int m0 = mh + gq, n0 = nh + tg*2;
    part[ks*512 + m0*16 + n0]       = acc[0];
    part[ks*512 + m0*16 + n0+1]     = acc[1];
    part[ks*512 + (m0+8)*16 + n0]   = acc[2];
    part[ks*512 + (m0+8)*16 + n0+1] = acc[3];
}

// att2 mma (ldmatrix): M=32, N=8 (4 real + 4 zero), K=512 -> part2[4][32][8]
__device__ __forceinline__ void att2_mma(uint32_t htA, uint32_t wdB, float* part2,
                                         int wid, int lane) {
    int gq = lane >> 2, tg = lane & 3;
    int mh = (wid & 1)*16, ks = wid >> 1;
    int rA = mh + (lane & 15);
    int swzA = (rA >> 1) & 3;
    int hiA = lane >> 4;
    int rB = lane & 7;
    int swzB = (rB >> 1) & 3;
    int hiB = (lane >> 3) & 1;
    uint32_t aL = htA + rA*64;
    uint32_t bL = wdB + rB*64;
    float acc[4] = {0.f, 0.f, 0.f, 0.f};
    for (int kt = ks*4; kt < ks*4 + 4; kt++) {
        uint32_t ah = aL + kt*2048;
        uint32_t bh = bL + kt*512;
#pragma unroll
        for (int kk = 0; kk < 2; kk++) {
            uint32_t cA = (uint32_t)(((2*kk + hiA) ^ swzA) << 4);
            uint32_t cB = (uint32_t)(((2*kk + hiB) ^ swzB) << 4);
            uint32_t Ah[4], Al[4], Bh[2], Bl[2];
            ldsm_x4(Ah, ah + cA);
            ldsm_x4(Al, ah + 32768 + cA);
            ldsm_x2(Bh, bh + cB);
            ldsm_x2(Bl, bh + 8192 + cB);
            mma16816(acc, Ah, Bh);
            mma16816(acc, Ah, Bl);
            mma16816(acc, Al, Bh);
        }
    }
    int m0 = mh + gq, n0 = tg*2;
    part2[ks*256 + m0*8 + n0]       = acc[0];
    part2[ks*256 + m0*8 + n0+1]     = acc[1];
    part2[ks*256 + (m0+8)*8 + n0]   = acc[2];
    part2[ks*256 + (m0+8)*8 + n0+1] = acc[3];
}

__global__ __launch_bounds__(NTHR)
void k_recur(const float* __restrict__ W_dec, const float* __restrict__ W_hh,
             const float* __restrict__ W_ih,
             const float* __restrict__ b_dec, const float* __restrict__ W_full,
             const float* __restrict__ b_full, float* __restrict__ out)
{
    extern __shared__ float sm[];
    char* smc = (char*)sm;
    __shared__ int sdl[BB];
    __shared__ int snb[TT];
    int tid = threadIdx.x, lane = tid & 31, wid = tid >> 5;
    int j = blockIdx.x;

    if (tid < BB) sdl[tid] = g_declen[tid];
    if (tid >= 64 && tid < 64 + TT) snb[tid - 64] = g_nbact[tid - 64];

    // convert weight slices to swizzled bf16 hi/lo tiles (once)
    for (int i = tid; i < 16*256; i += NTHR) {
        int r = i >> 8, kp = i & 255, k = kp*2;
        int gr = 512*(r >> 2) + j*4 + (r & 3);
        float2 w1 = *(const float2*)(W_hh + (size_t)gr*512 + k);
        float2 w2 = *(const float2*)(W_ih + (size_t)gr*1024 + 512 + k);
        uint32_t hp, lp;
        int kt = k >> 5, c = k & 31;
        cvt_hilo2(w1, hp, lp);
        stsw2(smc + WHH_OFF + kt*1024, r, c, hp);
        stsw2(smc + WHH_OFF + (16+kt)*1024, r, c, lp);
        cvt_hilo2(w2, hp, lp);
        stsw2(smc + WIHC_OFF + kt*1024, r, c, hp);
        stsw2(smc + WIHC_OFF + (16+kt)*1024, r, c, lp);
    }
    for (int i = tid; i < 8*256; i += NTHR) {
        int r = i >> 8, kp = i & 255, k = kp*2;
        float2 w = (r < 4) ? *(const float2*)(W_dec + (size_t)(j*4+r)*512 + k)
                           : make_float2(0.f, 0.f);
        uint32_t hp, lp;
        cvt_hilo2(w, hp, lp);
        int kt = k >> 5, c = k & 31;
        stsw2(smc + WDEC_OFF + kt*512, r, c, hp);
        stsw2(smc + WDEC_OFF + (16+kt)*512, r, c, lp);
    }
    __syncthreads();

    float* part  = (float*)(smc + PART_OFF);
    float* part2 = part + 1024;
    float* gh    = (float*)(smc + GH_OFF);
    uint32_t htS  = smem_u32(smc + HT_OFF);
    uint32_t whhS = smem_u32(smc + WHH_OFF);
    uint32_t wihS = smem_u32(smc + WIHC_OFF);
    uint32_t wdS  = smem_u32(smc + WDEC_OFF);

    int nbar = 0;
    for (int t = 0; t < TT; t++) {
        int npb = (snb[t] + 31) >> 5;
        // ---- Phase A: gates_h + att2 (mma) ----
        for (int pb = 0; pb < npb; pb++) {
            int b0 = pb*32;
            stage32(g_h, b0, smc + HT_OFF, tid);
            __syncthreads();
            gates_mma(htS, whhS, part, wid, lane);
            att2_mma(htS, wdS, part2, wid, lane);
            __syncthreads();
            for (int o = tid; o < 512; o += NTHR)
                gh[(b0 + (o >> 4))*16 + (o & 15)] = part[o] + part[512 + o];
            if (tid < 128) {
                int m = tid >> 2, q = tid & 3;
                float s = part2[m*8+q] + part2[256 + m*8+q] + part2[512 + m*8+q] + part2[768 + m*8+q];
                g_att2[(b0+m)*512 + j*4 + q] = s;
            }
            __syncthreads();
        }
        gridbar(nbar++, j);

        // ---- Phase B: attention (CTAs 0..63, active only) ----
        if (j < BB && t < sdl[j]) {
            int b = j;
            float* wout = out + OFF_WEIGHTS + (size_t)(b*TT + t)*PP;
            float* att = (float*)(smc + HT_OFF);
            float* s_att2 = att;
            float* s_wf   = att + 512;
            float* s_e    = att + 1024;
            float* s_red  = att + 1248;
            float* rbuf   = att + 1280;
            for (int a = tid; a < AA; a += NTHR) {
                s_att2[a] = __ldcg(&g_att2[b*512 + a]) + b_dec[a];
                s_wf[a] = W_full[a];
            }
            __syncthreads();
            const float* ea = g_encatt + (size_t)b * PP * AA;
            for (int p = wid; p < PP; p += 8) {
                const float* row = ea + (size_t)p * AA;
                float sum = 0.f;
                for (int a = lane; a < AA; a += 32)
                    sum += fmaxf(row[a] + s_att2[a], 0.f) * s_wf[a];
#pragma unroll
                for (int o = 16; o; o >>= 1) sum += __shfl_xor_sync(0xffffffffu, sum, o);
                if (lane == 0) s_e[p] = sum + b_full[0];
            }
            __syncthreads();
            float m = -1e30f;
            if (tid < PP) m = s_e[tid];
#pragma unroll
            for (int o = 16; o; o >>= 1) m = fmaxf(m, __shfl_xor_sync(0xffffffffu, m, o));
            if (lane == 0) s_red[wid] = m;
            __syncthreads();
            float mx = s_red[0];
#pragma unroll
            for (int i = 1; i < 8; i++) mx = fmaxf(mx, s_red[i]);
            float ev = 0.f;
            if (tid < PP) ev = expf(s_e[tid] - mx);
            float sv = ev;
#pragma unroll
            for (int o = 16; o; o >>= 1) sv += __shfl_xor_sync(0xffffffffu, sv, o);
            __syncthreads();
            if (lane == 0) s_red[wid] = sv;
            __syncthreads();
            float tot = 0.f;
#pragma unroll
            for (int i = 0; i < 8; i++) tot += s_red[i];
            float inv = 1.f / tot;
            if (tid < PP) {
                float al = ev * inv;
                s_e[tid] = al;
                wout[tid] = al;
            }
            __syncthreads();
            int hq = tid & 63, pc2 = tid >> 6;
            const float4* fb4 = (const float4*)(g_feats + (size_t)b * PP * HH);
            float4 a0 = make_float4(0,0,0,0), a1 = make_float4(0,0,0,0);
            for (int p = pc2; p < PP; p += 4) {
                float al = s_e[p];
                float4 v0 = fb4[p*128 + hq*2];
                float4 v1 = fb4[p*128 + hq*2 + 1];
                a0.x = fmaf(al, v0.x, a0.x); a0.y = fmaf(al, v0.y, a0.y);
                a0.z = fmaf(al, v0.z, a0.z); a0.w = fmaf(al, v0.w, a0.w);
                a1.x = fmaf(al, v1.x, a1.x); a1.y = fmaf(al, v1.y, a1.y);
                a1.z = fmaf(al, v1.z, a1.z); a1.w = fmaf(al, v1.w, a1.w);
            }
            float* rb = rbuf + pc2*512 + hq*8;
            rb[0]=a0.x; rb[1]=a0.y; rb[2]=a0.z; rb[3]=a0.w;
            rb[4]=a1.x; rb[5]=a1.y; rb[6]=a1.z; rb[7]=a1.w;
            __syncthreads();
            for (int o = tid; o < 512; o += NTHR) {
                float s = rbuf[o] + rbuf[512+o] + rbuf[1024+o] + rbuf[1536+o];
                g_ctx[b*512 + o] = s;
            }
        }
        gridbar(nbar++, j);

        // ---- Phase C: gates_ctx (mma) + combine + LSTM ----
        for (int pb = 0; pb < npb; pb++) {
            int b0 = pb*32;
            stage32(g_ctx, b0, smc + HT_OFF, tid);
            __syncthreads();
            gates_mma(htS, wihS, part, wid, lane);
            __syncthreads();
            for (int o = tid; o < 512; o += NTHR) {
                int m = o >> 4, n = o & 15;
                int b = b0 + m;
                int gr = 512*(n >> 2) + j*4 + (n & 3);
                gh[b*16 + n] += part[o] + part[512 + o] + g_embg[(size_t)(b*TT + t)*NG + gr];
            }
            __syncthreads();
        }
        {
            int b = tid >> 2, q = tid & 3;
            if (t < sdl[b]) {
                float gi = gh[b*16 + q];
                float gf = gh[b*16 + 4 + q];
                float gg = gh[b*16 + 8 + q];
                float go = gh[b*16 + 12 + q];
                float ig = 1.f / (1.f + expf(-gi));
                float fg = 1.f / (1.f + expf(-gf));
                float gv = tanhf(gg);
                float og = 1.f / (1.f + expf(-go));
                int kc = j*4 + q;
                float c_new = fg * g_c[b*512 + kc] + ig * gv;
                float h_new = og * tanhf(c_new);
                // write bf16 hi/lo history directly (replaces g_hall + k_cvt_hall)
                __nv_bfloat16 hh = __float2bfloat16(h_new);
                __nv_bfloat16 hl = __float2bfloat16(h_new - __bfloat162float(hh));
                g_hall2[(size_t)(b*TT + t)*1024 + kc]       = hh;
                g_hall2[(size_t)(b*TT + t)*1024 + 512 + kc] = hl;
                g_h[b*512 + kc] = h_new;
                g_c[b*512 + kc] = c_new;
            }
        }
        gridbar(nbar++, j);
    }
}

// ======================= launch =======================
extern "C" void kernel_launch(void* const* d_in, const int* in_sizes, int n_in,
                              void* d_out, int out_size) {
    const float* imf     = (const float*)d_in[0];
    const int*   caps    = (const int*)  d_in[1];
    const int*   caplens = (const int*)  d_in[2];
    const float* emb     = (const float*)d_in[3];
    const float* W_ih    = (const float*)d_in[4];
    const float* W_hh    = (const float*)d_in[5];
    const float* b_ih    = (const float*)d_in[6];
    const float* b_hh    = (const float*)d_in[7];
    const float* W_enc   = (const float*)d_in[8];
    const float* b_enc   = (const float*)d_in[9];
    const float* W_dec   = (const float*)d_in[10];
    const float* b_dec   = (const float*)d_in[11];
    const float* W_full  = (const float*)d_in[12];
    const float* b_full  = (const float*)d_in[13];
    const float* W_score = (const float*)d_in[14];
    const float* b_score = (const float*)d_in[15];
    float* out = (float*)d_out;

    cudaFuncSetAttribute(k_recur, cudaFuncAttributeMaxDynamicSharedMemorySize, SM_TOTAL);

    // 1: sort + caps/declen/sortind outputs
    k_sort<<<1, BB>>>(caplens, caps, out);
    // 2: fused gathers + bf16 hi/lo conversions + zeroing + init
    k_cvt_all<<<1024, 256>>>(imf, caps, emb, W_enc, W_ih, W_score, out);
    // 3: fused enc_att + G_emb tensor-core GEMMs
    k_gemm_pair<<<792, 256>>>(b_enc, b_ih, b_hh);
    // 4: persistent recurrence (writes g_hall2 directly)
    k_recur<<<NCTA, NTHR, SM_TOTAL>>>(W_dec, W_hh, W_ih, b_dec, W_full, b_full, out);
    // 5: scores GEMM
    k_gemm_scores<<<dim3((BB*TT + 127)/128, (VV + 127)/128), 256>>>(b_score, out);
}

// round 11
// speedup vs baseline: 1.7659x; 1.4157x over previous
#include <cuda_runtime.h>
#include <cuda_bf16.h>
#include <cstdint>
#include <math.h>

#define BB 64
#define PP 196
#define HH 512
#define EE 512
#define AA 512
#define VV 10000
#define MAXCAP 50
#define TT 49
#define NG 2048   // 4*H

// output layout (float32): scores (B,T,V), caps_s (B,50), decode_lengths (B,), weights (B,T,P), sort_ind (B,)
#define N_SCORES   (BB*TT*VV)
#define OFF_CAPS   (N_SCORES)
#define OFF_DECLEN (OFF_CAPS + BB*MAXCAP)
#define OFF_WEIGHTS (OFF_DECLEN + BB)
#define OFF_SORT   (OFF_WEIGHTS + BB*TT*PP)

#define NCTA 128
#define NTHR 256
#define NTHR_R 512

// ======================= scratch =======================
__device__ float g_feats[BB*PP*HH];
__device__ float g_encatt[BB*PP*AA];
__device__ float g_embg[BB*TT*NG];
__device__ float g_h[BB*HH];
__device__ float g_c[BB*HH];
__device__ float g_att2[BB*AA];
__device__ float g_ctx[BB*HH];
__device__ int   g_sortidx[BB];
__device__ int   g_declen[BB];
__device__ int   g_nbact[TT];
__device__ int   g_act[BB*TT];
__device__ int   g_nact;
__device__ int   g_bars[160];

// bf16 hi/lo packed [rows][1024]: cols 0-511 hi, 512-1023 lo
__device__ __nv_bfloat16 g_feats2[BB*PP*1024];
__device__ __nv_bfloat16 g_embT2[BB*TT*1024];
__device__ __nv_bfloat16 g_hall2[BB*TT*1024];
__device__ __nv_bfloat16 g_Wenc2[AA*1024];
__device__ __nv_bfloat16 g_Wih2[NG*1024];
__device__ __nv_bfloat16 g_Wsc2[VV*1024];

// ======================= helpers =======================
__device__ __forceinline__ void mma16816(float* d, const uint32_t* a, const uint32_t* b) {
    asm volatile("mma.sync.aligned.m16n8k16.row.col.f32.bf16.bf16.f32 "
        "{%0,%1,%2,%3}, {%4,%5,%6,%7}, {%8,%9}, {%0,%1,%2,%3};"
        : "+f"(d[0]), "+f"(d[1]), "+f"(d[2]), "+f"(d[3])
        : "r"(a[0]), "r"(a[1]), "r"(a[2]), "r"(a[3]), "r"(b[0]), "r"(b[1]));
}
__device__ __forceinline__ void ldsm_x4(uint32_t* r, uint32_t saddr) {
    asm volatile("ldmatrix.sync.aligned.m8n8.x4.shared.b16 {%0,%1,%2,%3}, [%4];"
        : "=r"(r[0]), "=r"(r[1]), "=r"(r[2]), "=r"(r[3]) : "r"(saddr));
}
__device__ __forceinline__ void ldsm_x2(uint32_t* r, uint32_t saddr) {
    asm volatile("ldmatrix.sync.aligned.m8n8.x2.shared.b16 {%0,%1}, [%2];"
        : "=r"(r[0]), "=r"(r[1]) : "r"(saddr));
}
__device__ __forceinline__ uint32_t smem_u32(const void* p) {
    return (uint32_t)__cvta_generic_to_shared(p);
}
// store bf16x2 at (r, c even 0..31) in swizzled tile (64B rows, 16B-chunk XOR)
__device__ __forceinline__ void stsw2(char* s, int r, int c, uint32_t v) {
    int byte = r*64 + ((((c >> 3) ^ ((r >> 1) & 3))) << 4) + (c & 7)*2;
    *(uint32_t*)(s + byte) = v;
}
__device__ __forceinline__ void cvt_hilo2(float2 v, uint32_t& hp, uint32_t& lp) {
    __nv_bfloat16 h0 = __float2bfloat16(v.x), h1 = __float2bfloat16(v.y);
    float l0 = v.x - __bfloat162float(h0), l1 = v.y - __bfloat162float(h1);
    __nv_bfloat16 b0 = __float2bfloat16(l0), b1 = __float2bfloat16(l1);
    hp = (uint32_t)__bfloat16_as_ushort(h0) | ((uint32_t)__bfloat16_as_ushort(h1) << 16);
    lp = (uint32_t)__bfloat16_as_ushort(b0) | ((uint32_t)__bfloat16_as_ushort(b1) << 16);
}

// ======================= prep kernels =======================
__global__ void k_sort(const int* __restrict__ caplens, const int* __restrict__ caps,
                       float* __restrict__ out) {
    __shared__ int s_sort[BB];
    if (threadIdx.x == 0) {
        int cl[BB];
        for (int i = 0; i < BB; i++) cl[i] = caplens[i];
        int r = 0;
        for (int v = MAXCAP; v >= 0 && r < BB; v--)
            for (int i = 0; i < BB; i++)
                if (cl[i] == v) { g_sortidx[r] = i; s_sort[r] = i; r++; }
        int na = 0;
        int dls[BB];
        for (int b = 0; b < BB; b++) {
            int dl = cl[g_sortidx[b]] - 1;
            dls[b] = dl;
            g_declen[b] = dl;
            out[OFF_DECLEN + b] = (float)dl;
            out[OFF_SORT + b]   = (float)g_sortidx[b];
            for (int t = 0; t < dl; t++) g_act[na++] = b*TT + t;
        }
        g_nact = na;
        for (int t = 0; t < TT; t++) {
            int c = 0;
            for (int b = 0; b < BB; b++) if (dls[b] > t) c++;
            g_nbact[t] = c;
        }
    }
    __syncthreads();
    int b = threadIdx.x;
    int src = s_sort[b];
    for (int t = 0; t < MAXCAP; t++)
        out[OFF_CAPS + b*MAXCAP + t] = (float)caps[src*MAXCAP + t];
}

// fused gather + hi/lo conversion (pairwise) + zero + init
#define P0 (BB*PP*256)
#define P1 (BB*TT*256)
#define P2 (AA*256)
#define P3 (NG*256)
#define P4 (VV*256)
#define Z5 (N_SCORES/4)
#define Z6 (BB*TT*PP/4)
#define Z7 (BB*HH)
#define Z8 160
__global__ void k_cvt_all(const float* __restrict__ imf, const int* __restrict__ caps,
                          const float* __restrict__ emb, const float* __restrict__ W_enc,
                          const float* __restrict__ W_ih, const float* __restrict__ W_score,
                          float* __restrict__ out)
{
    const int total = P0+P1+P2+P3+P4+Z5+Z6+Z7+Z8;
    for (int i = blockIdx.x*blockDim.x + threadIdx.x; i < total; i += gridDim.x*blockDim.x) {
        int x = i;
        if (x < P0) {
            int r = x >> 8, c2 = x & 255, k = c2*2;
            int b = r / PP, p = r - b*PP;
            float2 v = *(const float2*)(imf + ((size_t)g_sortidx[b]*PP + p)*512 + k);
            *(float2*)(g_feats + (size_t)r*512 + k) = v;
            uint32_t hp, lp; cvt_hilo2(v, hp, lp);
            ((uint32_t*)g_feats2)[(size_t)r*512 + c2] = hp;
            ((uint32_t*)g_feats2)[(size_t)r*512 + 256 + c2] = lp;
            continue;
        }
        x -= P0;
        if (x < P1) {
            int r = x >> 8, c2 = x & 255, k = c2*2;
            int b = r / TT, t = r - b*TT;
            int tok = caps[g_sortidx[b]*MAXCAP + t];
            float2 v = *(const float2*)(emb + (size_t)tok*512 + k);
            uint32_t hp, lp; cvt_hilo2(v, hp, lp);
            ((uint32_t*)g_embT2)[(size_t)r*512 + c2] = hp;
            ((uint32_t*)g_embT2)[(size_t)r*512 + 256 + c2] = lp;
            continue;
        }
        x -= P1;
        if (x < P2) {
            int r = x >> 8, c2 = x & 255, k = c2*2;
            float2 v = *(const float2*)(W_enc + (size_t)r*512 + k);
            uint32_t hp, lp; cvt_hilo2(v, hp, lp);
            ((uint32_t*)g_Wenc2)[(size_t)r*512 + c2] = hp;
            ((uint32_t*)g_Wenc2)[(size_t)r*512 + 256 + c2] = lp;
            continue;
        }
        x -= P2;
        if (x < P3) {
            int r = x >> 8, c2 = x & 255, k = c2*2;
            float2 v = *(const float2*)(W_ih + (size_t)r*1024 + k);
            uint32_t hp, lp; cvt_hilo2(v, hp, lp);
            ((uint32_t*)g_Wih2)[(size_t)r*512 + c2] = hp;
            ((uint32_t*)g_Wih2)[(size_t)r*512 + 256 + c2] = lp;
            continue;
        }
        x -= P3;
        if (x < P4) {
            int r = x >> 8, c2 = x & 255, k = c2*2;
            float2 v = *(const float2*)(W_score + (size_t)r*512 + k);
            uint32_t hp, lp; cvt_hilo2(v, hp, lp);
            ((uint32_t*)g_Wsc2)[(size_t)r*512 + c2] = hp;
            ((uint32_t*)g_Wsc2)[(size_t)r*512 + 256 + c2] = lp;
            continue;
        }
        x -= P4;
        if (x < Z5) {
            ((float4*)out)[x] = make_float4(0.f, 0.f, 0.f, 0.f);
            continue;
        }
        x -= Z5;
        if (x < Z6) {
            ((float4*)(out + OFF_WEIGHTS))[x] = make_float4(0.f, 0.f, 0.f, 0.f);
            continue;
        }
        x -= Z6;
        if (x < Z7) { g_h[x] = 0.f; g_c[x] = 0.f; continue; }
        x -= Z7;
        g_bars[x] = 0;
    }
}

// ======================= mma.sync bf16x3 GEMM body (ldmatrix + double buffer) ==========
__device__ __forceinline__ void hgemm_body(
    int bm, int bn,
    const __nv_bfloat16* __restrict__ A2, const __nv_bfloat16* __restrict__ B2,
    int M, int N, int ldc,
    const float* __restrict__ bias1, const float* __restrict__ bias2,
    float* __restrict__ C, const int* __restrict__ rowmap, int use_nact,
    __nv_bfloat16 (*As)[128*32], __nv_bfloat16 (*Bs)[128*32])
{
    int tid = threadIdx.x;
    int Ml = use_nact ? g_nact : M;
    if (bm*128 >= Ml) return;

    int lrow = tid >> 1;
    int lc0 = (tid & 1) * 2;
    int gm = bm*128 + lrow;
    const uint4* arow = nullptr;
    if (gm < Ml) { int r = rowmap ? rowmap[gm] : gm; arow = (const uint4*)(A2 + (size_t)r*1024); }
    int gn = bn*128 + lrow;
    const uint4* brow = (gn < N) ? (const uint4*)(B2 + (size_t)gn*1024) : nullptr;

    int swz = (lrow >> 1) & 3;
    uint4* aswp[2] = {(uint4*)(As[0] + lrow*32), (uint4*)(As[1] + lrow*32)};
    uint4* bswp[2] = {(uint4*)(Bs[0] + lrow*32), (uint4*)(Bs[1] + lrow*32)};
    int c0 = lc0 ^ swz, c1 = (lc0+1) ^ swz;

    int lane = tid & 31, wid = tid >> 5;
    int wm = (wid >> 2) * 64;
    int wn = (wid & 3) * 32;
    int gq = lane >> 2, tg = lane & 3;

    int rA = wm + (lane & 15);
    int swzA = (rA >> 1) & 3;
    int hiA = lane >> 4;
    int rB = wn + (lane & 7);
    int swzB = (rB >> 1) & 3;
    int hiB = (lane >> 3) & 1;
    uint32_t aS[2] = {smem_u32(As[0]) + rA*64, smem_u32(As[1]) + rA*64};
    uint32_t bS[2] = {smem_u32(Bs[0]) + rB*64, smem_u32(Bs[1]) + rB*64};

    float acc[4][4][4];
#pragma unroll
    for (int mt = 0; mt < 4; mt++)
#pragma unroll
        for (int nt = 0; nt < 4; nt++)
#pragma unroll
            for (int r = 0; r < 4; r++) acc[mt][nt][r] = 0.f;

    const uint4 z = make_uint4(0,0,0,0);
    const int kau4[3] = {0, 0, 64};
    const int kbu4[3] = {0, 64, 0};
    uint4 pa0 = arow ? arow[lc0]   : z;
    uint4 pa1 = arow ? arow[lc0+1] : z;
    uint4 pb0 = brow ? brow[lc0]   : z;
    uint4 pb1 = brow ? brow[lc0+1] : z;
    aswp[0][c0] = pa0; aswp[0][c1] = pa1;
    bswp[0][c0] = pb0; bswp[0][c1] = pb1;
    __syncthreads();

    for (int ci = 0; ci < 48; ci++) {
        int cur = ci & 1;
        if (ci + 1 < 48) {
            int term = (ci+1) >> 4, kc = (ci+1) & 15;
            int ab = kau4[term] + kc*4, bb = kbu4[term] + kc*4;
            pa0 = arow ? arow[ab + lc0]   : z;
            pa1 = arow ? arow[ab + lc0+1] : z;
            pb0 = brow ? brow[bb + lc0]   : z;
            pb1 = brow ? brow[bb + lc0+1] : z;
        }
#pragma unroll
        for (int kk = 0; kk < 2; kk++) {
            uint32_t cA = (uint32_t)(((2*kk + hiA) ^ swzA) << 4);
            uint32_t cB = (uint32_t)(((2*kk + hiB) ^ swzB) << 4);
            uint32_t afr[4][4];
#pragma unroll
            for (int mt = 0; mt < 4; mt++)
                ldsm_x4(afr[mt], aS[cur] + mt*1024 + cA);
            uint32_t bfr[4][2];
#pragma unroll
            for (int nt = 0; nt < 4; nt++)
                ldsm_x2(bfr[nt], bS[cur] + nt*512 + cB);
#pragma unroll
            for (int mt = 0; mt < 4; mt++)
#pragma unroll
                for (int nt = 0; nt < 4; nt++)
                    mma16816(acc[mt][nt], afr[mt], bfr[nt]);
        }
        if (ci + 1 < 48) {
            int nxt = cur ^ 1;
            aswp[nxt][c0] = pa0; aswp[nxt][c1] = pa1;
            bswp[nxt][c0] = pb0; bswp[nxt][c1] = pb1;
        }
        __syncthreads();
    }

#pragma unroll
    for (int mt = 0; mt < 4; mt++) {
        int m0 = bm*128 + wm + mt*16 + gq;
        int m1 = m0 + 8;
        size_t row0 = 0, row1 = 0;
        bool v0 = m0 < Ml, v1 = m1 < Ml;
        if (v0) row0 = (size_t)(rowmap ? rowmap[m0] : m0);
        if (v1) row1 = (size_t)(rowmap ? rowmap[m1] : m1);
#pragma unroll
        for (int nt = 0; nt < 4; nt++) {
            int col = bn*128 + wn + nt*8 + tg*2;
            if (col >= N) continue;
            float bx = bias1[col], by = bias1[col+1];
            if (bias2) { bx += bias2[col]; by += bias2[col+1]; }
            if (v0) {
                float2 o = make_float2(acc[mt][nt][0] + bx, acc[mt][nt][1] + by);
                *(float2*)(C + row0*(size_t)ldc + col) = o;
            }
            if (v1) {
                float2 o = make_float2(acc[mt][nt][2] + bx, acc[mt][nt][3] + by);
                *(float2*)(C + row1*(size_t)ldc + col) = o;
            }
        }
    }
}

__global__ __launch_bounds__(256)
void k_gemm_pair(const float* __restrict__ b_enc, const float* __restrict__ b_ih,
                 const float* __restrict__ b_hh)
{
    __shared__ __align__(16) __nv_bfloat16 As[2][128*32];
    __shared__ __align__(16) __nv_bfloat16 Bs[2][128*32];
    int idx = blockIdx.x;
    if (idx < 392) {
        hgemm_body(idx >> 2, idx & 3, g_feats2, g_Wenc2, BB*PP, AA, AA,
                   b_enc, nullptr, g_encatt, nullptr, 0, As, Bs);
    } else {
        idx -= 392;
        hgemm_body(idx >> 4, idx & 15, g_embT2, g_Wih2, BB*TT, NG, NG,
                   b_ih, b_hh, g_embg, g_act, 1, As, Bs);
    }
}

__global__ __launch_bounds__(256)
void k_gemm_scores(const float* __restrict__ b_score, float* __restrict__ out)
{
    __shared__ __align__(16) __nv_bfloat16 As[2][128*32];
    __shared__ __align__(16) __nv_bfloat16 Bs[2][128*32];
    hgemm_body(blockIdx.x, blockIdx.y, g_hall2, g_Wsc2, BB*TT, VV, VV,
               b_score, nullptr, out, g_act, 1, As, Bs);
}

// ======================= fused persistent recurrence (512 threads) =======================
// smem byte offsets
#define WHH_OFF  0
#define WIHC_OFF 32768
#define WDEC_OFF 65536
#define HT_OFF   81920
#define PART_OFF 147456
#define GH_OFF   163840
#define SM_TOTAL 167936

// flat per-slot barrier (replay-safe), tight spin — best measured variant
__device__ __forceinline__ void gridbar(int slot) {
    __syncthreads();
    if (threadIdx.x == 0) {
        int* p = &g_bars[slot];
        asm volatile("red.release.gpu.global.add.s32 [%0], 1;" :: "l"(p) : "memory");
        int v;
        do {
            asm volatile("ld.acquire.gpu.global.s32 %0, [%1];" : "=r"(v) : "l"(p) : "memory");
        } while (v < NCTA);
    }
    __syncthreads();
}

// stage 32 rows of fp32[512] (L2-coherent reads) into hi/lo swizzled tiles
__device__ __forceinline__ void stage32(const float* __restrict__ src, int b0, char* HTp, int tid) {
    for (int i = tid; i < 32*256; i += NTHR_R) {
        int r = i >> 8, kp = i & 255, k = kp*2;
        float2 v = __ldcg((const float2*)(src + (size_t)(b0+r)*512 + k));
        uint32_t hp, lp;
        cvt_hilo2(v, hp, lp);
        int kt = k >> 5, c = k & 31;
        stsw2(HTp + kt*2048, r, c, hp);
        stsw2(HTp + (16+kt)*2048, r, c, lp);
    }
}

// gates mma (ldmatrix, 16 warps): M=32, N=16, K=512 split 4 ways -> part[4][32][16]
__device__ __forceinline__ void gates_mma(uint32_t htA, uint32_t wbB, float* part,
                                          int wid, int lane) {
    int gq = lane >> 2, tg = lane & 3;
    int mh = (wid & 1)*16, nh = ((wid >> 1) & 1)*8, ks = wid >> 2;   // ks 0..3
    int rA = mh + (lane & 15);
    int swzA = (rA >> 1) & 3;
    int hiA = lane >> 4;
    int rB = nh + (lane & 7);
    int swzB = (rB >> 1) & 3;
    int hiB = (lane >> 3) & 1;
    uint32_t aL = htA + rA*64;
    uint32_t bL = wbB + rB*64;
    float acc[4] = {0.f, 0.f, 0.f, 0.f};
    for (int kt = ks*4; kt < ks*4 + 4; kt++) {
        uint32_t ah = aL + kt*2048;
        uint32_t bh = bL + kt*1024;
#pragma unroll
        for (int kk = 0; kk < 2; kk++) {
            uint32_t cA = (uint32_t)(((2*kk + hiA) ^ swzA) << 4);
            uint32_t cB = (uint32_t)(((2*kk + hiB) ^ swzB) << 4);
            uint32_t Ah[4], Al[4], Bh[2], Bl[2];
            ldsm_x4(Ah, ah + cA);
            ldsm_x4(Al, ah + 32768 + cA);
            ldsm_x2(Bh, bh + cB);
            ldsm_x2(Bl, bh + 16384 + cB);
            mma16816(acc, Ah, Bh);
            mma16816(acc, Ah, Bl);
            mma16816(acc, Al, Bh);
        }
    }
    int m0 = mh + gq, n0 = nh + tg*2;
    part[ks*512 + m0*16 + n0]       = acc[0];
    part[ks*512 + m0*16 + n0+1]     = acc[1];
    part[ks*512 + (m0+8)*16 + n0]   = acc[2];
    part[ks*512 + (m0+8)*16 + n0+1] = acc[3];
}

// att2 mma (ldmatrix, 16 warps): M=32, N=8 (4 real + 4 zero), K split 8 ways -> part2[8][32][8]
__device__ __forceinline__ void att2_mma(uint32_t htA, uint32_t wdB, float* part2,
                                         int wid, int lane) {
    int gq = lane >> 2, tg = lane & 3;
    int mh = (wid & 1)*16, ks = wid >> 1;   // ks 0..7
    int rA = mh + (lane & 15);
    int swzA = (rA >> 1) & 3;
    int hiA = lane >> 4;
    int rB = lane & 7;
    int swzB = (rB >> 1) & 3;
    int hiB = (lane >> 3) & 1;
    uint32_t aL = htA + rA*64;
    uint32_t bL = wdB + rB*64;
    float acc[4] = {0.f, 0.f, 0.f, 0.f};
    for (int kt = ks*2; kt < ks*2 + 2; kt++) {
        uint32_t ah = aL + kt*2048;
        uint32_t bh = bL + kt*512;
#pragma unroll
        for (int kk = 0; kk < 2; kk++) {
            uint32_t cA = (uint32_t)(((2*kk + hiA) ^ swzA) << 4);
            uint32_t cB = (uint32_t)(((2*kk + hiB) ^ swzB) << 4);
            uint32_t Ah[4], Al[4], Bh[2], Bl[2];
            ldsm_x4(Ah, ah + cA);
            ldsm_x4(Al, ah + 32768 + cA);
            ldsm_x2(Bh, bh + cB);
            ldsm_x2(Bl, bh + 8192 + cB);
            mma16816(acc, Ah, Bh);
            mma16816(acc, Ah, Bl);
            mma16816(acc, Al, Bh);
        }
    }
    int m0 = mh + gq, n0 = tg*2;
    part2[ks*256 + m0*8 + n0]       = acc[0];
    part2[ks*256 + m0*8 + n0+1]     = acc[1];
    part2[ks*256 + (m0+8)*8 + n0]   = acc[2];
    part2[ks*256 + (m0+8)*8 + n0+1] = acc[3];
}

__global__ __launch_bounds__(NTHR_R)
void k_recur(const float* __restrict__ W_dec, const float* __restrict__ W_hh,
             const float* __restrict__ W_ih,
             const float* __restrict__ b_dec, const float* __restrict__ W_full,
             const float* __restrict__ b_full, float* __restrict__ out)
{
    extern __shared__ float sm[];
    char* smc = (char*)sm;
    __shared__ int sdl[BB];
    __shared__ int snb[TT];
    int tid = threadIdx.x, lane = tid & 31, wid = tid >> 5;
    int j = blockIdx.x;

    if (tid < BB) sdl[tid] = g_declen[tid];
    if (tid >= 64 && tid < 64 + TT) snb[tid - 64] = g_nbact[tid - 64];

    // convert weight slices to swizzled bf16 hi/lo tiles (once)
    for (int i = tid; i < 16*256; i += NTHR_R) {
        int r = i >> 8, kp = i & 255, k = kp*2;
        int gr = 512*(r >> 2) + j*4 + (r & 3);
        float2 w1 = *(const float2*)(W_hh + (size_t)gr*512 + k);
        float2 w2 = *(const float2*)(W_ih + (size_t)gr*1024 + 512 + k);
        uint32_t hp, lp;
        int kt = k >> 5, c = k & 31;
        cvt_hilo2(w1, hp, lp);
        stsw2(smc + WHH_OFF + kt*1024, r, c, hp);
        stsw2(smc + WHH_OFF + (16+kt)*1024, r, c, lp);
        cvt_hilo2(w2, hp, lp);
        stsw2(smc + WIHC_OFF + kt*1024, r, c, hp);
        stsw2(smc + WIHC_OFF + (16+kt)*1024, r, c, lp);
    }
    for (int i = tid; i < 8*256; i += NTHR_R) {
        int r = i >> 8, kp = i & 255, k = kp*2;
        float2 w = (r < 4) ? *(const float2*)(W_dec + (size_t)(j*4+r)*512 + k)
                           : make_float2(0.f, 0.f);
        uint32_t hp, lp;
        cvt_hilo2(w, hp, lp);
        int kt = k >> 5, c = k & 31;
        stsw2(smc + WDEC_OFF + kt*512, r, c, hp);
        stsw2(smc + WDEC_OFF + (16+kt)*512, r, c, lp);
    }
    __syncthreads();

    float* part  = (float*)(smc + PART_OFF);       // 4*512 floats
    float* part2 = part + 2048;                    // 8*256 floats
    float* gh    = (float*)(smc + GH_OFF);
    uint32_t htS  = smem_u32(smc + HT_OFF);
    uint32_t whhS = smem_u32(smc + WHH_OFF);
    uint32_t wihS = smem_u32(smc + WIHC_OFF);
    uint32_t wdS  = smem_u32(smc + WDEC_OFF);

    int nbar = 0;
    for (int t = 0; t < TT; t++) {
        int npb = (snb[t] + 31) >> 5;
        // ---- Phase A: gates_h + att2 (mma) ----
        for (int pb = 0; pb < npb; pb++) {
            int b0 = pb*32;
            stage32(g_h, b0, smc + HT_OFF, tid);
            __syncthreads();
            gates_mma(htS, whhS, part, wid, lane);
            att2_mma(htS, wdS, part2, wid, lane);
            __syncthreads();
            for (int o = tid; o < 512; o += NTHR_R)
                gh[(b0 + (o >> 4))*16 + (o & 15)] =
                    part[o] + part[512 + o] + part[1024 + o] + part[1536 + o];
            if (tid < 128) {
                int m = tid >> 2, q = tid & 3;
                float s = 0.f;
#pragma unroll
                for (int ks = 0; ks < 8; ks++) s += part2[ks*256 + m*8 + q];
                g_att2[(b0+m)*512 + j*4 + q] = s;
            }
            __syncthreads();
        }
        gridbar(nbar++);

        // ---- Phase B: attention (CTAs 0..63, active only) ----
        if (j < BB && t < sdl[j]) {
            int b = j;
            float* wout = out + OFF_WEIGHTS + (size_t)(b*TT + t)*PP;
            float* att = (float*)(smc + HT_OFF);
            float* s_att2 = att;
            float* s_wf   = att + 512;
            float* s_e    = att + 1024;
            float* s_red  = att + 1248;
            float* rbuf   = att + 1280;
            for (int a = tid; a < AA; a += NTHR_R) {
                s_att2[a] = __ldcg(&g_att2[b*512 + a]) + b_dec[a];
                s_wf[a] = W_full[a];
            }
            __syncthreads();
            const float* ea = g_encatt + (size_t)b * PP * AA;
            for (int p = wid; p < PP; p += 16) {
                const float* row = ea + (size_t)p * AA;
                float sum = 0.f;
                for (int a = lane; a < AA; a += 32)
                    sum += fmaxf(row[a] + s_att2[a], 0.f) * s_wf[a];
#pragma unroll
                for (int o = 16; o; o >>= 1) sum += __shfl_xor_sync(0xffffffffu, sum, o);
                if (lane == 0) s_e[p] = sum + b_full[0];
            }
            __syncthreads();
            float m = -1e30f;
            if (tid < PP) m = s_e[tid];
#pragma unroll
            for (int o = 16; o; o >>= 1) m = fmaxf(m, __shfl_xor_sync(0xffffffffu, m, o));
            if (lane == 0) s_red[wid] = m;
            __syncthreads();
            float mx = s_red[0];
#pragma unroll
            for (int i = 1; i < 16; i++) mx = fmaxf(mx, s_red[i]);
            float ev = 0.f;
            if (tid < PP) ev = expf(s_e[tid] - mx);
            float sv = ev;
#pragma unroll
            for (int o = 16; o; o >>= 1) sv += __shfl_xor_sync(0xffffffffu, sv, o);
            __syncthreads();
            if (lane == 0) s_red[wid] = sv;
            __syncthreads();
            float tot = 0.f;
#pragma unroll
            for (int i = 0; i < 16; i++) tot += s_red[i];
            float inv = 1.f / tot;
            if (tid < PP) {
                float al = ev * inv;
                s_e[tid] = al;
                wout[tid] = al;
            }
            __syncthreads();
            int hq = tid & 63, pc2 = tid >> 6;   // 8-way pixel split
            const float4* fb4 = (const float4*)(g_feats + (size_t)b * PP * HH);
            float4 a0 = make_float4(0,0,0,0), a1 = make_float4(0,0,0,0);
            for (int p = pc2; p < PP; p += 8) {
                float al = s_e[p];
                float4 v0 = fb4[p*128 + hq*2];
                float4 v1 = fb4[p*128 + hq*2 + 1];
                a0.x = fmaf(al, v0.x, a0.x); a0.y = fmaf(al, v0.y, a0.y);
                a0.z = fmaf(al, v0.z, a0.z); a0.w = fmaf(al, v0.w, a0.w);
                a1.x = fmaf(al, v1.x, a1.x); a1.y = fmaf(al, v1.y, a1.y);
                a1.z = fmaf(al, v1.z, a1.z); a1.w = fmaf(al, v1.w, a1.w);
            }
            float* rb = rbuf + pc2*512 + hq*8;
            rb[0]=a0.x; rb[1]=a0.y; rb[2]=a0.z; rb[3]=a0.w;
            rb[4]=a1.x; rb[5]=a1.y; rb[6]=a1.z; rb[7]=a1.w;
            __syncthreads();
            for (int o = tid; o < 512; o += NTHR_R) {
                float s = 0.f;
#pragma unroll
                for (int q = 0; q < 8; q++) s += rbuf[q*512 + o];
                g_ctx[b*512 + o] = s;
            }
        }
        gridbar(nbar++);

        // ---- Phase C: gates_ctx (mma) + combine + LSTM ----
        for (int pb = 0; pb < npb; pb++) {
            int b0 = pb*32;
            stage32(g_ctx, b0, smc + HT_OFF, tid);
            __syncthreads();
            gates_mma(htS, wihS, part, wid, lane);
            __syncthreads();
            for (int o = tid; o < 512; o += NTHR_R) {
                int m = o >> 4, n = o & 15;
                int b = b0 + m;
                int gr = 512*(n >> 2) + j*4 + (n & 3);
                gh[b*16 + n] += part[o] + part[512 + o] + part[1024 + o] + part[1536 + o]
                              + g_embg[(size_t)(b*TT + t)*NG + gr];
            }
            __syncthreads();
        }
        if (tid < 256) {
            int b = tid >> 2, q = tid & 3;
            if (t < sdl[b]) {
                float gi = gh[b*16 + q];
                float gf = gh[b*16 + 4 + q];
                float gg = gh[b*16 + 8 + q];
                float go = gh[b*16 + 12 + q];
                float ig = 1.f / (1.f + expf(-gi));
                float fg = 1.f / (1.f + expf(-gf));
                float gv = tanhf(gg);
                float og = 1.f / (1.f + expf(-go));
                int kc = j*4 + q;
                float c_new = fg * g_c[b*512 + kc] + ig * gv;
                float h_new = og * tanhf(c_new);
                __nv_bfloat16 hh = __float2bfloat16(h_new);
                __nv_bfloat16 hl = __float2bfloat16(h_new - __bfloat162float(hh));
                g_hall2[(size_t)(b*TT + t)*1024 + kc]       = hh;
                g_hall2[(size_t)(b*TT + t)*1024 + 512 + kc] = hl;
                g_h[b*512 + kc] = h_new;
                g_c[b*512 + kc] = c_new;
            }
        }
        gridbar(nbar++);
    }
}

// ======================= launch =======================
extern "C" void kernel_launch(void* const* d_in, const int* in_sizes, int n_in,
                              void* d_out, int out_size) {
    const float* imf     = (const float*)d_in[0];
    const int*   caps    = (const int*)  d_in[1];
    const int*   caplens = (const int*)  d_in[2];
    const float* emb     = (const float*)d_in[3];
    const float* W_ih    = (const float*)d_in[4];
    const float* W_hh    = (const float*)d_in[5];
    const float* b_ih    = (const float*)d_in[6];
    const float* b_hh    = (const float*)d_in[7];
    const float* W_enc   = (const float*)d_in[8];
    const float* b_enc   = (const float*)d_in[9];
    const float* W_dec   = (const float*)d_in[10];
    const float* b_dec   = (const float*)d_in[11];
    const float* W_full  = (const float*)d_in[12];
    const float* b_full  = (const float*)d_in[13];
    const float* W_score = (const float*)d_in[14];
    const float* b_score = (const float*)d_in[15];
    float* out = (float*)d_out;

    cudaFuncSetAttribute(k_recur, cudaFuncAttributeMaxDynamicSharedMemorySize, SM_TOTAL);

    // 1: sort + caps/declen/sortind outputs
    k_sort<<<1, BB>>>(caplens, caps, out);
    // 2: fused gathers + bf16 hi/lo conversions + zeroing + init
    k_cvt_all<<<1024, 256>>>(imf, caps, emb, W_enc, W_ih, W_score, out);
    // 3: fused enc_att + G_emb tensor-core GEMMs
    k_gemm_pair<<<792, 256>>>(b_enc, b_ih, b_hh);
    // 4: persistent recurrence (512 threads, writes g_hall2 directly)
    k_recur<<<NCTA, NTHR_R, SM_TOTAL>>>(W_dec, W_hh, W_ih, b_dec, W_full, b_full, out);
    // 5: scores GEMM
    k_gemm_scores<<<dim3((BB*TT + 127)/128, (VV + 127)/128), 256>>>(b_score, out);
}

// round 12
// speedup vs baseline: 1.8867x; 1.0684x over previous
#include <cuda_runtime.h>
#include <cuda_bf16.h>
#include <cstdint>
#include <math.h>

#define BB 64
#define PP 196
#define HH 512
#define EE 512
#define AA 512
#define VV 10000
#define MAXCAP 50
#define TT 49
#define NG 2048   // 4*H

// output layout (float32): scores (B,T,V), caps_s (B,50), decode_lengths (B,), weights (B,T,P), sort_ind (B,)
#define N_SCORES   (BB*TT*VV)
#define OFF_CAPS   (N_SCORES)
#define OFF_DECLEN (OFF_CAPS + BB*MAXCAP)
#define OFF_WEIGHTS (OFF_DECLEN + BB)
#define OFF_SORT   (OFF_WEIGHTS + BB*TT*PP)

#define NCTA 128
#define NTHR 256
#define NTHR_R 1024

// ======================= scratch =======================
__device__ float g_feats[BB*PP*HH];
__device__ float g_encatt[BB*PP*AA];
__device__ float g_embg[BB*TT*NG];
__device__ float g_h[BB*HH];
__device__ float g_c[BB*HH];
__device__ float g_att2[BB*AA];
__device__ float g_ctx[BB*HH];
__device__ int   g_sortidx[BB];
__device__ int   g_declen[BB];
__device__ int   g_nbact[TT];
__device__ int   g_act[BB*TT];
__device__ int   g_nact;
__device__ int   g_bars[160];

// bf16 hi/lo packed [rows][1024]: cols 0-511 hi, 512-1023 lo
__device__ __nv_bfloat16 g_feats2[BB*PP*1024];
__device__ __nv_bfloat16 g_embT2[BB*TT*1024];
__device__ __nv_bfloat16 g_hall2[BB*TT*1024];
__device__ __nv_bfloat16 g_Wenc2[AA*1024];
__device__ __nv_bfloat16 g_Wih2[NG*1024];
__device__ __nv_bfloat16 g_Wsc2[VV*1024];

// ======================= helpers =======================
__device__ __forceinline__ void mma16816(float* d, const uint32_t* a, const uint32_t* b) {
    asm volatile("mma.sync.aligned.m16n8k16.row.col.f32.bf16.bf16.f32 "
        "{%0,%1,%2,%3}, {%4,%5,%6,%7}, {%8,%9}, {%0,%1,%2,%3};"
        : "+f"(d[0]), "+f"(d[1]), "+f"(d[2]), "+f"(d[3])
        : "r"(a[0]), "r"(a[1]), "r"(a[2]), "r"(a[3]), "r"(b[0]), "r"(b[1]));
}
__device__ __forceinline__ void ldsm_x4(uint32_t* r, uint32_t saddr) {
    asm volatile("ldmatrix.sync.aligned.m8n8.x4.shared.b16 {%0,%1,%2,%3}, [%4];"
        : "=r"(r[0]), "=r"(r[1]), "=r"(r[2]), "=r"(r[3]) : "r"(saddr));
}
__device__ __forceinline__ void ldsm_x2(uint32_t* r, uint32_t saddr) {
    asm volatile("ldmatrix.sync.aligned.m8n8.x2.shared.b16 {%0,%1}, [%2];"
        : "=r"(r[0]), "=r"(r[1]) : "r"(saddr));
}
__device__ __forceinline__ uint32_t smem_u32(const void* p) {
    return (uint32_t)__cvta_generic_to_shared(p);
}
// store bf16x2 at (r, c even 0..31) in swizzled tile (64B rows, 16B-chunk XOR)
__device__ __forceinline__ void stsw2(char* s, int r, int c, uint32_t v) {
    int byte = r*64 + ((((c >> 3) ^ ((r >> 1) & 3))) << 4) + (c & 7)*2;
    *(uint32_t*)(s + byte) = v;
}
__device__ __forceinline__ void cvt_hilo2(float2 v, uint32_t& hp, uint32_t& lp) {
    __nv_bfloat16 h0 = __float2bfloat16(v.x), h1 = __float2bfloat16(v.y);
    float l0 = v.x - __bfloat162float(h0), l1 = v.y - __bfloat162float(h1);
    __nv_bfloat16 b0 = __float2bfloat16(l0), b1 = __float2bfloat16(l1);
    hp = (uint32_t)__bfloat16_as_ushort(h0) | ((uint32_t)__bfloat16_as_ushort(h1) << 16);
    lp = (uint32_t)__bfloat16_as_ushort(b0) | ((uint32_t)__bfloat16_as_ushort(b1) << 16);
}

// ======================= prep kernels =======================
__global__ void k_sort(const int* __restrict__ caplens, const int* __restrict__ caps,
                       float* __restrict__ out) {
    __shared__ int s_sort[BB];
    if (threadIdx.x == 0) {
        int cl[BB];
        for (int i = 0; i < BB; i++) cl[i] = caplens[i];
        int r = 0;
        for (int v = MAXCAP; v >= 0 && r < BB; v--)
            for (int i = 0; i < BB; i++)
                if (cl[i] == v) { g_sortidx[r] = i; s_sort[r] = i; r++; }
        int na = 0;
        int dls[BB];
        for (int b = 0; b < BB; b++) {
            int dl = cl[g_sortidx[b]] - 1;
            dls[b] = dl;
            g_declen[b] = dl;
            out[OFF_DECLEN + b] = (float)dl;
            out[OFF_SORT + b]   = (float)g_sortidx[b];
            for (int t = 0; t < dl; t++) g_act[na++] = b*TT + t;
        }
        g_nact = na;
        for (int t = 0; t < TT; t++) {
            int c = 0;
            for (int b = 0; b < BB; b++) if (dls[b] > t) c++;
            g_nbact[t] = c;
        }
    }
    __syncthreads();
    int b = threadIdx.x;
    int src = s_sort[b];
    for (int t = 0; t < MAXCAP; t++)
        out[OFF_CAPS + b*MAXCAP + t] = (float)caps[src*MAXCAP + t];
}

// fused gather + hi/lo conversion (pairwise) + zero + init
#define P0 (BB*PP*256)
#define P1 (BB*TT*256)
#define P2 (AA*256)
#define P3 (NG*256)
#define P4 (VV*256)
#define Z5 (N_SCORES/4)
#define Z6 (BB*TT*PP/4)
#define Z7 (BB*HH)
#define Z8 160
__global__ void k_cvt_all(const float* __restrict__ imf, const int* __restrict__ caps,
                          const float* __restrict__ emb, const float* __restrict__ W_enc,
                          const float* __restrict__ W_ih, const float* __restrict__ W_score,
                          float* __restrict__ out)
{
    const int total = P0+P1+P2+P3+P4+Z5+Z6+Z7+Z8;
    for (int i = blockIdx.x*blockDim.x + threadIdx.x; i < total; i += gridDim.x*blockDim.x) {
        int x = i;
        if (x < P0) {
            int r = x >> 8, c2 = x & 255, k = c2*2;
            int b = r / PP, p = r - b*PP;
            float2 v = *(const float2*)(imf + ((size_t)g_sortidx[b]*PP + p)*512 + k);
            *(float2*)(g_feats + (size_t)r*512 + k) = v;
            uint32_t hp, lp; cvt_hilo2(v, hp, lp);
            ((uint32_t*)g_feats2)[(size_t)r*512 + c2] = hp;
            ((uint32_t*)g_feats2)[(size_t)r*512 + 256 + c2] = lp;
            continue;
        }
        x -= P0;
        if (x < P1) {
            int r = x >> 8, c2 = x & 255, k = c2*2;
            int b = r / TT, t = r - b*TT;
            int tok = caps[g_sortidx[b]*MAXCAP + t];
            float2 v = *(const float2*)(emb + (size_t)tok*512 + k);
            uint32_t hp, lp; cvt_hilo2(v, hp, lp);
            ((uint32_t*)g_embT2)[(size_t)r*512 + c2] = hp;
            ((uint32_t*)g_embT2)[(size_t)r*512 + 256 + c2] = lp;
            continue;
        }
        x -= P1;
        if (x < P2) {
            int r = x >> 8, c2 = x & 255, k = c2*2;
            float2 v = *(const float2*)(W_enc + (size_t)r*512 + k);
            uint32_t hp, lp; cvt_hilo2(v, hp, lp);
            ((uint32_t*)g_Wenc2)[(size_t)r*512 + c2] = hp;
            ((uint32_t*)g_Wenc2)[(size_t)r*512 + 256 + c2] = lp;
            continue;
        }
        x -= P2;
        if (x < P3) {
            int r = x >> 8, c2 = x & 255, k = c2*2;
            float2 v = *(const float2*)(W_ih + (size_t)r*1024 + k);
            uint32_t hp, lp; cvt_hilo2(v, hp, lp);
            ((uint32_t*)g_Wih2)[(size_t)r*512 + c2] = hp;
            ((uint32_t*)g_Wih2)[(size_t)r*512 + 256 + c2] = lp;
            continue;
        }
        x -= P3;
        if (x < P4) {
            int r = x >> 8, c2 = x & 255, k = c2*2;
            float2 v = *(const float2*)(W_score + (size_t)r*512 + k);
            uint32_t hp, lp; cvt_hilo2(v, hp, lp);
            ((uint32_t*)g_Wsc2)[(size_t)r*512 + c2] = hp;
            ((uint32_t*)g_Wsc2)[(size_t)r*512 + 256 + c2] = lp;
            continue;
        }
        x -= P4;
        if (x < Z5) {
            ((float4*)out)[x] = make_float4(0.f, 0.f, 0.f, 0.f);
            continue;
        }
        x -= Z5;
        if (x < Z6) {
            ((float4*)(out + OFF_WEIGHTS))[x] = make_float4(0.f, 0.f, 0.f, 0.f);
            continue;
        }
        x -= Z6;
        if (x < Z7) { g_h[x] = 0.f; g_c[x] = 0.f; continue; }
        x -= Z7;
        g_bars[x] = 0;
    }
}

// ======================= mma.sync bf16x3 GEMM body (ldmatrix + double buffer) ==========
__device__ __forceinline__ void hgemm_body(
    int bm, int bn,
    const __nv_bfloat16* __restrict__ A2, const __nv_bfloat16* __restrict__ B2,
    int M, int N, int ldc,
    const float* __restrict__ bias1, const float* __restrict__ bias2,
    float* __restrict__ C, const int* __restrict__ rowmap, int use_nact,
    __nv_bfloat16 (*As)[128*32], __nv_bfloat16 (*Bs)[128*32])
{
    int tid = threadIdx.x;
    int Ml = use_nact ? g_nact : M;
    if (bm*128 >= Ml) return;

    int lrow = tid >> 1;
    int lc0 = (tid & 1) * 2;
    int gm = bm*128 + lrow;
    const uint4* arow = nullptr;
    if (gm < Ml) { int r = rowmap ? rowmap[gm] : gm; arow = (const uint4*)(A2 + (size_t)r*1024); }
    int gn = bn*128 + lrow;
    const uint4* brow = (gn < N) ? (const uint4*)(B2 + (size_t)gn*1024) : nullptr;

    int swz = (lrow >> 1) & 3;
    uint4* aswp[2] = {(uint4*)(As[0] + lrow*32), (uint4*)(As[1] + lrow*32)};
    uint4* bswp[2] = {(uint4*)(Bs[0] + lrow*32), (uint4*)(Bs[1] + lrow*32)};
    int c0 = lc0 ^ swz, c1 = (lc0+1) ^ swz;

    int lane = tid & 31, wid = tid >> 5;
    int wm = (wid >> 2) * 64;
    int wn = (wid & 3) * 32;
    int gq = lane >> 2, tg = lane & 3;

    int rA = wm + (lane & 15);
    int swzA = (rA >> 1) & 3;
    int hiA = lane >> 4;
    int rB = wn + (lane & 7);
    int swzB = (rB >> 1) & 3;
    int hiB = (lane >> 3) & 1;
    uint32_t aS[2] = {smem_u32(As[0]) + rA*64, smem_u32(As[1]) + rA*64};
    uint32_t bS[2] = {smem_u32(Bs[0]) + rB*64, smem_u32(Bs[1]) + rB*64};

    float acc[4][4][4];
#pragma unroll
    for (int mt = 0; mt < 4; mt++)
#pragma unroll
        for (int nt = 0; nt < 4; nt++)
#pragma unroll
            for (int r = 0; r < 4; r++) acc[mt][nt][r] = 0.f;

    const uint4 z = make_uint4(0,0,0,0);
    const int kau4[3] = {0, 0, 64};
    const int kbu4[3] = {0, 64, 0};
    uint4 pa0 = arow ? arow[lc0]   : z;
    uint4 pa1 = arow ? arow[lc0+1] : z;
    uint4 pb0 = brow ? brow[lc0]   : z;
    uint4 pb1 = brow ? brow[lc0+1] : z;
    aswp[0][c0] = pa0; aswp[0][c1] = pa1;
    bswp[0][c0] = pb0; bswp[0][c1] = pb1;
    __syncthreads();

    for (int ci = 0; ci < 48; ci++) {
        int cur = ci & 1;
        if (ci + 1 < 48) {
            int term = (ci+1) >> 4, kc = (ci+1) & 15;
            int ab = kau4[term] + kc*4, bb = kbu4[term] + kc*4;
            pa0 = arow ? arow[ab + lc0]   : z;
            pa1 = arow ? arow[ab + lc0+1] : z;
            pb0 = brow ? brow[bb + lc0]   : z;
            pb1 = brow ? brow[bb + lc0+1] : z;
        }
#pragma unroll
        for (int kk = 0; kk < 2; kk++) {
            uint32_t cA = (uint32_t)(((2*kk + hiA) ^ swzA) << 4);
            uint32_t cB = (uint32_t)(((2*kk + hiB) ^ swzB) << 4);
            uint32_t afr[4][4];
#pragma unroll
            for (int mt = 0; mt < 4; mt++)
                ldsm_x4(afr[mt], aS[cur] + mt*1024 + cA);
            uint32_t bfr[4][2];
#pragma unroll
            for (int nt = 0; nt < 4; nt++)
                ldsm_x2(bfr[nt], bS[cur] + nt*512 + cB);
#pragma unroll
            for (int mt = 0; mt < 4; mt++)
#pragma unroll
                for (int nt = 0; nt < 4; nt++)
                    mma16816(acc[mt][nt], afr[mt], bfr[nt]);
        }
        if (ci + 1 < 48) {
            int nxt = cur ^ 1;
            aswp[nxt][c0] = pa0; aswp[nxt][c1] = pa1;
            bswp[nxt][c0] = pb0; bswp[nxt][c1] = pb1;
        }
        __syncthreads();
    }

#pragma unroll
    for (int mt = 0; mt < 4; mt++) {
        int m0 = bm*128 + wm + mt*16 + gq;
        int m1 = m0 + 8;
        size_t row0 = 0, row1 = 0;
        bool v0 = m0 < Ml, v1 = m1 < Ml;
        if (v0) row0 = (size_t)(rowmap ? rowmap[m0] : m0);
        if (v1) row1 = (size_t)(rowmap ? rowmap[m1] : m1);
#pragma unroll
        for (int nt = 0; nt < 4; nt++) {
            int col = bn*128 + wn + nt*8 + tg*2;
            if (col >= N) continue;
            float bx = bias1[col], by = bias1[col+1];
            if (bias2) { bx += bias2[col]; by += bias2[col+1]; }
            if (v0) {
                float2 o = make_float2(acc[mt][nt][0] + bx, acc[mt][nt][1] + by);
                *(float2*)(C + row0*(size_t)ldc + col) = o;
            }
            if (v1) {
                float2 o = make_float2(acc[mt][nt][2] + bx, acc[mt][nt][3] + by);
                *(float2*)(C + row1*(size_t)ldc + col) = o;
            }
        }
    }
}

__global__ __launch_bounds__(256)
void k_gemm_pair(const float* __restrict__ b_enc, const float* __restrict__ b_ih,
                 const float* __restrict__ b_hh)
{
    __shared__ __align__(16) __nv_bfloat16 As[2][128*32];
    __shared__ __align__(16) __nv_bfloat16 Bs[2][128*32];
    int idx = blockIdx.x;
    if (idx < 392) {
        hgemm_body(idx >> 2, idx & 3, g_feats2, g_Wenc2, BB*PP, AA, AA,
                   b_enc, nullptr, g_encatt, nullptr, 0, As, Bs);
    } else {
        idx -= 392;
        hgemm_body(idx >> 4, idx & 15, g_embT2, g_Wih2, BB*TT, NG, NG,
                   b_ih, b_hh, g_embg, g_act, 1, As, Bs);
    }
}

__global__ __launch_bounds__(256)
void k_gemm_scores(const float* __restrict__ b_score, float* __restrict__ out)
{
    __shared__ __align__(16) __nv_bfloat16 As[2][128*32];
    __shared__ __align__(16) __nv_bfloat16 Bs[2][128*32];
    hgemm_body(blockIdx.x, blockIdx.y, g_hall2, g_Wsc2, BB*TT, VV, VV,
               b_score, nullptr, out, g_act, 1, As, Bs);
}

// ======================= fused persistent recurrence (1024 threads) =======================
// smem byte offsets
#define WHH_OFF  0
#define WIHC_OFF 32768
#define WDEC_OFF 65536
#define HT_OFF   81920
#define PART_OFF 147456
#define GH_OFF   180224
#define SM_TOTAL 184320

// flat per-slot barrier (replay-safe), tight spin — best measured variant
__device__ __forceinline__ void gridbar(int slot) {
    __syncthreads();
    if (threadIdx.x == 0) {
        int* p = &g_bars[slot];
        asm volatile("red.release.gpu.global.add.s32 [%0], 1;" :: "l"(p) : "memory");
        int v;
        do {
            asm volatile("ld.acquire.gpu.global.s32 %0, [%1];" : "=r"(v) : "l"(p) : "memory");
        } while (v < NCTA);
    }
    __syncthreads();
}

// stage 32 rows of fp32[512] (L2-coherent reads) into hi/lo swizzled tiles
__device__ __forceinline__ void stage32(const float* __restrict__ src, int b0, char* HTp, int tid) {
    for (int i = tid; i < 32*256; i += NTHR_R) {
        int r = i >> 8, kp = i & 255, k = kp*2;
        float2 v = __ldcg((const float2*)(src + (size_t)(b0+r)*512 + k));
        uint32_t hp, lp;
        cvt_hilo2(v, hp, lp);
        int kt = k >> 5, c = k & 31;
        stsw2(HTp + kt*2048, r, c, hp);
        stsw2(HTp + (16+kt)*2048, r, c, lp);
    }
}

// gates mma (ldmatrix, 32 warps): M=32, N=16, K=512 split 8 ways -> part[8][32][16]
__device__ __forceinline__ void gates_mma(uint32_t htA, uint32_t wbB, float* part,
                                          int wid, int lane) {
    int gq = lane >> 2, tg = lane & 3;
    int mh = (wid & 1)*16, nh = ((wid >> 1) & 1)*8, ks = wid >> 2;   // ks 0..7
    int rA = mh + (lane & 15);
    int swzA = (rA >> 1) & 3;
    int hiA = lane >> 4;
    int rB = nh + (lane & 7);
    int swzB = (rB >> 1) & 3;
    int hiB = (lane >> 3) & 1;
    uint32_t aL = htA + rA*64;
    uint32_t bL = wbB + rB*64;
    float acc[4] = {0.f, 0.f, 0.f, 0.f};
    for (int kt = ks*2; kt < ks*2 + 2; kt++) {
        uint32_t ah = aL + kt*2048;
        uint32_t bh = bL + kt*1024;
#pragma unroll
        for (int kk = 0; kk < 2; kk++) {
            uint32_t cA = (uint32_t)(((2*kk + hiA) ^ swzA) << 4);
            uint32_t cB = (uint32_t)(((2*kk + hiB) ^ swzB) << 4);
            uint32_t Ah[4], Al[4], Bh[2], Bl[2];
            ldsm_x4(Ah, ah + cA);
            ldsm_x4(Al, ah + 32768 + cA);
            ldsm_x2(Bh, bh + cB);
            ldsm_x2(Bl, bh + 16384 + cB);
            mma16816(acc, Ah, Bh);
            mma16816(acc, Ah, Bl);
            mma16816(acc, Al, Bh);
        }
    }
    int m0 = mh + gq, n0 = nh + tg*2;
    part[ks*512 + m0*16 + n0]       = acc[0];
    part[ks*512 + m0*16 + n0+1]     = acc[1];
    part[ks*512 + (m0+8)*16 + n0]   = acc[2];
    part[ks*512 + (m0+8)*16 + n0+1] = acc[3];
}

// att2 mma (ldmatrix, 32 warps): M=32, N=8 (4 real + 4 zero), K split 16 ways -> part2[16][32][8]
__device__ __forceinline__ void att2_mma(uint32_t htA, uint32_t wdB, float* part2,
                                         int wid, int lane) {
    int gq = lane >> 2, tg = lane & 3;
    int mh = (wid & 1)*16, ks = wid >> 1;   // ks 0..15
    int rA = mh + (lane & 15);
    int swzA = (rA >> 1) & 3;
    int hiA = lane >> 4;
    int rB = lane & 7;
    int swzB = (rB >> 1) & 3;
    int hiB = (lane >> 3) & 1;
    uint32_t aL = htA + rA*64;
    uint32_t bL = wdB + rB*64;
    float acc[4] = {0.f, 0.f, 0.f, 0.f};
    {
        int kt = ks;
        uint32_t ah = aL + kt*2048;
        uint32_t bh = bL + kt*512;
#pragma unroll
        for (int kk = 0; kk < 2; kk++) {
            uint32_t cA = (uint32_t)(((2*kk + hiA) ^ swzA) << 4);
            uint32_t cB = (uint32_t)(((2*kk + hiB) ^ swzB) << 4);
            uint32_t Ah[4], Al[4], Bh[2], Bl[2];
            ldsm_x4(Ah, ah + cA);
            ldsm_x4(Al, ah + 32768 + cA);
            ldsm_x2(Bh, bh + cB);
            ldsm_x2(Bl, bh + 8192 + cB);
            mma16816(acc, Ah, Bh);
            mma16816(acc, Ah, Bl);
            mma16816(acc, Al, Bh);
        }
    }
    int m0 = mh + gq, n0 = tg*2;
    part2[ks*256 + m0*8 + n0]       = acc[0];
    part2[ks*256 + m0*8 + n0+1]     = acc[1];
    part2[ks*256 + (m0+8)*8 + n0]   = acc[2];
    part2[ks*256 + (m0+8)*8 + n0+1] = acc[3];
}

__global__ __launch_bounds__(NTHR_R)
void k_recur(const float* __restrict__ W_dec, const float* __restrict__ W_hh,
             const float* __restrict__ W_ih,
             const float* __restrict__ b_dec, const float* __restrict__ W_full,
             const float* __restrict__ b_full, float* __restrict__ out)
{
    extern __shared__ float sm[];
    char* smc = (char*)sm;
    __shared__ int sdl[BB];
    __shared__ int snb[TT];
    int tid = threadIdx.x, lane = tid & 31, wid = tid >> 5;
    int j = blockIdx.x;

    if (tid < BB) sdl[tid] = g_declen[tid];
    if (tid >= 64 && tid < 64 + TT) snb[tid - 64] = g_nbact[tid - 64];

    // convert weight slices to swizzled bf16 hi/lo tiles (once)
    for (int i = tid; i < 16*256; i += NTHR_R) {
        int r = i >> 8, kp = i & 255, k = kp*2;
        int gr = 512*(r >> 2) + j*4 + (r & 3);
        float2 w1 = *(const float2*)(W_hh + (size_t)gr*512 + k);
        float2 w2 = *(const float2*)(W_ih + (size_t)gr*1024 + 512 + k);
        uint32_t hp, lp;
        int kt = k >> 5, c = k & 31;
        cvt_hilo2(w1, hp, lp);
        stsw2(smc + WHH_OFF + kt*1024, r, c, hp);
        stsw2(smc + WHH_OFF + (16+kt)*1024, r, c, lp);
        cvt_hilo2(w2, hp, lp);
        stsw2(smc + WIHC_OFF + kt*1024, r, c, hp);
        stsw2(smc + WIHC_OFF + (16+kt)*1024, r, c, lp);
    }
    for (int i = tid; i < 8*256; i += NTHR_R) {
        int r = i >> 8, kp = i & 255, k = kp*2;
        float2 w = (r < 4) ? *(const float2*)(W_dec + (size_t)(j*4+r)*512 + k)
                           : make_float2(0.f, 0.f);
        uint32_t hp, lp;
        cvt_hilo2(w, hp, lp);
        int kt = k >> 5, c = k & 31;
        stsw2(smc + WDEC_OFF + kt*512, r, c, hp);
        stsw2(smc + WDEC_OFF + (16+kt)*512, r, c, lp);
    }
    __syncthreads();

    float* part  = (float*)(smc + PART_OFF);       // 8*512 floats
    float* part2 = part + 4096;                    // 16*256 floats
    float* gh    = (float*)(smc + GH_OFF);
    uint32_t htS  = smem_u32(smc + HT_OFF);
    uint32_t whhS = smem_u32(smc + WHH_OFF);
    uint32_t wihS = smem_u32(smc + WIHC_OFF);
    uint32_t wdS  = smem_u32(smc + WDEC_OFF);

    int nbar = 0;
    for (int t = 0; t < TT; t++) {
        int npb = (snb[t] + 31) >> 5;
        // ---- Phase A: gates_h + att2 (mma) ----
        for (int pb = 0; pb < npb; pb++) {
            int b0 = pb*32;
            stage32(g_h, b0, smc + HT_OFF, tid);
            __syncthreads();
            gates_mma(htS, whhS, part, wid, lane);
            att2_mma(htS, wdS, part2, wid, lane);
            __syncthreads();
            for (int o = tid; o < 512; o += NTHR_R) {
                float s = 0.f;
#pragma unroll
                for (int ks = 0; ks < 8; ks++) s += part[ks*512 + o];
                gh[(b0 + (o >> 4))*16 + (o & 15)] = s;
            }
            if (tid < 128) {
                int m = tid >> 2, q = tid & 3;
                float s = 0.f;
#pragma unroll
                for (int ks = 0; ks < 16; ks++) s += part2[ks*256 + m*8 + q];
                g_att2[(b0+m)*512 + j*4 + q] = s;
            }
            __syncthreads();
        }
        gridbar(nbar++);

        // ---- Phase B: attention (CTAs 0..63, active only) ----
        if (j < BB && t < sdl[j]) {
            int b = j;
            float* wout = out + OFF_WEIGHTS + (size_t)(b*TT + t)*PP;
            float* att = (float*)(smc + HT_OFF);
            float* s_att2 = att;
            float* s_wf   = att + 512;
            float* s_e    = att + 1024;
            float* s_red  = att + 1248;
            float* rbuf   = att + 1280;
            for (int a = tid; a < AA; a += NTHR_R) {
                s_att2[a] = __ldcg(&g_att2[b*512 + a]) + b_dec[a];
                s_wf[a] = W_full[a];
            }
            __syncthreads();
            const float* ea = g_encatt + (size_t)b * PP * AA;
            for (int p = wid; p < PP; p += 32) {
                const float* row = ea + (size_t)p * AA;
                float sum = 0.f;
                for (int a = lane; a < AA; a += 32)
                    sum += fmaxf(row[a] + s_att2[a], 0.f) * s_wf[a];
#pragma unroll
                for (int o = 16; o; o >>= 1) sum += __shfl_xor_sync(0xffffffffu, sum, o);
                if (lane == 0) s_e[p] = sum + b_full[0];
            }
            __syncthreads();
            float m = -1e30f;
            if (tid < PP) m = s_e[tid];
#pragma unroll
            for (int o = 16; o; o >>= 1) m = fmaxf(m, __shfl_xor_sync(0xffffffffu, m, o));
            if (lane == 0) s_red[wid] = m;
            __syncthreads();
            float mx = s_red[0];
#pragma unroll
            for (int i = 1; i < 7; i++) mx = fmaxf(mx, s_red[i]);
            float ev = 0.f;
            if (tid < PP) ev = expf(s_e[tid] - mx);
            float sv = ev;
#pragma unroll
            for (int o = 16; o; o >>= 1) sv += __shfl_xor_sync(0xffffffffu, sv, o);
            __syncthreads();
            if (lane == 0) s_red[wid] = sv;
            __syncthreads();
            float tot = 0.f;
#pragma unroll
            for (int i = 0; i < 7; i++) tot += s_red[i];
            float inv = 1.f / tot;
            if (tid < PP) {
                float al = ev * inv;
                s_e[tid] = al;
                wout[tid] = al;
            }
            __syncthreads();
            int hq = tid & 63, pc2 = tid >> 6;   // 16-way pixel split
            const float4* fb4 = (const float4*)(g_feats + (size_t)b * PP * HH);
            float4 a0 = make_float4(0,0,0,0), a1 = make_float4(0,0,0,0);
            for (int p = pc2; p < PP; p += 16) {
                float al = s_e[p];
                float4 v0 = fb4[p*128 + hq*2];
                float4 v1 = fb4[p*128 + hq*2 + 1];
                a0.x = fmaf(al, v0.x, a0.x); a0.y = fmaf(al, v0.y, a0.y);
                a0.z = fmaf(al, v0.z, a0.z); a0.w = fmaf(al, v0.w, a0.w);
                a1.x = fmaf(al, v1.x, a1.x); a1.y = fmaf(al, v1.y, a1.y);
                a1.z = fmaf(al, v1.z, a1.z); a1.w = fmaf(al, v1.w, a1.w);
            }
            float* rb = rbuf + pc2*512 + hq*8;
            rb[0]=a0.x; rb[1]=a0.y; rb[2]=a0.z; rb[3]=a0.w;
            rb[4]=a1.x; rb[5]=a1.y; rb[6]=a1.z; rb[7]=a1.w;
            __syncthreads();
            for (int o = tid; o < 512; o += NTHR_R) {
                float s = 0.f;
#pragma unroll
                for (int q = 0; q < 16; q++) s += rbuf[q*512 + o];
                g_ctx[b*512 + o] = s;
            }
        }
        gridbar(nbar++);

        // ---- Phase C: gates_ctx (mma) + combine + LSTM ----
        for (int pb = 0; pb < npb; pb++) {
            int b0 = pb*32;
            stage32(g_ctx, b0, smc + HT_OFF, tid);
            __syncthreads();
            gates_mma(htS, wihS, part, wid, lane);
            __syncthreads();
            for (int o = tid; o < 512; o += NTHR_R) {
                int m = o >> 4, n = o & 15;
                int b = b0 + m;
                int gr = 512*(n >> 2) + j*4 + (n & 3);
                float s = 0.f;
#pragma unroll
                for (int ks = 0; ks < 8; ks++) s += part[ks*512 + o];
                gh[b*16 + n] += s + g_embg[(size_t)(b*TT + t)*NG + gr];
            }
            __syncthreads();
        }
        if (tid < 256) {
            int b = tid >> 2, q = tid & 3;
            if (t < sdl[b]) {
                float gi = gh[b*16 + q];
                float gf = gh[b*16 + 4 + q];
                float gg = gh[b*16 + 8 + q];
                float go = gh[b*16 + 12 + q];
                float ig = 1.f / (1.f + expf(-gi));
                float fg = 1.f / (1.f + expf(-gf));
                float gv = tanhf(gg);
                float og = 1.f / (1.f + expf(-go));
                int kc = j*4 + q;
                float c_new = fg * g_c[b*512 + kc] + ig * gv;
                float h_new = og * tanhf(c_new);
                __nv_bfloat16 hh = __float2bfloat16(h_new);
                __nv_bfloat16 hl = __float2bfloat16(h_new - __bfloat162float(hh));
                g_hall2[(size_t)(b*TT + t)*1024 + kc]       = hh;
                g_hall2[(size_t)(b*TT + t)*1024 + 512 + kc] = hl;
                g_h[b*512 + kc] = h_new;
                g_c[b*512 + kc] = c_new;
            }
        }
        gridbar(nbar++);
    }
}

// ======================= launch =======================
extern "C" void kernel_launch(void* const* d_in, const int* in_sizes, int n_in,
                              void* d_out, int out_size) {
    const float* imf     = (const float*)d_in[0];
    const int*   caps    = (const int*)  d_in[1];
    const int*   caplens = (const int*)  d_in[2];
    const float* emb     = (const float*)d_in[3];
    const float* W_ih    = (const float*)d_in[4];
    const float* W_hh    = (const float*)d_in[5];
    const float* b_ih    = (const float*)d_in[6];
    const float* b_hh    = (const float*)d_in[7];
    const float* W_enc   = (const float*)d_in[8];
    const float* b_enc   = (const float*)d_in[9];
    const float* W_dec   = (const float*)d_in[10];
    const float* b_dec   = (const float*)d_in[11];
    const float* W_full  = (const float*)d_in[12];
    const float* b_full  = (const float*)d_in[13];
    const float* W_score = (const float*)d_in[14];
    const float* b_score = (const float*)d_in[15];
    float* out = (float*)d_out;

    cudaFuncSetAttribute(k_recur, cudaFuncAttributeMaxDynamicSharedMemorySize, SM_TOTAL);

    // 1: sort + caps/declen/sortind outputs
    k_sort<<<1, BB>>>(caplens, caps, out);
    // 2: fused gathers + bf16 hi/lo conversions + zeroing + init
    k_cvt_all<<<1024, 256>>>(imf, caps, emb, W_enc, W_ih, W_score, out);
    // 3: fused enc_att + G_emb tensor-core GEMMs
    k_gemm_pair<<<792, 256>>>(b_enc, b_ih, b_hh);
    // 4: persistent recurrence (1024 threads, writes g_hall2 directly)
    k_recur<<<NCTA, NTHR_R, SM_TOTAL>>>(W_dec, W_hh, W_ih, b_dec, W_full, b_full, out);
    // 5: scores GEMM
    k_gemm_scores<<<dim3((BB*TT + 127)/128, (VV + 127)/128), 256>>>(b_score, out);
}

// round 13
// speedup vs baseline: 1.9046x; 1.0095x over previous
#include <cuda_runtime.h>
#include <cuda_bf16.h>
#include <cstdint>
#include <math.h>

#define BB 64
#define PP 196
#define HH 512
#define EE 512
#define AA 512
#define VV 10000
#define MAXCAP 50
#define TT 49
#define NG 2048   // 4*H

// output layout (float32): scores (B,T,V), caps_s (B,50), decode_lengths (B,), weights (B,T,P), sort_ind (B,)
#define N_SCORES   (BB*TT*VV)
#define OFF_CAPS   (N_SCORES)
#define OFF_DECLEN (OFF_CAPS + BB*MAXCAP)
#define OFF_WEIGHTS (OFF_DECLEN + BB)
#define OFF_SORT   (OFF_WEIGHTS + BB*TT*PP)

#define NCTA 128
#define NTHR 256
#define NTHR_R 1024

// ======================= scratch =======================
__device__ float g_feats[BB*PP*HH];
__device__ float g_encatt[BB*PP*AA];
__device__ float g_embg[BB*TT*NG];
__device__ float g_h[BB*HH];
__device__ float g_c[BB*HH];
__device__ float g_att2[BB*AA];
__device__ float g_ctx[BB*HH];
__device__ float g_gh[BB*NG];          // gates_h: [b][slice 0..127][16]
__device__ int   g_sortidx[BB];
__device__ int   g_declen[BB];
__device__ int   g_nbact[TT];
__device__ int   g_act[BB*TT];
__device__ int   g_nact;
__device__ int   g_bars[160];

// bf16 hi/lo packed [rows][1024]: cols 0-511 hi, 512-1023 lo
__device__ __nv_bfloat16 g_feats2[BB*PP*1024];
__device__ __nv_bfloat16 g_embT2[BB*TT*1024];
__device__ __nv_bfloat16 g_hall2[BB*TT*1024];
__device__ __nv_bfloat16 g_Wenc2[AA*1024];
__device__ __nv_bfloat16 g_Wih2[NG*1024];
__device__ __nv_bfloat16 g_Wsc2[VV*1024];

// ======================= helpers =======================
__device__ __forceinline__ void mma16816(float* d, const uint32_t* a, const uint32_t* b) {
    asm volatile("mma.sync.aligned.m16n8k16.row.col.f32.bf16.bf16.f32 "
        "{%0,%1,%2,%3}, {%4,%5,%6,%7}, {%8,%9}, {%0,%1,%2,%3};"
        : "+f"(d[0]), "+f"(d[1]), "+f"(d[2]), "+f"(d[3])
        : "r"(a[0]), "r"(a[1]), "r"(a[2]), "r"(a[3]), "r"(b[0]), "r"(b[1]));
}
__device__ __forceinline__ void ldsm_x4(uint32_t* r, uint32_t saddr) {
    asm volatile("ldmatrix.sync.aligned.m8n8.x4.shared.b16 {%0,%1,%2,%3}, [%4];"
        : "=r"(r[0]), "=r"(r[1]), "=r"(r[2]), "=r"(r[3]) : "r"(saddr));
}
__device__ __forceinline__ void ldsm_x2(uint32_t* r, uint32_t saddr) {
    asm volatile("ldmatrix.sync.aligned.m8n8.x2.shared.b16 {%0,%1}, [%2];"
        : "=r"(r[0]), "=r"(r[1]) : "r"(saddr));
}
__device__ __forceinline__ uint32_t smem_u32(const void* p) {
    return (uint32_t)__cvta_generic_to_shared(p);
}
// store bf16x2 at (r, c even 0..31) in swizzled tile (64B rows, 16B-chunk XOR)
__device__ __forceinline__ void stsw2(char* s, int r, int c, uint32_t v) {
    int byte = r*64 + ((((c >> 3) ^ ((r >> 1) & 3))) << 4) + (c & 7)*2;
    *(uint32_t*)(s + byte) = v;
}
__device__ __forceinline__ void cvt_hilo2(float2 v, uint32_t& hp, uint32_t& lp) {
    __nv_bfloat16 h0 = __float2bfloat16(v.x), h1 = __float2bfloat16(v.y);
    float l0 = v.x - __bfloat162float(h0), l1 = v.y - __bfloat162float(h1);
    __nv_bfloat16 b0 = __float2bfloat16(l0), b1 = __float2bfloat16(l1);
    hp = (uint32_t)__bfloat16_as_ushort(h0) | ((uint32_t)__bfloat16_as_ushort(h1) << 16);
    lp = (uint32_t)__bfloat16_as_ushort(b0) | ((uint32_t)__bfloat16_as_ushort(b1) << 16);
}

// ======================= prep kernels =======================
__global__ void k_sort(const int* __restrict__ caplens, const int* __restrict__ caps,
                       float* __restrict__ out) {
    __shared__ int s_sort[BB];
    if (threadIdx.x == 0) {
        int cl[BB];
        for (int i = 0; i < BB; i++) cl[i] = caplens[i];
        int r = 0;
        for (int v = MAXCAP; v >= 0 && r < BB; v--)
            for (int i = 0; i < BB; i++)
                if (cl[i] == v) { g_sortidx[r] = i; s_sort[r] = i; r++; }
        int na = 0;
        int dls[BB];
        for (int b = 0; b < BB; b++) {
            int dl = cl[g_sortidx[b]] - 1;
            dls[b] = dl;
            g_declen[b] = dl;
            out[OFF_DECLEN + b] = (float)dl;
            out[OFF_SORT + b]   = (float)g_sortidx[b];
            for (int t = 0; t < dl; t++) g_act[na++] = b*TT + t;
        }
        g_nact = na;
        for (int t = 0; t < TT; t++) {
            int c = 0;
            for (int b = 0; b < BB; b++) if (dls[b] > t) c++;
            g_nbact[t] = c;
        }
    }
    __syncthreads();
    int b = threadIdx.x;
    int src = s_sort[b];
    for (int t = 0; t < MAXCAP; t++)
        out[OFF_CAPS + b*MAXCAP + t] = (float)caps[src*MAXCAP + t];
}

// fused gather + hi/lo conversion (pairwise) + zero + init
#define P0 (BB*PP*256)
#define P1 (BB*TT*256)
#define P2 (AA*256)
#define P3 (NG*256)
#define P4 (VV*256)
#define Z5 (N_SCORES/4)
#define Z6 (BB*TT*PP/4)
#define Z7 (BB*HH)
#define Z8 160
__global__ void k_cvt_all(const float* __restrict__ imf, const int* __restrict__ caps,
                          const float* __restrict__ emb, const float* __restrict__ W_enc,
                          const float* __restrict__ W_ih, const float* __restrict__ W_score,
                          float* __restrict__ out)
{
    const int total = P0+P1+P2+P3+P4+Z5+Z6+Z7+Z8;
    for (int i = blockIdx.x*blockDim.x + threadIdx.x; i < total; i += gridDim.x*blockDim.x) {
        int x = i;
        if (x < P0) {
            int r = x >> 8, c2 = x & 255, k = c2*2;
            int b = r / PP, p = r - b*PP;
            float2 v = *(const float2*)(imf + ((size_t)g_sortidx[b]*PP + p)*512 + k);
            *(float2*)(g_feats + (size_t)r*512 + k) = v;
            uint32_t hp, lp; cvt_hilo2(v, hp, lp);
            ((uint32_t*)g_feats2)[(size_t)r*512 + c2] = hp;
            ((uint32_t*)g_feats2)[(size_t)r*512 + 256 + c2] = lp;
            continue;
        }
        x -= P0;
        if (x < P1) {
            int r = x >> 8, c2 = x & 255, k = c2*2;
            int b = r / TT, t = r - b*TT;
            int tok = caps[g_sortidx[b]*MAXCAP + t];
            float2 v = *(const float2*)(emb + (size_t)tok*512 + k);
            uint32_t hp, lp; cvt_hilo2(v, hp, lp);
            ((uint32_t*)g_embT2)[(size_t)r*512 + c2] = hp;
            ((uint32_t*)g_embT2)[(size_t)r*512 + 256 + c2] = lp;
            continue;
        }
        x -= P1;
        if (x < P2) {
            int r = x >> 8, c2 = x & 255, k = c2*2;
            float2 v = *(const float2*)(W_enc + (size_t)r*512 + k);
            uint32_t hp, lp; cvt_hilo2(v, hp, lp);
            ((uint32_t*)g_Wenc2)[(size_t)r*512 + c2] = hp;
            ((uint32_t*)g_Wenc2)[(size_t)r*512 + 256 + c2] = lp;
            continue;
        }
        x -= P2;
        if (x < P3) {
            int r = x >> 8, c2 = x & 255, k = c2*2;
            float2 v = *(const float2*)(W_ih + (size_t)r*1024 + k);
            uint32_t hp, lp; cvt_hilo2(v, hp, lp);
            ((uint32_t*)g_Wih2)[(size_t)r*512 + c2] = hp;
            ((uint32_t*)g_Wih2)[(size_t)r*512 + 256 + c2] = lp;
            continue;
        }
        x -= P3;
        if (x < P4) {
            int r = x >> 8, c2 = x & 255, k = c2*2;
            float2 v = *(const float2*)(W_score + (size_t)r*512 + k);
            uint32_t hp, lp; cvt_hilo2(v, hp, lp);
            ((uint32_t*)g_Wsc2)[(size_t)r*512 + c2] = hp;
            ((uint32_t*)g_Wsc2)[(size_t)r*512 + 256 + c2] = lp;
            continue;
        }
        x -= P4;
        if (x < Z5) {
            ((float4*)out)[x] = make_float4(0.f, 0.f, 0.f, 0.f);
            continue;
        }
        x -= Z5;
        if (x < Z6) {
            ((float4*)(out + OFF_WEIGHTS))[x] = make_float4(0.f, 0.f, 0.f, 0.f);
            continue;
        }
        x -= Z6;
        if (x < Z7) { g_h[x] = 0.f; g_c[x] = 0.f; continue; }
        x -= Z7;
        g_bars[x] = 0;
    }
}

// ======================= mma.sync bf16x3 GEMM body (ldmatrix + double buffer) ==========
__device__ __forceinline__ void hgemm_body(
    int bm, int bn,
    const __nv_bfloat16* __restrict__ A2, const __nv_bfloat16* __restrict__ B2,
    int M, int N, int ldc,
    const float* __restrict__ bias1, const float* __restrict__ bias2,
    float* __restrict__ C, const int* __restrict__ rowmap, int use_nact,
    __nv_bfloat16 (*As)[128*32], __nv_bfloat16 (*Bs)[128*32])
{
    int tid = threadIdx.x;
    int Ml = use_nact ? g_nact : M;
    if (bm*128 >= Ml) return;

    int lrow = tid >> 1;
    int lc0 = (tid & 1) * 2;
    int gm = bm*128 + lrow;
    const uint4* arow = nullptr;
    if (gm < Ml) { int r = rowmap ? rowmap[gm] : gm; arow = (const uint4*)(A2 + (size_t)r*1024); }
    int gn = bn*128 + lrow;
    const uint4* brow = (gn < N) ? (const uint4*)(B2 + (size_t)gn*1024) : nullptr;

    int swz = (lrow >> 1) & 3;
    uint4* aswp[2] = {(uint4*)(As[0] + lrow*32), (uint4*)(As[1] + lrow*32)};
    uint4* bswp[2] = {(uint4*)(Bs[0] + lrow*32), (uint4*)(Bs[1] + lrow*32)};
    int c0 = lc0 ^ swz, c1 = (lc0+1) ^ swz;

    int lane = tid & 31, wid = tid >> 5;
    int wm = (wid >> 2) * 64;
    int wn = (wid & 3) * 32;
    int gq = lane >> 2, tg = lane & 3;

    int rA = wm + (lane & 15);
    int swzA = (rA >> 1) & 3;
    int hiA = lane >> 4;
    int rB = wn + (lane & 7);
    int swzB = (rB >> 1) & 3;
    int hiB = (lane >> 3) & 1;
    uint32_t aS[2] = {smem_u32(As[0]) + rA*64, smem_u32(As[1]) + rA*64};
    uint32_t bS[2] = {smem_u32(Bs[0]) + rB*64, smem_u32(Bs[1]) + rB*64};

    float acc[4][4][4];
#pragma unroll
    for (int mt = 0; mt < 4; mt++)
#pragma unroll
        for (int nt = 0; nt < 4; nt++)
#pragma unroll
            for (int r = 0; r < 4; r++) acc[mt][nt][r] = 0.f;

    const uint4 z = make_uint4(0,0,0,0);
    const int kau4[3] = {0, 0, 64};
    const int kbu4[3] = {0, 64, 0};
    uint4 pa0 = arow ? arow[lc0]   : z;
    uint4 pa1 = arow ? arow[lc0+1] : z;
    uint4 pb0 = brow ? brow[lc0]   : z;
    uint4 pb1 = brow ? brow[lc0+1] : z;
    aswp[0][c0] = pa0; aswp[0][c1] = pa1;
    bswp[0][c0] = pb0; bswp[0][c1] = pb1;
    __syncthreads();

    for (int ci = 0; ci < 48; ci++) {
        int cur = ci & 1;
        if (ci + 1 < 48) {
            int term = (ci+1) >> 4, kc = (ci+1) & 15;
            int ab = kau4[term] + kc*4, bb = kbu4[term] + kc*4;
            pa0 = arow ? arow[ab + lc0]   : z;
            pa1 = arow ? arow[ab + lc0+1] : z;
            pb0 = brow ? brow[bb + lc0]   : z;
            pb1 = brow ? brow[bb + lc0+1] : z;
        }
#pragma unroll
        for (int kk = 0; kk < 2; kk++) {
            uint32_t cA = (uint32_t)(((2*kk + hiA) ^ swzA) << 4);
            uint32_t cB = (uint32_t)(((2*kk + hiB) ^ swzB) << 4);
            uint32_t afr[4][4];
#pragma unroll
            for (int mt = 0; mt < 4; mt++)
                ldsm_x4(afr[mt], aS[cur] + mt*1024 + cA);
            uint32_t bfr[4][2];
#pragma unroll
            for (int nt = 0; nt < 4; nt++)
                ldsm_x2(bfr[nt], bS[cur] + nt*512 + cB);
#pragma unroll
            for (int mt = 0; mt < 4; mt++)
#pragma unroll
                for (int nt = 0; nt < 4; nt++)
                    mma16816(acc[mt][nt], afr[mt], bfr[nt]);
        }
        if (ci + 1 < 48) {
            int nxt = cur ^ 1;
            aswp[nxt][c0] = pa0; aswp[nxt][c1] = pa1;
            bswp[nxt][c0] = pb0; bswp[nxt][c1] = pb1;
        }
        __syncthreads();
    }

#pragma unroll
    for (int mt = 0; mt < 4; mt++) {
        int m0 = bm*128 + wm + mt*16 + gq;
        int m1 = m0 + 8;
        size_t row0 = 0, row1 = 0;
        bool v0 = m0 < Ml, v1 = m1 < Ml;
        if (v0) row0 = (size_t)(rowmap ? rowmap[m0] : m0);
        if (v1) row1 = (size_t)(rowmap ? rowmap[m1] : m1);
#pragma unroll
        for (int nt = 0; nt < 4; nt++) {
            int col = bn*128 + wn + nt*8 + tg*2;
            if (col >= N) continue;
            float bx = bias1[col], by = bias1[col+1];
            if (bias2) { bx += bias2[col]; by += bias2[col+1]; }
            if (v0) {
                float2 o = make_float2(acc[mt][nt][0] + bx, acc[mt][nt][1] + by);
                *(float2*)(C + row0*(size_t)ldc + col) = o;
            }
            if (v1) {
                float2 o = make_float2(acc[mt][nt][2] + bx, acc[mt][nt][3] + by);
                *(float2*)(C + row1*(size_t)ldc + col) = o;
            }
        }
    }
}

__global__ __launch_bounds__(256)
void k_gemm_pair(const float* __restrict__ b_enc, const float* __restrict__ b_ih,
                 const float* __restrict__ b_hh)
{
    __shared__ __align__(16) __nv_bfloat16 As[2][128*32];
    __shared__ __align__(16) __nv_bfloat16 Bs[2][128*32];
    int idx = blockIdx.x;
    if (idx < 392) {
        hgemm_body(idx >> 2, idx & 3, g_feats2, g_Wenc2, BB*PP, AA, AA,
                   b_enc, nullptr, g_encatt, nullptr, 0, As, Bs);
    } else {
        idx -= 392;
        hgemm_body(idx >> 4, idx & 15, g_embT2, g_Wih2, BB*TT, NG, NG,
                   b_ih, b_hh, g_embg, g_act, 1, As, Bs);
    }
}

__global__ __launch_bounds__(256)
void k_gemm_scores(const float* __restrict__ b_score, float* __restrict__ out)
{
    __shared__ __align__(16) __nv_bfloat16 As[2][128*32];
    __shared__ __align__(16) __nv_bfloat16 Bs[2][128*32];
    hgemm_body(blockIdx.x, blockIdx.y, g_hall2, g_Wsc2, BB*TT, VV, VV,
               b_score, nullptr, out, g_act, 1, As, Bs);
}

// ======================= fused persistent recurrence (1024 threads) =======================
// smem byte offsets
#define WIHC_OFF 0
#define WDEC_OFF 32768
#define WHH_OFF  49152
#define HT_OFF   114688
#define PART_OFF 180224
#define GH_OFF   196608
#define SM_TOTAL 200704

// flat per-slot barrier (replay-safe), tight spin — best measured variant
__device__ __forceinline__ void gridbar(int slot) {
    __syncthreads();
    if (threadIdx.x == 0) {
        int* p = &g_bars[slot];
        asm volatile("red.release.gpu.global.add.s32 [%0], 1;" :: "l"(p) : "memory");
        int v;
        do {
            asm volatile("ld.acquire.gpu.global.s32 %0, [%1];" : "=r"(v) : "l"(p) : "memory");
        } while (v < NCTA);
    }
    __syncthreads();
}

// stage 32 rows of fp32[512] (L2-coherent reads) into hi/lo swizzled tiles
__device__ __forceinline__ void stage32(const float* __restrict__ src, int b0, char* HTp, int tid) {
    for (int i = tid; i < 32*256; i += NTHR_R) {
        int r = i >> 8, kp = i & 255, k = kp*2;
        float2 v = __ldcg((const float2*)(src + (size_t)(b0+r)*512 + k));
        uint32_t hp, lp;
        cvt_hilo2(v, hp, lp);
        int kt = k >> 5, c = k & 31;
        stsw2(HTp + kt*2048, r, c, hp);
        stsw2(HTp + (16+kt)*2048, r, c, lp);
    }
}

// gates_ctx mma (32 warps): M=32, N=16 (slice j), K split 8 -> part[8][32][16]
__device__ __forceinline__ void gates_mma(uint32_t htA, uint32_t wbB, float* part,
                                          int wid, int lane) {
    int gq = lane >> 2, tg = lane & 3;
    int mh = (wid & 1)*16, nh = ((wid >> 1) & 1)*8, ks = wid >> 2;   // ks 0..7
    int rA = mh + (lane & 15);
    int swzA = (rA >> 1) & 3;
    int hiA = lane >> 4;
    int rB = nh + (lane & 7);
    int swzB = (rB >> 1) & 3;
    int hiB = (lane >> 3) & 1;
    uint32_t aL = htA + rA*64;
    uint32_t bL = wbB + rB*64;
    float acc[4] = {0.f, 0.f, 0.f, 0.f};
    for (int kt = ks*2; kt < ks*2 + 2; kt++) {
        uint32_t ah = aL + kt*2048;
        uint32_t bh = bL + kt*1024;
#pragma unroll
        for (int kk = 0; kk < 2; kk++) {
            uint32_t cA = (uint32_t)(((2*kk + hiA) ^ swzA) << 4);
            uint32_t cB = (uint32_t)(((2*kk + hiB) ^ swzB) << 4);
            uint32_t Ah[4], Al[4], Bh[2], Bl[2];
            ldsm_x4(Ah, ah + cA);
            ldsm_x4(Al, ah + 32768 + cA);
            ldsm_x2(Bh, bh + cB);
            ldsm_x2(Bl, bh + 16384 + cB);
            mma16816(acc, Ah, Bh);
            mma16816(acc, Ah, Bl);
            mma16816(acc, Al, Bh);
        }
    }
    int m0 = mh + gq, n0 = nh + tg*2;
    part[ks*512 + m0*16 + n0]       = acc[0];
    part[ks*512 + m0*16 + n0+1]     = acc[1];
    part[ks*512 + (m0+8)*16 + n0]   = acc[2];
    part[ks*512 + (m0+8)*16 + n0+1] = acc[3];
}

// gates_h mma for 2 slices (32 warps): M=32, N=32 rows, K split 4 -> part[4][32][32]
// WHH tiles: 32 rows x 64B = 2048B per kt tile; hi tiles 0..15, lo at +32768
__device__ __forceinline__ void gates_mma32(uint32_t htA, uint32_t whB, float* part,
                                            int wid, int lane) {
    int gq = lane >> 2, tg = lane & 3;
    int mh = (wid & 1)*16, nh = ((wid >> 1) & 3)*8, ks = wid >> 3;   // ks 0..3
    int rA = mh + (lane & 15);
    int swzA = (rA >> 1) & 3;
    int hiA = lane >> 4;
    int rB = nh + (lane & 7);
    int swzB = (rB >> 1) & 3;
    int hiB = (lane >> 3) & 1;
    uint32_t aL = htA + rA*64;
    uint32_t bL = whB + rB*64;
    float acc[4] = {0.f, 0.f, 0.f, 0.f};
    for (int kt = ks*4; kt < ks*4 + 4; kt++) {
        uint32_t ah = aL + kt*2048;
        uint32_t bh = bL + kt*2048;
#pragma unroll
        for (int kk = 0; kk < 2; kk++) {
            uint32_t cA = (uint32_t)(((2*kk + hiA) ^ swzA) << 4);
            uint32_t cB = (uint32_t)(((2*kk + hiB) ^ swzB) << 4);
            uint32_t Ah[4], Al[4], Bh[2], Bl[2];
            ldsm_x4(Ah, ah + cA);
            ldsm_x4(Al, ah + 32768 + cA);
            ldsm_x2(Bh, bh + cB);
            ldsm_x2(Bl, bh + 32768 + cB);
            mma16816(acc, Ah, Bh);
            mma16816(acc, Ah, Bl);
            mma16816(acc, Al, Bh);
        }
    }
    int m0 = mh + gq, n0 = nh + tg*2;
    part[ks*1024 + m0*32 + n0]       = acc[0];
    part[ks*1024 + m0*32 + n0+1]     = acc[1];
    part[ks*1024 + (m0+8)*32 + n0]   = acc[2];
    part[ks*1024 + (m0+8)*32 + n0+1] = acc[3];
}

// att2 mma (32 warps): M=32, N=8 (4 real + 4 zero), K split 16 -> part2[16][32][8]
__device__ __forceinline__ void att2_mma(uint32_t htA, uint32_t wdB, float* part2,
                                         int wid, int lane) {
    int gq = lane >> 2, tg = lane & 3;
    int mh = (wid & 1)*16, ks = wid >> 1;   // ks 0..15
    int rA = mh + (lane & 15);
    int swzA = (rA >> 1) & 3;
    int hiA = lane >> 4;
    int rB = lane & 7;
    int swzB = (rB >> 1) & 3;
    int hiB = (lane >> 3) & 1;
    uint32_t aL = htA + rA*64;
    uint32_t bL = wdB + rB*64;
    float acc[4] = {0.f, 0.f, 0.f, 0.f};
    {
        int kt = ks;
        uint32_t ah = aL + kt*2048;
        uint32_t bh = bL + kt*512;
#pragma unroll
        for (int kk = 0; kk < 2; kk++) {
            uint32_t cA = (uint32_t)(((2*kk + hiA) ^ swzA) << 4);
            uint32_t cB = (uint32_t)(((2*kk + hiB) ^ swzB) << 4);
            uint32_t Ah[4], Al[4], Bh[2], Bl[2];
            ldsm_x4(Ah, ah + cA);
            ldsm_x4(Al, ah + 32768 + cA);
            ldsm_x2(Bh, bh + cB);
            ldsm_x2(Bl, bh + 8192 + cB);
            mma16816(acc, Ah, Bh);
            mma16816(acc, Ah, Bl);
            mma16816(acc, Al, Bh);
        }
    }
    int m0 = mh + gq, n0 = tg*2;
    part2[ks*256 + m0*8 + n0]       = acc[0];
    part2[ks*256 + m0*8 + n0+1]     = acc[1];
    part2[ks*256 + (m0+8)*8 + n0]   = acc[2];
    part2[ks*256 + (m0+8)*8 + n0+1] = acc[3];
}

__global__ __launch_bounds__(NTHR_R)
void k_recur(const float* __restrict__ W_dec, const float* __restrict__ W_hh,
             const float* __restrict__ W_ih,
             const float* __restrict__ b_dec, const float* __restrict__ W_full,
             const float* __restrict__ b_full, float* __restrict__ out)
{
    extern __shared__ float sm[];
    char* smc = (char*)sm;
    __shared__ int sdl[BB];
    __shared__ int snb[TT];
    int tid = threadIdx.x, lane = tid & 31, wid = tid >> 5;
    int j = blockIdx.x;

    if (tid < BB) sdl[tid] = g_declen[tid];
    if (tid >= 64 && tid < 64 + TT) snb[tid - 64] = g_nbact[tid - 64];

    // WIHC slice j (all CTAs) + WDEC slice j (all CTAs)
    for (int i = tid; i < 16*256; i += NTHR_R) {
        int r = i >> 8, kp = i & 255, k = kp*2;
        int gr = 512*(r >> 2) + j*4 + (r & 3);
        float2 w2 = *(const float2*)(W_ih + (size_t)gr*1024 + 512 + k);
        uint32_t hp, lp;
        int kt = k >> 5, c = k & 31;
        cvt_hilo2(w2, hp, lp);
        stsw2(smc + WIHC_OFF + kt*1024, r, c, hp);
        stsw2(smc + WIHC_OFF + (16+kt)*1024, r, c, lp);
    }
    for (int i = tid; i < 8*256; i += NTHR_R) {
        int r = i >> 8, kp = i & 255, k = kp*2;
        float2 w = (r < 4) ? *(const float2*)(W_dec + (size_t)(j*4+r)*512 + k)
                           : make_float2(0.f, 0.f);
        uint32_t hp, lp;
        cvt_hilo2(w, hp, lp);
        int kt = k >> 5, c = k & 31;
        stsw2(smc + WDEC_OFF + kt*512, r, c, hp);
        stsw2(smc + WDEC_OFF + (16+kt)*512, r, c, lp);
    }
    // WHH 2 slices (CTAs 64..127 only): slices s0, s0+1, 32 rows
    if (j >= 64) {
        int s0 = (j - 64)*2;
        for (int i = tid; i < 32*256; i += NTHR_R) {
            int r = i >> 8, kp = i & 255, k = kp*2;
            int s = s0 + (r >> 4), rr = r & 15;
            int gr = 512*(rr >> 2) + s*4 + (rr & 3);
            float2 w1 = *(const float2*)(W_hh + (size_t)gr*512 + k);
            uint32_t hp, lp;
            int kt = k >> 5, c = k & 31;
            cvt_hilo2(w1, hp, lp);
            stsw2(smc + WHH_OFF + kt*2048, r, c, hp);
            stsw2(smc + WHH_OFF + 32768 + kt*2048, r, c, lp);
        }
    }
    __syncthreads();

    float* part  = (float*)(smc + PART_OFF);       // up to 4096 floats
    float* part2 = part;                           // att2 reuses same region (16*256=4096)
    float* gh    = (float*)(smc + GH_OFF);
    uint32_t htS  = smem_u32(smc + HT_OFF);
    uint32_t wihS = smem_u32(smc + WIHC_OFF);
    uint32_t whhS = smem_u32(smc + WHH_OFF);
    uint32_t wdS  = smem_u32(smc + WDEC_OFF);

    int nbar = 0;
    for (int t = 0; t < TT; t++) {
        int npb = (snb[t] + 31) >> 5;
        // ---- Phase A: att2 only ----
        for (int pb = 0; pb < npb; pb++) {
            int b0 = pb*32;
            stage32(g_h, b0, smc + HT_OFF, tid);
            __syncthreads();
            att2_mma(htS, wdS, part2, wid, lane);
            __syncthreads();
            if (tid < 128) {
                int m = tid >> 2, q = tid & 3;
                float s = 0.f;
#pragma unroll
                for (int ks = 0; ks < 16; ks++) s += part2[ks*256 + m*8 + q];
                g_att2[(b0+m)*512 + j*4 + q] = s;
            }
            __syncthreads();
        }
        gridbar(nbar++);

        // ---- Phase B: attention (CTAs 0..63) || gates_h (CTAs 64..127) ----
        if (j >= 64) {
            int s0 = (j - 64)*2;
            for (int pb = 0; pb < npb; pb++) {
                int b0 = pb*32;
                stage32(g_h, b0, smc + HT_OFF, tid);
                __syncthreads();
                gates_mma32(htS, whhS, part, wid, lane);
                __syncthreads();
                // reduce part[4][32][32] -> g_gh[(b*128 + s)*16 + rr]
                {
                    int o = tid;   // 1024 outputs, 1024 threads
                    int m = o >> 5, n = o & 31;
                    float s = part[o] + part[1024 + o] + part[2048 + o] + part[3072 + o];
                    int sl = s0 + (n >> 4), rr = n & 15;
                    g_gh[((b0 + m)*128 + sl)*16 + rr] = s;
                }
                __syncthreads();
            }
        } else if (t < sdl[j]) {
            int b = j;
            float* wout = out + OFF_WEIGHTS + (size_t)(b*TT + t)*PP;
            float* att = (float*)(smc + HT_OFF);
            float* s_att2 = att;
            float* s_wf   = att + 512;
            float* s_e    = att + 1024;
            float* s_red  = att + 1248;
            float* rbuf   = att + 1280;
            for (int a = tid; a < AA; a += NTHR_R) {
                s_att2[a] = __ldcg(&g_att2[b*512 + a]) + b_dec[a];
                s_wf[a] = W_full[a];
            }
            __syncthreads();
            const float* ea = g_encatt + (size_t)b * PP * AA;
            for (int p = wid; p < PP; p += 32) {
                const float* row = ea + (size_t)p * AA;
                float sum = 0.f;
                for (int a = lane; a < AA; a += 32)
                    sum += fmaxf(row[a] + s_att2[a], 0.f) * s_wf[a];
#pragma unroll
                for (int o = 16; o; o >>= 1) sum += __shfl_xor_sync(0xffffffffu, sum, o);
                if (lane == 0) s_e[p] = sum + b_full[0];
            }
            __syncthreads();
            float m = -1e30f;
            if (tid < PP) m = s_e[tid];
#pragma unroll
            for (int o = 16; o; o >>= 1) m = fmaxf(m, __shfl_xor_sync(0xffffffffu, m, o));
            if (lane == 0) s_red[wid] = m;
            __syncthreads();
            float mx = s_red[0];
#pragma unroll
            for (int i = 1; i < 7; i++) mx = fmaxf(mx, s_red[i]);
            float ev = 0.f;
            if (tid < PP) ev = expf(s_e[tid] - mx);
            float sv = ev;
#pragma unroll
            for (int o = 16; o; o >>= 1) sv += __shfl_xor_sync(0xffffffffu, sv, o);
            __syncthreads();
            if (lane == 0) s_red[wid] = sv;
            __syncthreads();
            float tot = 0.f;
#pragma unroll
            for (int i = 0; i < 7; i++) tot += s_red[i];
            float inv = 1.f / tot;
            if (tid < PP) {
                float al = ev * inv;
                s_e[tid] = al;
                wout[tid] = al;
            }
            __syncthreads();
            int hq = tid & 63, pc2 = tid >> 6;   // 16-way pixel split
            const float4* fb4 = (const float4*)(g_feats + (size_t)b * PP * HH);
            float4 a0 = make_float4(0,0,0,0), a1 = make_float4(0,0,0,0);
            for (int p = pc2; p < PP; p += 16) {
                float al = s_e[p];
                float4 v0 = fb4[p*128 + hq*2];
                float4 v1 = fb4[p*128 + hq*2 + 1];
                a0.x = fmaf(al, v0.x, a0.x); a0.y = fmaf(al, v0.y, a0.y);
                a0.z = fmaf(al, v0.z, a0.z); a0.w = fmaf(al, v0.w, a0.w);
                a1.x = fmaf(al, v1.x, a1.x); a1.y = fmaf(al, v1.y, a1.y);
                a1.z = fmaf(al, v1.z, a1.z); a1.w = fmaf(al, v1.w, a1.w);
            }
            float* rb = rbuf + pc2*512 + hq*8;
            rb[0]=a0.x; rb[1]=a0.y; rb[2]=a0.z; rb[3]=a0.w;
            rb[4]=a1.x; rb[5]=a1.y; rb[6]=a1.z; rb[7]=a1.w;
            __syncthreads();
            for (int o = tid; o < 512; o += NTHR_R) {
                float s = 0.f;
#pragma unroll
                for (int q = 0; q < 16; q++) s += rbuf[q*512 + o];
                g_ctx[b*512 + o] = s;
            }
        }
        gridbar(nbar++);

        // ---- Phase C: gates_ctx (mma) + combine(g_gh, embg) + LSTM ----
        for (int pb = 0; pb < npb; pb++) {
            int b0 = pb*32;
            stage32(g_ctx, b0, smc + HT_OFF, tid);
            __syncthreads();
            gates_mma(htS, wihS, part, wid, lane);
            __syncthreads();
            for (int o = tid; o < 512; o += NTHR_R) {
                int m = o >> 4, n = o & 15;
                int b = b0 + m;
                int gr = 512*(n >> 2) + j*4 + (n & 3);
                float s = 0.f;
#pragma unroll
                for (int ks = 0; ks < 8; ks++) s += part[ks*512 + o];
                gh[b*16 + n] = s + __ldcg(&g_gh[(b*128 + j)*16 + n])
                             + g_embg[(size_t)(b*TT + t)*NG + gr];
            }
            __syncthreads();
        }
        if (tid < 256) {
            int b = tid >> 2, q = tid & 3;
            if (t < sdl[b]) {
                float gi = gh[b*16 + q];
                float gf = gh[b*16 + 4 + q];
                float gg = gh[b*16 + 8 + q];
                float go = gh[b*16 + 12 + q];
                float ig = 1.f / (1.f + expf(-gi));
                float fg = 1.f / (1.f + expf(-gf));
                float gv = tanhf(gg);
                float og = 1.f / (1.f + expf(-go));
                int kc = j*4 + q;
                float c_new = fg * g_c[b*512 + kc] + ig * gv;
                float h_new = og * tanhf(c_new);
                __nv_bfloat16 hh = __float2bfloat16(h_new);
                __nv_bfloat16 hl = __float2bfloat16(h_new - __bfloat162float(hh));
                g_hall2[(size_t)(b*TT + t)*1024 + kc]       = hh;
                g_hall2[(size_t)(b*TT + t)*1024 + 512 + kc] = hl;
                g_h[b*512 + kc] = h_new;
                g_c[b*512 + kc] = c_new;
            }
        }
        gridbar(nbar++);
    }
}

// ======================= launch =======================
extern "C" void kernel_launch(void* const* d_in, const int* in_sizes, int n_in,
                              void* d_out, int out_size) {
    const float* imf     = (const float*)d_in[0];
    const int*   caps    = (const int*)  d_in[1];
    const int*   caplens = (const int*)  d_in[2];
    const float* emb     = (const float*)d_in[3];
    const float* W_ih    = (const float*)d_in[4];
    const float* W_hh    = (const float*)d_in[5];
    const float* b_ih    = (const float*)d_in[6];
    const float* b_hh    = (const float*)d_in[7];
    const float* W_enc   = (const float*)d_in[8];
    const float* b_enc   = (const float*)d_in[9];
    const float* W_dec   = (const float*)d_in[10];
    const float* b_dec   = (const float*)d_in[11];
    const float* W_full  = (const float*)d_in[12];
    const float* b_full  = (const float*)d_in[13];
    const float* W_score = (const float*)d_in[14];
    const float* b_score = (const float*)d_in[15];
    float* out = (float*)d_out;

    cudaFuncSetAttribute(k_recur, cudaFuncAttributeMaxDynamicSharedMemorySize, SM_TOTAL);

    // 1: sort + caps/declen/sortind outputs
    k_sort<<<1, BB>>>(caplens, caps, out);
    // 2: fused gathers + bf16 hi/lo conversions + zeroing + init
    k_cvt_all<<<1024, 256>>>(imf, caps, emb, W_enc, W_ih, W_score, out);
    // 3: fused enc_att + G_emb tensor-core GEMMs
    k_gemm_pair<<<792, 256>>>(b_enc, b_ih, b_hh);
    // 4: persistent recurrence (1024 threads, phase-specialized)
    k_recur<<<NCTA, NTHR_R, SM_TOTAL>>>(W_dec, W_hh, W_ih, b_dec, W_full, b_full, out);
    // 5: scores GEMM
    k_gemm_scores<<<dim3((BB*TT + 127)/128, (VV + 127)/128), 256>>>(b_score, out);
}

// round 14
// speedup vs baseline: 1.9902x; 1.0449x over previous
#include <cuda_runtime.h>
#include <cuda_bf16.h>
#include <cstdint>
#include <math.h>

#define BB 64
#define PP 196
#define HH 512
#define EE 512
#define AA 512
#define VV 10000
#define MAXCAP 50
#define TT 49
#define NG 2048   // 4*H

// output layout (float32): scores (B,T,V), caps_s (B,50), decode_lengths (B,), weights (B,T,P), sort_ind (B,)
#define N_SCORES   (BB*TT*VV)
#define OFF_CAPS   (N_SCORES)
#define OFF_DECLEN (OFF_CAPS + BB*MAXCAP)
#define OFF_WEIGHTS (OFF_DECLEN + BB)
#define OFF_SORT   (OFF_WEIGHTS + BB*TT*PP)

#define NCTA 128
#define NTHR 256
#define NTHR_R 1024

// ======================= scratch =======================
__device__ float g_feats[BB*PP*HH];
__device__ float g_encatt[BB*PP*AA];
__device__ float g_embg[BB*TT*NG];
__device__ float g_c[BB*HH];
__device__ float g_att2[BB*AA];
__device__ float g_gh[BB*NG];          // gates_h: [b][slice 0..127][16]
__device__ int   g_sortidx[BB];
__device__ int   g_declen[BB];
__device__ int   g_nbact[TT];
__device__ int   g_act[BB*TT];
__device__ int   g_nact;
__device__ int   g_bars[160];

// h/ctx in MMA-native tile format: [pb 0..1][64KB tile: hi kt 0..15, lo kt 16..31, each 32r x 64B]
__device__ __align__(16) char g_h2[131072];
__device__ __align__(16) char g_ctx2[131072];

// bf16 hi/lo packed [rows][1024]: cols 0-511 hi, 512-1023 lo
__device__ __nv_bfloat16 g_feats2[BB*PP*1024];
__device__ __nv_bfloat16 g_embT2[BB*TT*1024];
__device__ __nv_bfloat16 g_hall2[BB*TT*1024];
__device__ __nv_bfloat16 g_Wenc2[AA*1024];
__device__ __nv_bfloat16 g_Wih2[NG*1024];
__device__ __nv_bfloat16 g_Wsc2[VV*1024];

// ======================= helpers =======================
__device__ __forceinline__ void mma16816(float* d, const uint32_t* a, const uint32_t* b) {
    asm volatile("mma.sync.aligned.m16n8k16.row.col.f32.bf16.bf16.f32 "
        "{%0,%1,%2,%3}, {%4,%5,%6,%7}, {%8,%9}, {%0,%1,%2,%3};"
        : "+f"(d[0]), "+f"(d[1]), "+f"(d[2]), "+f"(d[3])
        : "r"(a[0]), "r"(a[1]), "r"(a[2]), "r"(a[3]), "r"(b[0]), "r"(b[1]));
}
__device__ __forceinline__ void ldsm_x4(uint32_t* r, uint32_t saddr) {
    asm volatile("ldmatrix.sync.aligned.m8n8.x4.shared.b16 {%0,%1,%2,%3}, [%4];"
        : "=r"(r[0]), "=r"(r[1]), "=r"(r[2]), "=r"(r[3]) : "r"(saddr));
}
__device__ __forceinline__ void ldsm_x2(uint32_t* r, uint32_t saddr) {
    asm volatile("ldmatrix.sync.aligned.m8n8.x2.shared.b16 {%0,%1}, [%2];"
        : "=r"(r[0]), "=r"(r[1]) : "r"(saddr));
}
__device__ __forceinline__ uint32_t smem_u32(const void* p) {
    return (uint32_t)__cvta_generic_to_shared(p);
}
// store bf16x2 at (r, c even 0..31) in swizzled tile (64B rows, 16B-chunk XOR)
__device__ __forceinline__ void stsw2(char* s, int r, int c, uint32_t v) {
    int byte = r*64 + ((((c >> 3) ^ ((r >> 1) & 3))) << 4) + (c & 7)*2;
    *(uint32_t*)(s + byte) = v;
}
__device__ __forceinline__ void cvt_hilo2(float2 v, uint32_t& hp, uint32_t& lp) {
    __nv_bfloat16 h0 = __float2bfloat16(v.x), h1 = __float2bfloat16(v.y);
    float l0 = v.x - __bfloat162float(h0), l1 = v.y - __bfloat162float(h1);
    __nv_bfloat16 b0 = __float2bfloat16(l0), b1 = __float2bfloat16(l1);
    hp = (uint32_t)__bfloat16_as_ushort(h0) | ((uint32_t)__bfloat16_as_ushort(h1) << 16);
    lp = (uint32_t)__bfloat16_as_ushort(b0) | ((uint32_t)__bfloat16_as_ushort(b1) << 16);
}

// ======================= prep kernels =======================
__global__ void k_sort(const int* __restrict__ caplens, const int* __restrict__ caps,
                       float* __restrict__ out) {
    __shared__ int s_sort[BB];
    if (threadIdx.x == 0) {
        int cl[BB];
        for (int i = 0; i < BB; i++) cl[i] = caplens[i];
        int r = 0;
        for (int v = MAXCAP; v >= 0 && r < BB; v--)
            for (int i = 0; i < BB; i++)
                if (cl[i] == v) { g_sortidx[r] = i; s_sort[r] = i; r++; }
        int na = 0;
        int dls[BB];
        for (int b = 0; b < BB; b++) {
            int dl = cl[g_sortidx[b]] - 1;
            dls[b] = dl;
            g_declen[b] = dl;
            out[OFF_DECLEN + b] = (float)dl;
            out[OFF_SORT + b]   = (float)g_sortidx[b];
            for (int t = 0; t < dl; t++) g_act[na++] = b*TT + t;
        }
        g_nact = na;
        for (int t = 0; t < TT; t++) {
            int c = 0;
            for (int b = 0; b < BB; b++) if (dls[b] > t) c++;
            g_nbact[t] = c;
        }
    }
    __syncthreads();
    int b = threadIdx.x;
    int src = s_sort[b];
    for (int t = 0; t < MAXCAP; t++)
        out[OFF_CAPS + b*MAXCAP + t] = (float)caps[src*MAXCAP + t];
}

// fused gather + hi/lo conversion (pairwise) + zero + init
#define P0 (BB*PP*256)
#define P1 (BB*TT*256)
#define P2 (AA*256)
#define P3 (NG*256)
#define P4 (VV*256)
#define Z5 (N_SCORES/4)
#define Z6 (BB*TT*PP/4)
#define Z7 (BB*HH)
#define Z7B (2*131072/16)
#define Z8 160
__global__ void k_cvt_all(const float* __restrict__ imf, const int* __restrict__ caps,
                          const float* __restrict__ emb, const float* __restrict__ W_enc,
                          const float* __restrict__ W_ih, const float* __restrict__ W_score,
                          float* __restrict__ out)
{
    const int total = P0+P1+P2+P3+P4+Z5+Z6+Z7+Z7B+Z8;
    for (int i = blockIdx.x*blockDim.x + threadIdx.x; i < total; i += gridDim.x*blockDim.x) {
        int x = i;
        if (x < P0) {
            int r = x >> 8, c2 = x & 255, k = c2*2;
            int b = r / PP, p = r - b*PP;
            float2 v = *(const float2*)(imf + ((size_t)g_sortidx[b]*PP + p)*512 + k);
            *(float2*)(g_feats + (size_t)r*512 + k) = v;
            uint32_t hp, lp; cvt_hilo2(v, hp, lp);
            ((uint32_t*)g_feats2)[(size_t)r*512 + c2] = hp;
            ((uint32_t*)g_feats2)[(size_t)r*512 + 256 + c2] = lp;
            continue;
        }
        x -= P0;
        if (x < P1) {
            int r = x >> 8, c2 = x & 255, k = c2*2;
            int b = r / TT, t = r - b*TT;
            int tok = caps[g_sortidx[b]*MAXCAP + t];
            float2 v = *(const float2*)(emb + (size_t)tok*512 + k);
            uint32_t hp, lp; cvt_hilo2(v, hp, lp);
            ((uint32_t*)g_embT2)[(size_t)r*512 + c2] = hp;
            ((uint32_t*)g_embT2)[(size_t)r*512 + 256 + c2] = lp;
            continue;
        }
        x -= P1;
        if (x < P2) {
            int r = x >> 8, c2 = x & 255, k = c2*2;
            float2 v = *(const float2*)(W_enc + (size_t)r*512 + k);
            uint32_t hp, lp; cvt_hilo2(v, hp, lp);
            ((uint32_t*)g_Wenc2)[(size_t)r*512 + c2] = hp;
            ((uint32_t*)g_Wenc2)[(size_t)r*512 + 256 + c2] = lp;
            continue;
        }
        x -= P2;
        if (x < P3) {
            int r = x >> 8, c2 = x & 255, k = c2*2;
            float2 v = *(const float2*)(W_ih + (size_t)r*1024 + k);
            uint32_t hp, lp; cvt_hilo2(v, hp, lp);
            ((uint32_t*)g_Wih2)[(size_t)r*512 + c2] = hp;
            ((uint32_t*)g_Wih2)[(size_t)r*512 + 256 + c2] = lp;
            continue;
        }
        x -= P3;
        if (x < P4) {
            int r = x >> 8, c2 = x & 255, k = c2*2;
            float2 v = *(const float2*)(W_score + (size_t)r*512 + k);
            uint32_t hp, lp; cvt_hilo2(v, hp, lp);
            ((uint32_t*)g_Wsc2)[(size_t)r*512 + c2] = hp;
            ((uint32_t*)g_Wsc2)[(size_t)r*512 + 256 + c2] = lp;
            continue;
        }
        x -= P4;
        if (x < Z5) {
            ((float4*)out)[x] = make_float4(0.f, 0.f, 0.f, 0.f);
            continue;
        }
        x -= Z5;
        if (x < Z6) {
            ((float4*)(out + OFF_WEIGHTS))[x] = make_float4(0.f, 0.f, 0.f, 0.f);
            continue;
        }
        x -= Z6;
        if (x < Z7) { g_c[x] = 0.f; continue; }
        x -= Z7;
        if (x < Z7B) {
            uint4 z = make_uint4(0,0,0,0);
            if (x < 131072/16) ((uint4*)g_h2)[x] = z;
            else ((uint4*)g_ctx2)[x - 131072/16] = z;
            continue;
        }
        x -= Z7B;
        g_bars[x] = 0;
    }
}

// ======================= mma.sync bf16x3 GEMM body (ldmatrix + double buffer) ==========
__device__ __forceinline__ void hgemm_body(
    int bm, int bn,
    const __nv_bfloat16* __restrict__ A2, const __nv_bfloat16* __restrict__ B2,
    int M, int N, int ldc,
    const float* __restrict__ bias1, const float* __restrict__ bias2,
    float* __restrict__ C, const int* __restrict__ rowmap, int use_nact,
    __nv_bfloat16 (*As)[128*32], __nv_bfloat16 (*Bs)[128*32])
{
    int tid = threadIdx.x;
    int Ml = use_nact ? g_nact : M;
    if (bm*128 >= Ml) return;

    int lrow = tid >> 1;
    int lc0 = (tid & 1) * 2;
    int gm = bm*128 + lrow;
    const uint4* arow = nullptr;
    if (gm < Ml) { int r = rowmap ? rowmap[gm] : gm; arow = (const uint4*)(A2 + (size_t)r*1024); }
    int gn = bn*128 + lrow;
    const uint4* brow = (gn < N) ? (const uint4*)(B2 + (size_t)gn*1024) : nullptr;

    int swz = (lrow >> 1) & 3;
    uint4* aswp[2] = {(uint4*)(As[0] + lrow*32), (uint4*)(As[1] + lrow*32)};
    uint4* bswp[2] = {(uint4*)(Bs[0] + lrow*32), (uint4*)(Bs[1] + lrow*32)};
    int c0 = lc0 ^ swz, c1 = (lc0+1) ^ swz;

    int lane = tid & 31, wid = tid >> 5;
    int wm = (wid >> 2) * 64;
    int wn = (wid & 3) * 32;
    int gq = lane >> 2, tg = lane & 3;

    int rA = wm + (lane & 15);
    int swzA = (rA >> 1) & 3;
    int hiA = lane >> 4;
    int rB = wn + (lane & 7);
    int swzB = (rB >> 1) & 3;
    int hiB = (lane >> 3) & 1;
    uint32_t aS[2] = {smem_u32(As[0]) + rA*64, smem_u32(As[1]) + rA*64};
    uint32_t bS[2] = {smem_u32(Bs[0]) + rB*64, smem_u32(Bs[1]) + rB*64};

    float acc[4][4][4];
#pragma unroll
    for (int mt = 0; mt < 4; mt++)
#pragma unroll
        for (int nt = 0; nt < 4; nt++)
#pragma unroll
            for (int r = 0; r < 4; r++) acc[mt][nt][r] = 0.f;

    const uint4 z = make_uint4(0,0,0,0);
    const int kau4[3] = {0, 0, 64};
    const int kbu4[3] = {0, 64, 0};
    uint4 pa0 = arow ? arow[lc0]   : z;
    uint4 pa1 = arow ? arow[lc0+1] : z;
    uint4 pb0 = brow ? brow[lc0]   : z;
    uint4 pb1 = brow ? brow[lc0+1] : z;
    aswp[0][c0] = pa0; aswp[0][c1] = pa1;
    bswp[0][c0] = pb0; bswp[0][c1] = pb1;
    __syncthreads();

    for (int ci = 0; ci < 48; ci++) {
        int cur = ci & 1;
        if (ci + 1 < 48) {
            int term = (ci+1) >> 4, kc = (ci+1) & 15;
            int ab = kau4[term] + kc*4, bb = kbu4[term] + kc*4;
            pa0 = arow ? arow[ab + lc0]   : z;
            pa1 = arow ? arow[ab + lc0+1] : z;
            pb0 = brow ? brow[bb + lc0]   : z;
            pb1 = brow ? brow[bb + lc0+1] : z;
        }
#pragma unroll
        for (int kk = 0; kk < 2; kk++) {
            uint32_t cA = (uint32_t)(((2*kk + hiA) ^ swzA) << 4);
            uint32_t cB = (uint32_t)(((2*kk + hiB) ^ swzB) << 4);
            uint32_t afr[4][4];
#pragma unroll
            for (int mt = 0; mt < 4; mt++)
                ldsm_x4(afr[mt], aS[cur] + mt*1024 + cA);
            uint32_t bfr[4][2];
#pragma unroll
            for (int nt = 0; nt < 4; nt++)
                ldsm_x2(bfr[nt], bS[cur] + nt*512 + cB);
#pragma unroll
            for (int mt = 0; mt < 4; mt++)
#pragma unroll
                for (int nt = 0; nt < 4; nt++)
                    mma16816(acc[mt][nt], afr[mt], bfr[nt]);
        }
        if (ci + 1 < 48) {
            int nxt = cur ^ 1;
            aswp[nxt][c0] = pa0; aswp[nxt][c1] = pa1;
            bswp[nxt][c0] = pb0; bswp[nxt][c1] = pb1;
        }
        __syncthreads();
    }

#pragma unroll
    for (int mt = 0; mt < 4; mt++) {
        int m0 = bm*128 + wm + mt*16 + gq;
        int m1 = m0 + 8;
        size_t row0 = 0, row1 = 0;
        bool v0 = m0 < Ml, v1 = m1 < Ml;
        if (v0) row0 = (size_t)(rowmap ? rowmap[m0] : m0);
        if (v1) row1 = (size_t)(rowmap ? rowmap[m1] : m1);
#pragma unroll
        for (int nt = 0; nt < 4; nt++) {
            int col = bn*128 + wn + nt*8 + tg*2;
            if (col >= N) continue;
            float bx = bias1[col], by = bias1[col+1];
            if (bias2) { bx += bias2[col]; by += bias2[col+1]; }
            if (v0) {
                float2 o = make_float2(acc[mt][nt][0] + bx, acc[mt][nt][1] + by);
                *(float2*)(C + row0*(size_t)ldc + col) = o;
            }
            if (v1) {
                float2 o = make_float2(acc[mt][nt][2] + bx, acc[mt][nt][3] + by);
                *(float2*)(C + row1*(size_t)ldc + col) = o;
            }
        }
    }
}

__global__ __launch_bounds__(256)
void k_gemm_pair(const float* __restrict__ b_enc, const float* __restrict__ b_ih,
                 const float* __restrict__ b_hh)
{
    __shared__ __align__(16) __nv_bfloat16 As[2][128*32];
    __shared__ __align__(16) __nv_bfloat16 Bs[2][128*32];
    int idx = blockIdx.x;
    if (idx < 392) {
        hgemm_body(idx >> 2, idx & 3, g_feats2, g_Wenc2, BB*PP, AA, AA,
                   b_enc, nullptr, g_encatt, nullptr, 0, As, Bs);
    } else {
        idx -= 392;
        hgemm_body(idx >> 4, idx & 15, g_embT2, g_Wih2, BB*TT, NG, NG,
                   b_ih, b_hh, g_embg, g_act, 1, As, Bs);
    }
}

__global__ __launch_bounds__(256)
void k_gemm_scores(const float* __restrict__ b_score, float* __restrict__ out)
{
    __shared__ __align__(16) __nv_bfloat16 As[2][128*32];
    __shared__ __align__(16) __nv_bfloat16 Bs[2][128*32];
    hgemm_body(blockIdx.x, blockIdx.y, g_hall2, g_Wsc2, BB*TT, VV, VV,
               b_score, nullptr, out, g_act, 1, As, Bs);
}

// ======================= fused persistent recurrence (1024 threads) =======================
// smem byte offsets
#define WIHC_OFF 0
#define WDEC_OFF 32768
#define WHH_OFF  49152
#define HT_OFF   114688
#define PART_OFF 180224
#define GH_OFF   196608
#define SM_TOTAL 200704

// flat per-slot barrier (replay-safe), tight spin
__device__ __forceinline__ void gridbar(int slot) {
    __syncthreads();
    if (threadIdx.x == 0) {
        int* p = &g_bars[slot];
        asm volatile("red.release.gpu.global.add.s32 [%0], 1;" :: "l"(p) : "memory");
        int v;
        do {
            asm volatile("ld.acquire.gpu.global.s32 %0, [%1];" : "=r"(v) : "l"(p) : "memory");
        } while (v < NCTA);
    }
    __syncthreads();
}

// copy one 64KB tile (pb) from tile-format global to smem HT — pure 16B copies
__device__ __forceinline__ void copy32(const char* __restrict__ srcTiles, int pb,
                                       char* HTp, int tid) {
    const uint4* src = (const uint4*)(srcTiles + pb*65536);
    uint4* dst = (uint4*)HTp;
#pragma unroll
    for (int i = 0; i < 4; i++) {
        int o = tid + i*NTHR_R;
        dst[o] = __ldcg(src + o);
    }
}

// gates_ctx mma (32 warps): M=32, N=16 (slice j), K split 8 -> part[8][32][16]
__device__ __forceinline__ void gates_mma(uint32_t htA, uint32_t wbB, float* part,
                                          int wid, int lane) {
    int gq = lane >> 2, tg = lane & 3;
    int mh = (wid & 1)*16, nh = ((wid >> 1) & 1)*8, ks = wid >> 2;   // ks 0..7
    int rA = mh + (lane & 15);
    int swzA = (rA >> 1) & 3;
    int hiA = lane >> 4;
    int rB = nh + (lane & 7);
    int swzB = (rB >> 1) & 3;
    int hiB = (lane >> 3) & 1;
    uint32_t aL = htA + rA*64;
    uint32_t bL = wbB + rB*64;
    float acc[4] = {0.f, 0.f, 0.f, 0.f};
    for (int kt = ks*2; kt < ks*2 + 2; kt++) {
        uint32_t ah = aL + kt*2048;
        uint32_t bh = bL + kt*1024;
#pragma unroll
        for (int kk = 0; kk < 2; kk++) {
            uint32_t cA = (uint32_t)(((2*kk + hiA) ^ swzA) << 4);
            uint32_t cB = (uint32_t)(((2*kk + hiB) ^ swzB) << 4);
            uint32_t Ah[4], Al[4], Bh[2], Bl[2];
            ldsm_x4(Ah, ah + cA);
            ldsm_x4(Al, ah + 32768 + cA);
            ldsm_x2(Bh, bh + cB);
            ldsm_x2(Bl, bh + 16384 + cB);
            mma16816(acc, Ah, Bh);
            mma16816(acc, Ah, Bl);
            mma16816(acc, Al, Bh);
        }
    }
    int m0 = mh + gq, n0 = nh + tg*2;
    part[ks*512 + m0*16 + n0]       = acc[0];
    part[ks*512 + m0*16 + n0+1]     = acc[1];
    part[ks*512 + (m0+8)*16 + n0]   = acc[2];
    part[ks*512 + (m0+8)*16 + n0+1] = acc[3];
}

// gates_h mma for 2 slices (32 warps): M=32, N=32 rows, K split 4 -> part[4][32][32]
__device__ __forceinline__ void gates_mma32(uint32_t htA, uint32_t whB, float* part,
                                            int wid, int lane) {
    int gq = lane >> 2, tg = lane & 3;
    int mh = (wid & 1)*16, nh = ((wid >> 1) & 3)*8, ks = wid >> 3;   // ks 0..3
    int rA = mh + (lane & 15);
    int swzA = (rA >> 1) & 3;
    int hiA = lane >> 4;
    int rB = nh + (lane & 7);
    int swzB = (rB >> 1) & 3;
    int hiB = (lane >> 3) & 1;
    uint32_t aL = htA + rA*64;
    uint32_t bL = whB + rB*64;
    float acc[4] = {0.f, 0.f, 0.f, 0.f};
    for (int kt = ks*4; kt < ks*4 + 4; kt++) {
        uint32_t ah = aL + kt*2048;
        uint32_t bh = bL + kt*2048;
#pragma unroll
        for (int kk = 0; kk < 2; kk++) {
            uint32_t cA = (uint32_t)(((2*kk + hiA) ^ swzA) << 4);
            uint32_t cB = (uint32_t)(((2*kk + hiB) ^ swzB) << 4);
            uint32_t Ah[4], Al[4], Bh[2], Bl[2];
            ldsm_x4(Ah, ah + cA);
            ldsm_x4(Al, ah + 32768 + cA);
            ldsm_x2(Bh, bh + cB);
            ldsm_x2(Bl, bh + 32768 + cB);
            mma16816(acc, Ah, Bh);
            mma16816(acc, Ah, Bl);
            mma16816(acc, Al, Bh);
        }
    }
    int m0 = mh + gq, n0 = nh + tg*2;
    part[ks*1024 + m0*32 + n0]       = acc[0];
    part[ks*1024 + m0*32 + n0+1]     = acc[1];
    part[ks*1024 + (m0+8)*32 + n0]   = acc[2];
    part[ks*1024 + (m0+8)*32 + n0+1] = acc[3];
}

// att2 mma (32 warps): M=32, N=8 (4 real + 4 zero), K split 16 -> part2[16][32][8]
__device__ __forceinline__ void att2_mma(uint32_t htA, uint32_t wdB, float* part2,
                                         int wid, int lane) {
    int gq = lane >> 2, tg = lane & 3;
    int mh = (wid & 1)*16, ks = wid >> 1;   // ks 0..15
    int rA = mh + (lane & 15);
    int swzA = (rA >> 1) & 3;
    int hiA = lane >> 4;
    int rB = lane & 7;
    int swzB = (rB >> 1) & 3;
    int hiB = (lane >> 3) & 1;
    uint32_t aL = htA + rA*64;
    uint32_t bL = wdB + rB*64;
    float acc[4] = {0.f, 0.f, 0.f, 0.f};
    {
        int kt = ks;
        uint32_t ah = aL + kt*2048;
        uint32_t bh = bL + kt*512;
#pragma unroll
        for (int kk = 0; kk < 2; kk++) {
            uint32_t cA = (uint32_t)(((2*kk + hiA) ^ swzA) << 4);
            uint32_t cB = (uint32_t)(((2*kk + hiB) ^ swzB) << 4);
            uint32_t Ah[4], Al[4], Bh[2], Bl[2];
            ldsm_x4(Ah, ah + cA);
            ldsm_x4(Al, ah + 32768 + cA);
            ldsm_x2(Bh, bh + cB);
            ldsm_x2(Bl, bh + 8192 + cB);
            mma16816(acc, Ah, Bh);
            mma16816(acc, Ah, Bl);
            mma16816(acc, Al, Bh);
        }
    }
    int m0 = mh + gq, n0 = tg*2;
    part2[ks*256 + m0*8 + n0]       = acc[0];
    part2[ks*256 + m0*8 + n0+1]     = acc[1];
    part2[ks*256 + (m0+8)*8 + n0]   = acc[2];
    part2[ks*256 + (m0+8)*8 + n0+1] = acc[3];
}

__global__ __launch_bounds__(NTHR_R)
void k_recur(const float* __restrict__ W_dec, const float* __restrict__ W_hh,
             const float* __restrict__ W_ih,
             const float* __restrict__ b_dec, const float* __restrict__ W_full,
             const float* __restrict__ b_full, float* __restrict__ out)
{
    extern __shared__ float sm[];
    char* smc = (char*)sm;
    __shared__ int sdl[BB];
    __shared__ int snb[TT];
    int tid = threadIdx.x, lane = tid & 31, wid = tid >> 5;
    int j = blockIdx.x;

    if (tid < BB) sdl[tid] = g_declen[tid];
    if (tid >= 64 && tid < 64 + TT) snb[tid - 64] = g_nbact[tid - 64];

    // WIHC slice j + WDEC slice j (all CTAs)
    for (int i = tid; i < 16*256; i += NTHR_R) {
        int r = i >> 8, kp = i & 255, k = kp*2;
        int gr = 512*(r >> 2) + j*4 + (r & 3);
        float2 w2 = *(const float2*)(W_ih + (size_t)gr*1024 + 512 + k);
        uint32_t hp, lp;
        int kt = k >> 5, c = k & 31;
        cvt_hilo2(w2, hp, lp);
        stsw2(smc + WIHC_OFF + kt*1024, r, c, hp);
        stsw2(smc + WIHC_OFF + (16+kt)*1024, r, c, lp);
    }
    for (int i = tid; i < 8*256; i += NTHR_R) {
        int r = i >> 8, kp = i & 255, k = kp*2;
        float2 w = (r < 4) ? *(const float2*)(W_dec + (size_t)(j*4+r)*512 + k)
                           : make_float2(0.f, 0.f);
        uint32_t hp, lp;
        cvt_hilo2(w, hp, lp);
        int kt = k >> 5, c = k & 31;
        stsw2(smc + WDEC_OFF + kt*512, r, c, hp);
        stsw2(smc + WDEC_OFF + (16+kt)*512, r, c, lp);
    }
    // WHH 2 slices (CTAs 64..127 only)
    if (j >= 64) {
        int s0 = (j - 64)*2;
        for (int i = tid; i < 32*256; i += NTHR_R) {
            int r = i >> 8, kp = i & 255, k = kp*2;
            int s = s0 + (r >> 4), rr = r & 15;
            int gr = 512*(rr >> 2) + s*4 + (rr & 3);
            float2 w1 = *(const float2*)(W_hh + (size_t)gr*512 + k);
            uint32_t hp, lp;
            int kt = k >> 5, c = k & 31;
            cvt_hilo2(w1, hp, lp);
            stsw2(smc + WHH_OFF + kt*2048, r, c, hp);
            stsw2(smc + WHH_OFF + 32768 + kt*2048, r, c, lp);
        }
    }
    __syncthreads();

    float* part  = (float*)(smc + PART_OFF);
    float* part2 = part;
    float* gh    = (float*)(smc + GH_OFF);
    uint32_t htS  = smem_u32(smc + HT_OFF);
    uint32_t wihS = smem_u32(smc + WIHC_OFF);
    uint32_t whhS = smem_u32(smc + WHH_OFF);
    uint32_t wdS  = smem_u32(smc + WDEC_OFF);

    int nbar = 0;
    for (int t = 0; t < TT; t++) {
        int npb = (snb[t] + 31) >> 5;
        // ---- Phase A: att2 only ----
        for (int pb = 0; pb < npb; pb++) {
            int b0 = pb*32;
            copy32(g_h2, pb, smc + HT_OFF, tid);
            __syncthreads();
            att2_mma(htS, wdS, part2, wid, lane);
            __syncthreads();
            if (tid < 128) {
                int m = tid >> 2, q = tid & 3;
                float s = 0.f;
#pragma unroll
                for (int ks = 0; ks < 16; ks++) s += part2[ks*256 + m*8 + q];
                g_att2[(b0+m)*512 + j*4 + q] = s;
            }
            __syncthreads();
        }
        gridbar(nbar++);

        // ---- Phase B: attention (CTAs 0..63) || gates_h (CTAs 64..127) ----
        if (j >= 64) {
            int s0 = (j - 64)*2;
            for (int pb = 0; pb < npb; pb++) {
                int b0 = pb*32;
                copy32(g_h2, pb, smc + HT_OFF, tid);
                __syncthreads();
                gates_mma32(htS, whhS, part, wid, lane);
                __syncthreads();
                {
                    int o = tid;
                    int m = o >> 5, n = o & 31;
                    float s = part[o] + part[1024 + o] + part[2048 + o] + part[3072 + o];
                    int sl = s0 + (n >> 4), rr = n & 15;
                    g_gh[((b0 + m)*128 + sl)*16 + rr] = s;
                }
                __syncthreads();
            }
        } else if (t < sdl[j]) {
            int b = j;
            float* wout = out + OFF_WEIGHTS + (size_t)(b*TT + t)*PP;
            float* att = (float*)(smc + HT_OFF);
            float* s_att2 = att;
            float* s_wf   = att + 512;
            float* s_e    = att + 1024;
            float* s_red  = att + 1248;
            float* rbuf   = att + 1280;
            for (int a = tid; a < AA; a += NTHR_R) {
                s_att2[a] = __ldcg(&g_att2[b*512 + a]) + b_dec[a];
                s_wf[a] = W_full[a];
            }
            __syncthreads();
            const float* ea = g_encatt + (size_t)b * PP * AA;
            for (int p = wid; p < PP; p += 32) {
                const float* row = ea + (size_t)p * AA;
                float sum = 0.f;
                for (int a = lane; a < AA; a += 32)
                    sum += fmaxf(row[a] + s_att2[a], 0.f) * s_wf[a];
#pragma unroll
                for (int o = 16; o; o >>= 1) sum += __shfl_xor_sync(0xffffffffu, sum, o);
                if (lane == 0) s_e[p] = sum + b_full[0];
            }
            __syncthreads();
            float m = -1e30f;
            if (tid < PP) m = s_e[tid];
#pragma unroll
            for (int o = 16; o; o >>= 1) m = fmaxf(m, __shfl_xor_sync(0xffffffffu, m, o));
            if (lane == 0) s_red[wid] = m;
            __syncthreads();
            float mx = s_red[0];
#pragma unroll
            for (int i = 1; i < 7; i++) mx = fmaxf(mx, s_red[i]);
            float ev = 0.f;
            if (tid < PP) ev = expf(s_e[tid] - mx);
            float sv = ev;
#pragma unroll
            for (int o = 16; o; o >>= 1) sv += __shfl_xor_sync(0xffffffffu, sv, o);
            __syncthreads();
            if (lane == 0) s_red[wid] = sv;
            __syncthreads();
            float tot = 0.f;
#pragma unroll
            for (int i = 0; i < 7; i++) tot += s_red[i];
            float inv = 1.f / tot;
            if (tid < PP) {
                float al = ev * inv;
                s_e[tid] = al;
                wout[tid] = al;
            }
            __syncthreads();
            int hq = tid & 63, pc2 = tid >> 6;
            const float4* fb4 = (const float4*)(g_feats + (size_t)b * PP * HH);
            float4 a0 = make_float4(0,0,0,0), a1 = make_float4(0,0,0,0);
            for (int p = pc2; p < PP; p += 16) {
                float al = s_e[p];
                float4 v0 = fb4[p*128 + hq*2];
                float4 v1 = fb4[p*128 + hq*2 + 1];
                a0.x = fmaf(al, v0.x, a0.x); a0.y = fmaf(al, v0.y, a0.y);
                a0.z = fmaf(al, v0.z, a0.z); a0.w = fmaf(al, v0.w, a0.w);
                a1.x = fmaf(al, v1.x, a1.x); a1.y = fmaf(al, v1.y, a1.y);
                a1.z = fmaf(al, v1.z, a1.z); a1.w = fmaf(al, v1.w, a1.w);
            }
            float* rb = rbuf + pc2*512 + hq*8;
            rb[0]=a0.x; rb[1]=a0.y; rb[2]=a0.z; rb[3]=a0.w;
            rb[4]=a1.x; rb[5]=a1.y; rb[6]=a1.z; rb[7]=a1.w;
            __syncthreads();
            // ctx -> g_ctx2 tile format (convert once here)
            if (tid < 256) {
                int o = tid*2;
                float s0v = 0.f, s1v = 0.f;
#pragma unroll
                for (int q = 0; q < 16; q++) {
                    s0v += rbuf[q*512 + o];
                    s1v += rbuf[q*512 + o + 1];
                }
                uint32_t hp, lp;
                cvt_hilo2(make_float2(s0v, s1v), hp, lp);
                int pbb = b >> 5, r = b & 31, kt = o >> 5, c = o & 31;
                char* base = g_ctx2 + pbb*65536;
                stsw2(base + kt*2048, r, c, hp);
                stsw2(base + (16+kt)*2048, r, c, lp);
            }
        }
        gridbar(nbar++);

        // ---- Phase C: gates_ctx (mma) + combine(g_gh, embg) + LSTM ----
        for (int pb = 0; pb < npb; pb++) {
            int b0 = pb*32;
            copy32(g_ctx2, pb, smc + HT_OFF, tid);
            __syncthreads();
            gates_mma(htS, wihS, part, wid, lane);
            __syncthreads();
            for (int o = tid; o < 512; o += NTHR_R) {
                int m = o >> 4, n = o & 15;
                int b = b0 + m;
                int gr = 512*(n >> 2) + j*4 + (n & 3);
                float s = 0.f;
#pragma unroll
                for (int ks = 0; ks < 8; ks++) s += part[ks*512 + o];
                gh[b*16 + n] = s + __ldcg(&g_gh[(b*128 + j)*16 + n])
                             + g_embg[(size_t)(b*TT + t)*NG + gr];
            }
            __syncthreads();
        }
        if (tid < 128) {
            int b = tid >> 1, qp = tid & 1;
            if (t < sdl[b]) {
                float hn[2];
#pragma unroll
                for (int e = 0; e < 2; e++) {
                    int q = qp*2 + e;
                    float gi = gh[b*16 + q];
                    float gf = gh[b*16 + 4 + q];
                    float gg = gh[b*16 + 8 + q];
                    float go = gh[b*16 + 12 + q];
                    float ig = 1.f / (1.f + expf(-gi));
                    float fg = 1.f / (1.f + expf(-gf));
                    float gv = tanhf(gg);
                    float og = 1.f / (1.f + expf(-go));
                    int kc = j*4 + q;
                    float c_new = fg * g_c[b*512 + kc] + ig * gv;
                    hn[e] = og * tanhf(c_new);
                    g_c[b*512 + kc] = c_new;
                }
                int kc0 = j*4 + qp*2;
                uint32_t hp, lp;
                cvt_hilo2(make_float2(hn[0], hn[1]), hp, lp);
                // h2 tile format
                int pbb = b >> 5, r = b & 31, kt = kc0 >> 5, c = kc0 & 31;
                char* base = g_h2 + pbb*65536;
                stsw2(base + kt*2048, r, c, hp);
                stsw2(base + (16+kt)*2048, r, c, lp);
                // hall2 standard layout
                *(uint32_t*)&g_hall2[(size_t)(b*TT + t)*1024 + kc0]       = hp;
                *(uint32_t*)&g_hall2[(size_t)(b*TT + t)*1024 + 512 + kc0] = lp;
            }
        }
        gridbar(nbar++);
    }
}

// ======================= launch =======================
extern "C" void kernel_launch(void* const* d_in, const int* in_sizes, int n_in,
                              void* d_out, int out_size) {
    const float* imf     = (const float*)d_in[0];
    const int*   caps    = (const int*)  d_in[1];
    const int*   caplens = (const int*)  d_in[2];
    const float* emb     = (const float*)d_in[3];
    const float* W_ih    = (const float*)d_in[4];
    const float* W_hh    = (const float*)d_in[5];
    const float* b_ih    = (const float*)d_in[6];
    const float* b_hh    = (const float*)d_in[7];
    const float* W_enc   = (const float*)d_in[8];
    const float* b_enc   = (const float*)d_in[9];
    const float* W_dec   = (const float*)d_in[10];
    const float* b_dec   = (const float*)d_in[11];
    const float* W_full  = (const float*)d_in[12];
    const float* b_full  = (const float*)d_in[13];
    const float* W_score = (const float*)d_in[14];
    const float* b_score = (const float*)d_in[15];
    float* out = (float*)d_out;

    cudaFuncSetAttribute(k_recur, cudaFuncAttributeMaxDynamicSharedMemorySize, SM_TOTAL);

    // 1: sort + caps/declen/sortind outputs
    k_sort<<<1, BB>>>(caplens, caps, out);
    // 2: fused gathers + bf16 hi/lo conversions + zeroing + init
    k_cvt_all<<<1024, 256>>>(imf, caps, emb, W_enc, W_ih, W_score, out);
    // 3: fused enc_att + G_emb tensor-core GEMMs
    k_gemm_pair<<<792, 256>>>(b_enc, b_ih, b_hh);
    // 4: persistent recurrence (1024 threads, tile-format state)
    k_recur<<<NCTA, NTHR_R, SM_TOTAL>>>(W_dec, W_hh, W_ih, b_dec, W_full, b_full, out);
    // 5: scores GEMM
    k_gemm_scores<<<dim3((BB*TT + 127)/128, (VV + 127)/128), 256>>>(b_score, out);
}

// round 15
// speedup vs baseline: 2.0188x; 1.0144x over previous
#include <cuda_runtime.h>
#include <cuda_bf16.h>
#include <cstdint>
#include <math.h>

#define BB 64
#define PP 196
#define HH 512
#define EE 512
#define AA 512
#define VV 10000
#define MAXCAP 50
#define TT 49
#define NG 2048   // 4*H

// output layout (float32): scores (B,T,V), caps_s (B,50), decode_lengths (B,), weights (B,T,P), sort_ind (B,)
#define N_SCORES   (BB*TT*VV)
#define OFF_CAPS   (N_SCORES)
#define OFF_DECLEN (OFF_CAPS + BB*MAXCAP)
#define OFF_WEIGHTS (OFF_DECLEN + BB)
#define OFF_SORT   (OFF_WEIGHTS + BB*TT*PP)

#define NCTA 128
#define NTHR 256
#define NTHR_R 1024

// ======================= scratch =======================
__device__ float g_feats[BB*PP*HH];
__device__ float g_encatt[BB*PP*AA];
__device__ float g_embg[BB*TT*NG];
__device__ float g_c[BB*HH];
__device__ float g_att2[BB*AA];
__device__ float g_gh[BB*NG];          // gates_h: [b][slice 0..127][16]
__device__ int   g_sortidx[BB];
__device__ int   g_declen[BB];
__device__ int   g_nbact[TT];
__device__ int   g_act[BB*TT];
__device__ int   g_nact;
__device__ int   g_bars[160];

// h/ctx in MMA-native tile format: [pb 0..1][64KB tile: hi kt 0..15, lo kt 16..31, each 32r x 64B]
__device__ __align__(16) char g_h2[131072];
__device__ __align__(16) char g_ctx2[131072];

// bf16 hi/lo packed [rows][1024]: cols 0-511 hi, 512-1023 lo
__device__ __nv_bfloat16 g_feats2[BB*PP*1024];
__device__ __nv_bfloat16 g_embT2[BB*TT*1024];
__device__ __nv_bfloat16 g_hall2[BB*TT*1024];
__device__ __nv_bfloat16 g_Wenc2[AA*1024];
__device__ __nv_bfloat16 g_Wih2[NG*1024];
__device__ __nv_bfloat16 g_Wsc2[VV*1024];

// ======================= helpers =======================
__device__ __forceinline__ void mma16816(float* d, const uint32_t* a, const uint32_t* b) {
    asm volatile("mma.sync.aligned.m16n8k16.row.col.f32.bf16.bf16.f32 "
        "{%0,%1,%2,%3}, {%4,%5,%6,%7}, {%8,%9}, {%0,%1,%2,%3};"
        : "+f"(d[0]), "+f"(d[1]), "+f"(d[2]), "+f"(d[3])
        : "r"(a[0]), "r"(a[1]), "r"(a[2]), "r"(a[3]), "r"(b[0]), "r"(b[1]));
}
__device__ __forceinline__ void ldsm_x4(uint32_t* r, uint32_t saddr) {
    asm volatile("ldmatrix.sync.aligned.m8n8.x4.shared.b16 {%0,%1,%2,%3}, [%4];"
        : "=r"(r[0]), "=r"(r[1]), "=r"(r[2]), "=r"(r[3]) : "r"(saddr));
}
__device__ __forceinline__ void ldsm_x2(uint32_t* r, uint32_t saddr) {
    asm volatile("ldmatrix.sync.aligned.m8n8.x2.shared.b16 {%0,%1}, [%2];"
        : "=r"(r[0]), "=r"(r[1]) : "r"(saddr));
}
__device__ __forceinline__ uint32_t smem_u32(const void* p) {
    return (uint32_t)__cvta_generic_to_shared(p);
}
// store bf16x2 at (r, c even 0..31) in swizzled tile (64B rows, 16B-chunk XOR)
__device__ __forceinline__ void stsw2(char* s, int r, int c, uint32_t v) {
    int byte = r*64 + ((((c >> 3) ^ ((r >> 1) & 3))) << 4) + (c & 7)*2;
    *(uint32_t*)(s + byte) = v;
}
__device__ __forceinline__ void cvt_hilo2(float2 v, uint32_t& hp, uint32_t& lp) {
    __nv_bfloat16 h0 = __float2bfloat16(v.x), h1 = __float2bfloat16(v.y);
    float l0 = v.x - __bfloat162float(h0), l1 = v.y - __bfloat162float(h1);
    __nv_bfloat16 b0 = __float2bfloat16(l0), b1 = __float2bfloat16(l1);
    hp = (uint32_t)__bfloat16_as_ushort(h0) | ((uint32_t)__bfloat16_as_ushort(h1) << 16);
    lp = (uint32_t)__bfloat16_as_ushort(b0) | ((uint32_t)__bfloat16_as_ushort(b1) << 16);
}

// ======================= prep kernels =======================
__global__ void k_sort(const int* __restrict__ caplens, const int* __restrict__ caps,
                       float* __restrict__ out) {
    __shared__ int s_sort[BB];
    if (threadIdx.x == 0) {
        int cl[BB];
        for (int i = 0; i < BB; i++) cl[i] = caplens[i];
        int r = 0;
        for (int v = MAXCAP; v >= 0 && r < BB; v--)
            for (int i = 0; i < BB; i++)
                if (cl[i] == v) { g_sortidx[r] = i; s_sort[r] = i; r++; }
        int na = 0;
        int dls[BB];
        for (int b = 0; b < BB; b++) {
            int dl = cl[g_sortidx[b]] - 1;
            dls[b] = dl;
            g_declen[b] = dl;
            out[OFF_DECLEN + b] = (float)dl;
            out[OFF_SORT + b]   = (float)g_sortidx[b];
            for (int t = 0; t < dl; t++) g_act[na++] = b*TT + t;
        }
        g_nact = na;
        for (int t = 0; t < TT; t++) {
            int c = 0;
            for (int b = 0; b < BB; b++) if (dls[b] > t) c++;
            g_nbact[t] = c;
        }
    }
    __syncthreads();
    int b = threadIdx.x;
    int src = s_sort[b];
    for (int t = 0; t < MAXCAP; t++)
        out[OFF_CAPS + b*MAXCAP + t] = (float)caps[src*MAXCAP + t];
}

// fused gather + hi/lo conversion (pairwise) + zero + init
#define P0 (BB*PP*256)
#define P1 (BB*TT*256)
#define P2 (AA*256)
#define P3 (NG*256)
#define P4 (VV*256)
#define Z5 (N_SCORES/4)
#define Z6 (BB*TT*PP/4)
#define Z7 (BB*HH)
#define Z7B (2*131072/16)
#define Z8 160
__global__ void k_cvt_all(const float* __restrict__ imf, const int* __restrict__ caps,
                          const float* __restrict__ emb, const float* __restrict__ W_enc,
                          const float* __restrict__ W_ih, const float* __restrict__ W_score,
                          float* __restrict__ out)
{
    const int total = P0+P1+P2+P3+P4+Z5+Z6+Z7+Z7B+Z8;
    for (int i = blockIdx.x*blockDim.x + threadIdx.x; i < total; i += gridDim.x*blockDim.x) {
        int x = i;
        if (x < P0) {
            int r = x >> 8, c2 = x & 255, k = c2*2;
            int b = r / PP, p = r - b*PP;
            float2 v = *(const float2*)(imf + ((size_t)g_sortidx[b]*PP + p)*512 + k);
            *(float2*)(g_feats + (size_t)r*512 + k) = v;
            uint32_t hp, lp; cvt_hilo2(v, hp, lp);
            ((uint32_t*)g_feats2)[(size_t)r*512 + c2] = hp;
            ((uint32_t*)g_feats2)[(size_t)r*512 + 256 + c2] = lp;
            continue;
        }
        x -= P0;
        if (x < P1) {
            int r = x >> 8, c2 = x & 255, k = c2*2;
            int b = r / TT, t = r - b*TT;
            int tok = caps[g_sortidx[b]*MAXCAP + t];
            float2 v = *(const float2*)(emb + (size_t)tok*512 + k);
            uint32_t hp, lp; cvt_hilo2(v, hp, lp);
            ((uint32_t*)g_embT2)[(size_t)r*512 + c2] = hp;
            ((uint32_t*)g_embT2)[(size_t)r*512 + 256 + c2] = lp;
            continue;
        }
        x -= P1;
        if (x < P2) {
            int r = x >> 8, c2 = x & 255, k = c2*2;
            float2 v = *(const float2*)(W_enc + (size_t)r*512 + k);
            uint32_t hp, lp; cvt_hilo2(v, hp, lp);
            ((uint32_t*)g_Wenc2)[(size_t)r*512 + c2] = hp;
            ((uint32_t*)g_Wenc2)[(size_t)r*512 + 256 + c2] = lp;
            continue;
        }
        x -= P2;
        if (x < P3) {
            int r = x >> 8, c2 = x & 255, k = c2*2;
            float2 v = *(const float2*)(W_ih + (size_t)r*1024 + k);
            uint32_t hp, lp; cvt_hilo2(v, hp, lp);
            ((uint32_t*)g_Wih2)[(size_t)r*512 + c2] = hp;
            ((uint32_t*)g_Wih2)[(size_t)r*512 + 256 + c2] = lp;
            continue;
        }
        x -= P3;
        if (x < P4) {
            int r = x >> 8, c2 = x & 255, k = c2*2;
            float2 v = *(const float2*)(W_score + (size_t)r*512 + k);
            uint32_t hp, lp; cvt_hilo2(v, hp, lp);
            ((uint32_t*)g_Wsc2)[(size_t)r*512 + c2] = hp;
            ((uint32_t*)g_Wsc2)[(size_t)r*512 + 256 + c2] = lp;
            continue;
        }
        x -= P4;
        if (x < Z5) {
            ((float4*)out)[x] = make_float4(0.f, 0.f, 0.f, 0.f);
            continue;
        }
        x -= Z5;
        if (x < Z6) {
            ((float4*)(out + OFF_WEIGHTS))[x] = make_float4(0.f, 0.f, 0.f, 0.f);
            continue;
        }
        x -= Z6;
        if (x < Z7) { g_c[x] = 0.f; continue; }
        x -= Z7;
        if (x < Z7B) {
            uint4 z = make_uint4(0,0,0,0);
            if (x < 131072/16) ((uint4*)g_h2)[x] = z;
            else ((uint4*)g_ctx2)[x - 131072/16] = z;
            continue;
        }
        x -= Z7B;
        g_bars[x] = 0;
    }
}

// ======================= mma.sync bf16x3 GEMM body (ldmatrix + double buffer) ==========
__device__ __forceinline__ void hgemm_body(
    int bm, int bn,
    const __nv_bfloat16* __restrict__ A2, const __nv_bfloat16* __restrict__ B2,
    int M, int N, int ldc,
    const float* __restrict__ bias1, const float* __restrict__ bias2,
    float* __restrict__ C, const int* __restrict__ rowmap, int use_nact,
    __nv_bfloat16 (*As)[128*32], __nv_bfloat16 (*Bs)[128*32])
{
    int tid = threadIdx.x;
    int Ml = use_nact ? g_nact : M;
    if (bm*128 >= Ml) return;

    int lrow = tid >> 1;
    int lc0 = (tid & 1) * 2;
    int gm = bm*128 + lrow;
    const uint4* arow = nullptr;
    if (gm < Ml) { int r = rowmap ? rowmap[gm] : gm; arow = (const uint4*)(A2 + (size_t)r*1024); }
    int gn = bn*128 + lrow;
    const uint4* brow = (gn < N) ? (const uint4*)(B2 + (size_t)gn*1024) : nullptr;

    int swz = (lrow >> 1) & 3;
    uint4* aswp[2] = {(uint4*)(As[0] + lrow*32), (uint4*)(As[1] + lrow*32)};
    uint4* bswp[2] = {(uint4*)(Bs[0] + lrow*32), (uint4*)(Bs[1] + lrow*32)};
    int c0 = lc0 ^ swz, c1 = (lc0+1) ^ swz;

    int lane = tid & 31, wid = tid >> 5;
    int wm = (wid >> 2) * 64;
    int wn = (wid & 3) * 32;
    int gq = lane >> 2, tg = lane & 3;

    int rA = wm + (lane & 15);
    int swzA = (rA >> 1) & 3;
    int hiA = lane >> 4;
    int rB = wn + (lane & 7);
    int swzB = (rB >> 1) & 3;
    int hiB = (lane >> 3) & 1;
    uint32_t aS[2] = {smem_u32(As[0]) + rA*64, smem_u32(As[1]) + rA*64};
    uint32_t bS[2] = {smem_u32(Bs[0]) + rB*64, smem_u32(Bs[1]) + rB*64};

    float acc[4][4][4];
#pragma unroll
    for (int mt = 0; mt < 4; mt++)
#pragma unroll
        for (int nt = 0; nt < 4; nt++)
#pragma unroll
            for (int r = 0; r < 4; r++) acc[mt][nt][r] = 0.f;

    const uint4 z = make_uint4(0,0,0,0);
    const int kau4[3] = {0, 0, 64};
    const int kbu4[3] = {0, 64, 0};
    uint4 pa0 = arow ? arow[lc0]   : z;
    uint4 pa1 = arow ? arow[lc0+1] : z;
    uint4 pb0 = brow ? brow[lc0]   : z;
    uint4 pb1 = brow ? brow[lc0+1] : z;
    aswp[0][c0] = pa0; aswp[0][c1] = pa1;
    bswp[0][c0] = pb0; bswp[0][c1] = pb1;
    __syncthreads();

    for (int ci = 0; ci < 48; ci++) {
        int cur = ci & 1;
        if (ci + 1 < 48) {
            int term = (ci+1) >> 4, kc = (ci+1) & 15;
            int ab = kau4[term] + kc*4, bb = kbu4[term] + kc*4;
            pa0 = arow ? arow[ab + lc0]   : z;
            pa1 = arow ? arow[ab + lc0+1] : z;
            pb0 = brow ? brow[bb + lc0]   : z;
            pb1 = brow ? brow[bb + lc0+1] : z;
        }
#pragma unroll
        for (int kk = 0; kk < 2; kk++) {
            uint32_t cA = (uint32_t)(((2*kk + hiA) ^ swzA) << 4);
            uint32_t cB = (uint32_t)(((2*kk + hiB) ^ swzB) << 4);
            uint32_t afr[4][4];
#pragma unroll
            for (int mt = 0; mt < 4; mt++)
                ldsm_x4(afr[mt], aS[cur] + mt*1024 + cA);
            uint32_t bfr[4][2];
#pragma unroll
            for (int nt = 0; nt < 4; nt++)
                ldsm_x2(bfr[nt], bS[cur] + nt*512 + cB);
#pragma unroll
            for (int mt = 0; mt < 4; mt++)
#pragma unroll
                for (int nt = 0; nt < 4; nt++)
                    mma16816(acc[mt][nt], afr[mt], bfr[nt]);
        }
        if (ci + 1 < 48) {
            int nxt = cur ^ 1;
            aswp[nxt][c0] = pa0; aswp[nxt][c1] = pa1;
            bswp[nxt][c0] = pb0; bswp[nxt][c1] = pb1;
        }
        __syncthreads();
    }

#pragma unroll
    for (int mt = 0; mt < 4; mt++) {
        int m0 = bm*128 + wm + mt*16 + gq;
        int m1 = m0 + 8;
        size_t row0 = 0, row1 = 0;
        bool v0 = m0 < Ml, v1 = m1 < Ml;
        if (v0) row0 = (size_t)(rowmap ? rowmap[m0] : m0);
        if (v1) row1 = (size_t)(rowmap ? rowmap[m1] : m1);
#pragma unroll
        for (int nt = 0; nt < 4; nt++) {
            int col = bn*128 + wn + nt*8 + tg*2;
            if (col >= N) continue;
            float bx = bias1[col], by = bias1[col+1];
            if (bias2) { bx += bias2[col]; by += bias2[col+1]; }
            if (v0) {
                float2 o = make_float2(acc[mt][nt][0] + bx, acc[mt][nt][1] + by);
                *(float2*)(C + row0*(size_t)ldc + col) = o;
            }
            if (v1) {
                float2 o = make_float2(acc[mt][nt][2] + bx, acc[mt][nt][3] + by);
                *(float2*)(C + row1*(size_t)ldc + col) = o;
            }
        }
    }
}

__global__ __launch_bounds__(256)
void k_gemm_pair(const float* __restrict__ b_enc, const float* __restrict__ b_ih,
                 const float* __restrict__ b_hh)
{
    __shared__ __align__(16) __nv_bfloat16 As[2][128*32];
    __shared__ __align__(16) __nv_bfloat16 Bs[2][128*32];
    int idx = blockIdx.x;
    if (idx < 392) {
        hgemm_body(idx >> 2, idx & 3, g_feats2, g_Wenc2, BB*PP, AA, AA,
                   b_enc, nullptr, g_encatt, nullptr, 0, As, Bs);
    } else {
        idx -= 392;
        hgemm_body(idx >> 4, idx & 15, g_embT2, g_Wih2, BB*TT, NG, NG,
                   b_ih, b_hh, g_embg, g_act, 1, As, Bs);
    }
}

__global__ __launch_bounds__(256)
void k_gemm_scores(const float* __restrict__ b_score, float* __restrict__ out)
{
    __shared__ __align__(16) __nv_bfloat16 As[2][128*32];
    __shared__ __align__(16) __nv_bfloat16 Bs[2][128*32];
    hgemm_body(blockIdx.x, blockIdx.y, g_hall2, g_Wsc2, BB*TT, VV, VV,
               b_score, nullptr, out, g_act, 1, As, Bs);
}

// ======================= fused persistent recurrence (1024 threads) =======================
// smem byte offsets
#define WIHC_OFF 0
#define WDEC_OFF 32768
#define WHH_OFF  49152
#define HT_OFF   114688
#define PART_OFF 180224
#define GH_OFF   196608
#define SM_TOTAL 200704

// flat per-slot barrier (replay-safe), tight spin; cnt = arrival count
__device__ __forceinline__ void gridbar_n(int slot, int cnt) {
    __syncthreads();
    if (threadIdx.x == 0) {
        int* p = &g_bars[slot];
        asm volatile("red.release.gpu.global.add.s32 [%0], 1;" :: "l"(p) : "memory");
        int v;
        do {
            asm volatile("ld.acquire.gpu.global.s32 %0, [%1];" : "=r"(v) : "l"(p) : "memory");
        } while (v < cnt);
    }
    __syncthreads();
}

// copy one 64KB tile (pb) from tile-format global to smem HT — pure 16B copies
__device__ __forceinline__ void copy32(const char* __restrict__ srcTiles, int pb,
                                       char* HTp, int tid) {
    const uint4* src = (const uint4*)(srcTiles + pb*65536);
    uint4* dst = (uint4*)HTp;
#pragma unroll
    for (int i = 0; i < 4; i++) {
        int o = tid + i*NTHR_R;
        dst[o] = __ldcg(src + o);
    }
}

// gates_ctx mma (32 warps): M=32, N=16 (slice j), K split 8 -> part[8][32][16]
__device__ __forceinline__ void gates_mma(uint32_t htA, uint32_t wbB, float* part,
                                          int wid, int lane) {
    int gq = lane >> 2, tg = lane & 3;
    int mh = (wid & 1)*16, nh = ((wid >> 1) & 1)*8, ks = wid >> 2;   // ks 0..7
    int rA = mh + (lane & 15);
    int swzA = (rA >> 1) & 3;
    int hiA = lane >> 4;
    int rB = nh + (lane & 7);
    int swzB = (rB >> 1) & 3;
    int hiB = (lane >> 3) & 1;
    uint32_t aL = htA + rA*64;
    uint32_t bL = wbB + rB*64;
    float acc[4] = {0.f, 0.f, 0.f, 0.f};
    for (int kt = ks*2; kt < ks*2 + 2; kt++) {
        uint32_t ah = aL + kt*2048;
        uint32_t bh = bL + kt*1024;
#pragma unroll
        for (int kk = 0; kk < 2; kk++) {
            uint32_t cA = (uint32_t)(((2*kk + hiA) ^ swzA) << 4);
            uint32_t cB = (uint32_t)(((2*kk + hiB) ^ swzB) << 4);
            uint32_t Ah[4], Al[4], Bh[2], Bl[2];
            ldsm_x4(Ah, ah + cA);
            ldsm_x4(Al, ah + 32768 + cA);
            ldsm_x2(Bh, bh + cB);
            ldsm_x2(Bl, bh + 16384 + cB);
            mma16816(acc, Ah, Bh);
            mma16816(acc, Ah, Bl);
            mma16816(acc, Al, Bh);
        }
    }
    int m0 = mh + gq, n0 = nh + tg*2;
    part[ks*512 + m0*16 + n0]       = acc[0];
    part[ks*512 + m0*16 + n0+1]     = acc[1];
    part[ks*512 + (m0+8)*16 + n0]   = acc[2];
    part[ks*512 + (m0+8)*16 + n0+1] = acc[3];
}

// gates_h mma for 2 slices (32 warps): M=32, N=32 rows, K split 4 -> part[4][32][32]
__device__ __forceinline__ void gates_mma32(uint32_t htA, uint32_t whB, float* part,
                                            int wid, int lane) {
    int gq = lane >> 2, tg = lane & 3;
    int mh = (wid & 1)*16, nh = ((wid >> 1) & 3)*8, ks = wid >> 3;   // ks 0..3
    int rA = mh + (lane & 15);
    int swzA = (rA >> 1) & 3;
    int hiA = lane >> 4;
    int rB = nh + (lane & 7);
    int swzB = (rB >> 1) & 3;
    int hiB = (lane >> 3) & 1;
    uint32_t aL = htA + rA*64;
    uint32_t bL = whB + rB*64;
    float acc[4] = {0.f, 0.f, 0.f, 0.f};
    for (int kt = ks*4; kt < ks*4 + 4; kt++) {
        uint32_t ah = aL + kt*2048;
        uint32_t bh = bL + kt*2048;
#pragma unroll
        for (int kk = 0; kk < 2; kk++) {
            uint32_t cA = (uint32_t)(((2*kk + hiA) ^ swzA) << 4);
            uint32_t cB = (uint32_t)(((2*kk + hiB) ^ swzB) << 4);
            uint32_t Ah[4], Al[4], Bh[2], Bl[2];
            ldsm_x4(Ah, ah + cA);
            ldsm_x4(Al, ah + 32768 + cA);
            ldsm_x2(Bh, bh + cB);
            ldsm_x2(Bl, bh + 32768 + cB);
            mma16816(acc, Ah, Bh);
            mma16816(acc, Ah, Bl);
            mma16816(acc, Al, Bh);
        }
    }
    int m0 = mh + gq, n0 = nh + tg*2;
    part[ks*1024 + m0*32 + n0]       = acc[0];
    part[ks*1024 + m0*32 + n0+1]     = acc[1];
    part[ks*1024 + (m0+8)*32 + n0]   = acc[2];
    part[ks*1024 + (m0+8)*32 + n0+1] = acc[3];
}

// att2 mma (32 warps): M=32, N=8 (ALL 8 rows real: slices j and j+64), K split 16
__device__ __forceinline__ void att2_mma(uint32_t htA, uint32_t wdB, float* part2,
                                         int wid, int lane) {
    int gq = lane >> 2, tg = lane & 3;
    int mh = (wid & 1)*16, ks = wid >> 1;   // ks 0..15
    int rA = mh + (lane & 15);
    int swzA = (rA >> 1) & 3;
    int hiA = lane >> 4;
    int rB = lane & 7;
    int swzB = (rB >> 1) & 3;
    int hiB = (lane >> 3) & 1;
    uint32_t aL = htA + rA*64;
    uint32_t bL = wdB + rB*64;
    float acc[4] = {0.f, 0.f, 0.f, 0.f};
    {
        int kt = ks;
        uint32_t ah = aL + kt*2048;
        uint32_t bh = bL + kt*512;
#pragma unroll
        for (int kk = 0; kk < 2; kk++) {
            uint32_t cA = (uint32_t)(((2*kk + hiA) ^ swzA) << 4);
            uint32_t cB = (uint32_t)(((2*kk + hiB) ^ swzB) << 4);
            uint32_t Ah[4], Al[4], Bh[2], Bl[2];
            ldsm_x4(Ah, ah + cA);
            ldsm_x4(Al, ah + 32768 + cA);
            ldsm_x2(Bh, bh + cB);
            ldsm_x2(Bl, bh + 8192 + cB);
            mma16816(acc, Ah, Bh);
            mma16816(acc, Ah, Bl);
            mma16816(acc, Al, Bh);
        }
    }
    int m0 = mh + gq, n0 = tg*2;
    part2[ks*256 + m0*8 + n0]       = acc[0];
    part2[ks*256 + m0*8 + n0+1]     = acc[1];
    part2[ks*256 + (m0+8)*8 + n0]   = acc[2];
    part2[ks*256 + (m0+8)*8 + n0+1] = acc[3];
}

__global__ __launch_bounds__(NTHR_R)
void k_recur(const float* __restrict__ W_dec, const float* __restrict__ W_hh,
             const float* __restrict__ W_ih,
             const float* __restrict__ b_dec, const float* __restrict__ W_full,
             const float* __restrict__ b_full, float* __restrict__ out)
{
    extern __shared__ float sm[];
    char* smc = (char*)sm;
    __shared__ int sdl[BB];
    __shared__ int snb[TT];
    int tid = threadIdx.x, lane = tid & 31, wid = tid >> 5;
    int j = blockIdx.x;

    if (tid < BB) sdl[tid] = g_declen[tid];
    if (tid >= 64 && tid < 64 + TT) snb[tid - 64] = g_nbact[tid - 64];

    // WIHC slice j (all CTAs)
    for (int i = tid; i < 16*256; i += NTHR_R) {
        int r = i >> 8, kp = i & 255, k = kp*2;
        int gr = 512*(r >> 2) + j*4 + (r & 3);
        float2 w2 = *(const float2*)(W_ih + (size_t)gr*1024 + 512 + k);
        uint32_t hp, lp;
        int kt = k >> 5, c = k & 31;
        cvt_hilo2(w2, hp, lp);
        stsw2(smc + WIHC_OFF + kt*1024, r, c, hp);
        stsw2(smc + WIHC_OFF + (16+kt)*1024, r, c, lp);
    }
    // WDEC 8 rows: slices j and j+64 (CTAs 0..63 only)
    if (j < 64) {
        for (int i = tid; i < 8*256; i += NTHR_R) {
            int r = i >> 8, kp = i & 255, k = kp*2;
            int gr = (r < 4) ? (j*4 + r) : ((j+64)*4 + (r-4));
            float2 w = *(const float2*)(W_dec + (size_t)gr*512 + k);
            uint32_t hp, lp;
            cvt_hilo2(w, hp, lp);
            int kt = k >> 5, c = k & 31;
            stsw2(smc + WDEC_OFF + kt*512, r, c, hp);
            stsw2(smc + WDEC_OFF + (16+kt)*512, r, c, lp);
        }
    }
    // WHH 2 slices (CTAs 64..127 only)
    if (j >= 64) {
        int s0 = (j - 64)*2;
        for (int i = tid; i < 32*256; i += NTHR_R) {
            int r = i >> 8, kp = i & 255, k = kp*2;
            int s = s0 + (r >> 4), rr = r & 15;
            int gr = 512*(rr >> 2) + s*4 + (rr & 3);
            float2 w1 = *(const float2*)(W_hh + (size_t)gr*512 + k);
            uint32_t hp, lp;
            int kt = k >> 5, c = k & 31;
            cvt_hilo2(w1, hp, lp);
            stsw2(smc + WHH_OFF + kt*2048, r, c, hp);
            stsw2(smc + WHH_OFF + 32768 + kt*2048, r, c, lp);
        }
    }
    __syncthreads();

    float* part  = (float*)(smc + PART_OFF);
    float* part2 = part;
    float* gh    = (float*)(smc + GH_OFF);
    uint32_t htS  = smem_u32(smc + HT_OFF);
    uint32_t wihS = smem_u32(smc + WIHC_OFF);
    uint32_t whhS = smem_u32(smc + WHH_OFF);
    uint32_t wdS  = smem_u32(smc + WDEC_OFF);

    for (int t = 0; t < TT; t++) {
        int npb = (snb[t] + 31) >> 5;
        // ---- Phase A+B split by CTA role ----
        if (j < 64) {
            // att2 for slices j and j+64
            for (int pb = 0; pb < npb; pb++) {
                int b0 = pb*32;
                copy32(g_h2, pb, smc + HT_OFF, tid);
                __syncthreads();
                att2_mma(htS, wdS, part2, wid, lane);
                __syncthreads();
                if (tid < 256) {
                    int m = tid >> 3, q = tid & 7;
                    float s = 0.f;
#pragma unroll
                    for (int ks = 0; ks < 16; ks++) s += part2[ks*256 + m*8 + q];
                    int col = (q < 4) ? (j*4 + q) : ((j+64)*4 + (q-4));
                    g_att2[(b0+m)*512 + col] = s;
                }
                __syncthreads();
            }
            gridbar_n(98 + t, 64);   // att2 ready among attention CTAs

            // attention
            if (t < sdl[j]) {
                int b = j;
                float* wout = out + OFF_WEIGHTS + (size_t)(b*TT + t)*PP;
                float* att = (float*)(smc + HT_OFF);
                float* s_att2 = att;
                float* s_wf   = att + 512;
                float* s_e    = att + 1024;
                float* s_red  = att + 1248;
                float* rbuf   = att + 1280;
                for (int a = tid; a < AA; a += NTHR_R) {
                    s_att2[a] = __ldcg(&g_att2[b*512 + a]) + b_dec[a];
                    s_wf[a] = W_full[a];
                }
                __syncthreads();
                const float4* s_att2v = (const float4*)s_att2;
                const float4* s_wfv   = (const float4*)s_wf;
                const float* ea = g_encatt + (size_t)b * PP * AA;
                for (int p = wid; p < PP; p += 32) {
                    const float4* row4 = (const float4*)(ea + (size_t)p * AA);
                    float sum = 0.f;
#pragma unroll
                    for (int k4 = 0; k4 < 4; k4++) {
                        int idx = lane + 32*k4;
                        float4 v = row4[idx];
                        float4 a2 = s_att2v[idx];
                        float4 wf = s_wfv[idx];
                        sum += fmaxf(v.x + a2.x, 0.f) * wf.x
                             + fmaxf(v.y + a2.y, 0.f) * wf.y
                             + fmaxf(v.z + a2.z, 0.f) * wf.z
                             + fmaxf(v.w + a2.w, 0.f) * wf.w;
                    }
#pragma unroll
                    for (int o = 16; o; o >>= 1) sum += __shfl_xor_sync(0xffffffffu, sum, o);
                    if (lane == 0) s_e[p] = sum + b_full[0];
                }
                __syncthreads();
                float m = -1e30f;
                if (tid < PP) m = s_e[tid];
#pragma unroll
                for (int o = 16; o; o >>= 1) m = fmaxf(m, __shfl_xor_sync(0xffffffffu, m, o));
                if (lane == 0) s_red[wid] = m;
                __syncthreads();
                float mx = s_red[0];
#pragma unroll
                for (int i = 1; i < 7; i++) mx = fmaxf(mx, s_red[i]);
                float ev = 0.f;
                if (tid < PP) ev = expf(s_e[tid] - mx);
                float sv = ev;
#pragma unroll
                for (int o = 16; o; o >>= 1) sv += __shfl_xor_sync(0xffffffffu, sv, o);
                __syncthreads();
                if (lane == 0) s_red[wid] = sv;
                __syncthreads();
                float tot = 0.f;
#pragma unroll
                for (int i = 0; i < 7; i++) tot += s_red[i];
                float inv = 1.f / tot;
                if (tid < PP) {
                    float al = ev * inv;
                    s_e[tid] = al;
                    wout[tid] = al;
                }
                __syncthreads();
                int hq = tid & 63, pc2 = tid >> 6;
                const float4* fb4 = (const float4*)(g_feats + (size_t)b * PP * HH);
                float4 a0 = make_float4(0,0,0,0), a1 = make_float4(0,0,0,0);
                for (int p = pc2; p < PP; p += 16) {
                    float al = s_e[p];
                    float4 v0 = fb4[p*128 + hq*2];
                    float4 v1 = fb4[p*128 + hq*2 + 1];
                    a0.x = fmaf(al, v0.x, a0.x); a0.y = fmaf(al, v0.y, a0.y);
                    a0.z = fmaf(al, v0.z, a0.z); a0.w = fmaf(al, v0.w, a0.w);
                    a1.x = fmaf(al, v1.x, a1.x); a1.y = fmaf(al, v1.y, a1.y);
                    a1.z = fmaf(al, v1.z, a1.z); a1.w = fmaf(al, v1.w, a1.w);
                }
                float* rb = rbuf + pc2*512 + hq*8;
                rb[0]=a0.x; rb[1]=a0.y; rb[2]=a0.z; rb[3]=a0.w;
                rb[4]=a1.x; rb[5]=a1.y; rb[6]=a1.z; rb[7]=a1.w;
                __syncthreads();
                if (tid < 256) {
                    int o = tid*2;
                    float s0v = 0.f, s1v = 0.f;
#pragma unroll
                    for (int q = 0; q < 16; q++) {
                        s0v += rbuf[q*512 + o];
                        s1v += rbuf[q*512 + o + 1];
                    }
                    uint32_t hp, lp;
                    cvt_hilo2(make_float2(s0v, s1v), hp, lp);
                    int pbb = b >> 5, r = b & 31, kt = o >> 5, c = o & 31;
                    char* base = g_ctx2 + pbb*65536;
                    stsw2(base + kt*2048, r, c, hp);
                    stsw2(base + (16+kt)*2048, r, c, lp);
                }
            }
        } else {
            // gates_h (2 slices), starts immediately
            int s0 = (j - 64)*2;
            for (int pb = 0; pb < npb; pb++) {
                int b0 = pb*32;
                copy32(g_h2, pb, smc + HT_OFF, tid);
                __syncthreads();
                gates_mma32(htS, whhS, part, wid, lane);
                __syncthreads();
                {
                    int o = tid;
                    int m = o >> 5, n = o & 31;
                    float s = part[o] + part[1024 + o] + part[2048 + o] + part[3072 + o];
                    int sl = s0 + (n >> 4), rr = n & 15;
                    g_gh[((b0 + m)*128 + sl)*16 + rr] = s;
                }
                __syncthreads();
            }
        }
        gridbar_n(2*t, NCTA);

        // ---- Phase C: gates_ctx (mma) + combine(g_gh, embg) + LSTM ----
        for (int pb = 0; pb < npb; pb++) {
            int b0 = pb*32;
            copy32(g_ctx2, pb, smc + HT_OFF, tid);
            __syncthreads();
            gates_mma(htS, wihS, part, wid, lane);
            __syncthreads();
            for (int o = tid; o < 512; o += NTHR_R) {
                int m = o >> 4, n = o & 15;
                int b = b0 + m;
                int gr = 512*(n >> 2) + j*4 + (n & 3);
                float s = 0.f;
#pragma unroll
                for (int ks = 0; ks < 8; ks++) s += part[ks*512 + o];
                gh[b*16 + n] = s + __ldcg(&g_gh[(b*128 + j)*16 + n])
                             + g_embg[(size_t)(b*TT + t)*NG + gr];
            }
            __syncthreads();
        }
        if (tid < 128) {
            int b = tid >> 1, qp = tid & 1;
            if (t < sdl[b]) {
                float hn[2];
#pragma unroll
                for (int e = 0; e < 2; e++) {
                    int q = qp*2 + e;
                    float gi = gh[b*16 + q];
                    float gf = gh[b*16 + 4 + q];
                    float gg = gh[b*16 + 8 + q];
                    float go = gh[b*16 + 12 + q];
                    float ig = 1.f / (1.f + expf(-gi));
                    float fg = 1.f / (1.f + expf(-gf));
                    float gv = tanhf(gg);
                    float og = 1.f / (1.f + expf(-go));
                    int kc = j*4 + q;
                    float c_new = fg * g_c[b*512 + kc] + ig * gv;
                    hn[e] = og * tanhf(c_new);
                    g_c[b*512 + kc] = c_new;
                }
                int kc0 = j*4 + qp*2;
                uint32_t hp, lp;
                cvt_hilo2(make_float2(hn[0], hn[1]), hp, lp);
                int pbb = b >> 5, r = b & 31, kt = kc0 >> 5, c = kc0 & 31;
                char* base = g_h2 + pbb*65536;
                stsw2(base + kt*2048, r, c, hp);
                stsw2(base + (16+kt)*2048, r, c, lp);
                *(uint32_t*)&g_hall2[(size_t)(b*TT + t)*1024 + kc0]       = hp;
                *(uint32_t*)&g_hall2[(size_t)(b*TT + t)*1024 + 512 + kc0] = lp;
            }
        }
        gridbar_n(2*t + 1, NCTA);
    }
}

// ======================= launch =======================
extern "C" void kernel_launch(void* const* d_in, const int* in_sizes, int n_in,
                              void* d_out, int out_size) {
    const float* imf     = (const float*)d_in[0];
    const int*   caps    = (const int*)  d_in[1];
    const int*   caplens = (const int*)  d_in[2];
    const float* emb     = (const float*)d_in[3];
    const float* W_ih    = (const float*)d_in[4];
    const float* W_hh    = (const float*)d_in[5];
    const float* b_ih    = (const float*)d_in[6];
    const float* b_hh    = (const float*)d_in[7];
    const float* W_enc   = (const float*)d_in[8];
    const float* b_enc   = (const float*)d_in[9];
    const float* W_dec   = (const float*)d_in[10];
    const float* b_dec   = (const float*)d_in[11];
    const float* W_full  = (const float*)d_in[12];
    const float* b_full  = (const float*)d_in[13];
    const float* W_score = (const float*)d_in[14];
    const float* b_score = (const float*)d_in[15];
    float* out = (float*)d_out;

    cudaFuncSetAttribute(k_recur, cudaFuncAttributeMaxDynamicSharedMemorySize, SM_TOTAL);

    // 1: sort + caps/declen/sortind outputs
    k_sort<<<1, BB>>>(caplens, caps, out);
    // 2: fused gathers + bf16 hi/lo conversions + zeroing + init
    k_cvt_all<<<1024, 256>>>(imf, caps, emb, W_enc, W_ih, W_score, out);
    // 3: fused enc_att + G_emb tensor-core GEMMs
    k_gemm_pair<<<792, 256>>>(b_enc, b_ih, b_hh);
    // 4: persistent recurrence (1024 threads, role-split phases)
    k_recur<<<NCTA, NTHR_R, SM_TOTAL>>>(W_dec, W_hh, W_ih, b_dec, W_full, b_full, out);
    // 5: scores GEMM
    k_gemm_scores<<<dim3((BB*TT + 127)/128, (VV + 127)/128), 256>>>(b_score, out);
}

// round 16
// speedup vs baseline: 2.1765x; 1.0781x over previous
#include <cuda_runtime.h>
#include <cuda_bf16.h>
#include <cstdint>
#include <math.h>

#define BB 64
#define PP 196
#define HH 512
#define EE 512
#define AA 512
#define VV 10000
#define MAXCAP 50
#define TT 49
#define NG 2048   // 4*H

// output layout (float32): scores (B,T,V), caps_s (B,50), decode_lengths (B,), weights (B,T,P), sort_ind (B,)
#define N_SCORES   (BB*TT*VV)
#define OFF_CAPS   (N_SCORES)
#define OFF_DECLEN (OFF_CAPS + BB*MAXCAP)
#define OFF_WEIGHTS (OFF_DECLEN + BB)
#define OFF_SORT   (OFF_WEIGHTS + BB*TT*PP)

#define NCTA 128
#define NTHR 256
#define NTHR_R 1024

// ======================= scratch =======================
__device__ float g_feats[BB*PP*HH];
__device__ float g_encatt[BB*PP*AA];
__device__ float g_embg[BB*TT*NG];
__device__ float g_c[BB*HH];
__device__ float g_att2[BB*AA];
__device__ float g_gh[BB*NG];          // gates_h: [b][slice 0..127][16]
__device__ int   g_sortidx[BB];
__device__ int   g_declen[BB];
__device__ int   g_nbact[TT];
__device__ int   g_act[BB*TT];
__device__ int   g_nact;
__device__ int   g_bars[160];

// h/ctx in MMA-native tile format: [pb 0..1][64KB tile: hi kt 0..15, lo kt 16..31, each 32r x 64B]
__device__ __align__(16) char g_h2[131072];
__device__ __align__(16) char g_ctx2[131072];

// bf16 hi/lo packed [rows][1024]: cols 0-511 hi, 512-1023 lo
__device__ __nv_bfloat16 g_feats2[BB*PP*1024];
__device__ __nv_bfloat16 g_embT2[BB*TT*1024];
__device__ __nv_bfloat16 g_hall2[BB*TT*1024];
__device__ __nv_bfloat16 g_Wenc2[AA*1024];
__device__ __nv_bfloat16 g_Wih2[NG*1024];
__device__ __nv_bfloat16 g_Wsc2[VV*1024];

// ======================= helpers =======================
__device__ __forceinline__ void mma16816(float* d, const uint32_t* a, const uint32_t* b) {
    asm volatile("mma.sync.aligned.m16n8k16.row.col.f32.bf16.bf16.f32 "
        "{%0,%1,%2,%3}, {%4,%5,%6,%7}, {%8,%9}, {%0,%1,%2,%3};"
        : "+f"(d[0]), "+f"(d[1]), "+f"(d[2]), "+f"(d[3])
        : "r"(a[0]), "r"(a[1]), "r"(a[2]), "r"(a[3]), "r"(b[0]), "r"(b[1]));
}
__device__ __forceinline__ void ldsm_x4(uint32_t* r, uint32_t saddr) {
    asm volatile("ldmatrix.sync.aligned.m8n8.x4.shared.b16 {%0,%1,%2,%3}, [%4];"
        : "=r"(r[0]), "=r"(r[1]), "=r"(r[2]), "=r"(r[3]) : "r"(saddr));
}
__device__ __forceinline__ void ldsm_x2(uint32_t* r, uint32_t saddr) {
    asm volatile("ldmatrix.sync.aligned.m8n8.x2.shared.b16 {%0,%1}, [%2];"
        : "=r"(r[0]), "=r"(r[1]) : "r"(saddr));
}
__device__ __forceinline__ uint32_t smem_u32(const void* p) {
    return (uint32_t)__cvta_generic_to_shared(p);
}
// store bf16x2 at (r, c even 0..31) in swizzled tile (64B rows, 16B-chunk XOR)
__device__ __forceinline__ void stsw2(char* s, int r, int c, uint32_t v) {
    int byte = r*64 + ((((c >> 3) ^ ((r >> 1) & 3))) << 4) + (c & 7)*2;
    *(uint32_t*)(s + byte) = v;
}
__device__ __forceinline__ void cvt_hilo2(float2 v, uint32_t& hp, uint32_t& lp) {
    __nv_bfloat16 h0 = __float2bfloat16(v.x), h1 = __float2bfloat16(v.y);
    float l0 = v.x - __bfloat162float(h0), l1 = v.y - __bfloat162float(h1);
    __nv_bfloat16 b0 = __float2bfloat16(l0), b1 = __float2bfloat16(l1);
    hp = (uint32_t)__bfloat16_as_ushort(h0) | ((uint32_t)__bfloat16_as_ushort(h1) << 16);
    lp = (uint32_t)__bfloat16_as_ushort(b0) | ((uint32_t)__bfloat16_as_ushort(b1) << 16);
}

// ======================= prep kernels =======================
__global__ void k_sort(const int* __restrict__ caplens, const int* __restrict__ caps,
                       float* __restrict__ out) {
    __shared__ int s_sort[BB];
    if (threadIdx.x == 0) {
        int cl[BB];
        for (int i = 0; i < BB; i++) cl[i] = caplens[i];
        int r = 0;
        for (int v = MAXCAP; v >= 0 && r < BB; v--)
            for (int i = 0; i < BB; i++)
                if (cl[i] == v) { g_sortidx[r] = i; s_sort[r] = i; r++; }
        int na = 0;
        int dls[BB];
        for (int b = 0; b < BB; b++) {
            int dl = cl[g_sortidx[b]] - 1;
            dls[b] = dl;
            g_declen[b] = dl;
            out[OFF_DECLEN + b] = (float)dl;
            out[OFF_SORT + b]   = (float)g_sortidx[b];
            for (int t = 0; t < dl; t++) g_act[na++] = b*TT + t;
        }
        g_nact = na;
        for (int t = 0; t < TT; t++) {
            int c = 0;
            for (int b = 0; b < BB; b++) if (dls[b] > t) c++;
            g_nbact[t] = c;
        }
    }
    __syncthreads();
    int b = threadIdx.x;
    int src = s_sort[b];
    for (int t = 0; t < MAXCAP; t++)
        out[OFF_CAPS + b*MAXCAP + t] = (float)caps[src*MAXCAP + t];
}

// fused gather + hi/lo conversion (pairwise) + zero + init
#define P0 (BB*PP*256)
#define P1 (BB*TT*256)
#define P2 (AA*256)
#define P3 (NG*256)
#define P4 (VV*256)
#define Z5 (N_SCORES/4)
#define Z6 (BB*TT*PP/4)
#define Z7 (BB*HH)
#define Z7B (2*131072/16)
#define Z8 160
__global__ void k_cvt_all(const float* __restrict__ imf, const int* __restrict__ caps,
                          const float* __restrict__ emb, const float* __restrict__ W_enc,
                          const float* __restrict__ W_ih, const float* __restrict__ W_score,
                          float* __restrict__ out)
{
    const int total = P0+P1+P2+P3+P4+Z5+Z6+Z7+Z7B+Z8;
    for (int i = blockIdx.x*blockDim.x + threadIdx.x; i < total; i += gridDim.x*blockDim.x) {
        int x = i;
        if (x < P0) {
            int r = x >> 8, c2 = x & 255, k = c2*2;
            int b = r / PP, p = r - b*PP;
            float2 v = *(const float2*)(imf + ((size_t)g_sortidx[b]*PP + p)*512 + k);
            *(float2*)(g_feats + (size_t)r*512 + k) = v;
            uint32_t hp, lp; cvt_hilo2(v, hp, lp);
            ((uint32_t*)g_feats2)[(size_t)r*512 + c2] = hp;
            ((uint32_t*)g_feats2)[(size_t)r*512 + 256 + c2] = lp;
            continue;
        }
        x -= P0;
        if (x < P1) {
            int r = x >> 8, c2 = x & 255, k = c2*2;
            int b = r / TT, t = r - b*TT;
            int tok = caps[g_sortidx[b]*MAXCAP + t];
            float2 v = *(const float2*)(emb + (size_t)tok*512 + k);
            uint32_t hp, lp; cvt_hilo2(v, hp, lp);
            ((uint32_t*)g_embT2)[(size_t)r*512 + c2] = hp;
            ((uint32_t*)g_embT2)[(size_t)r*512 + 256 + c2] = lp;
            continue;
        }
        x -= P1;
        if (x < P2) {
            int r = x >> 8, c2 = x & 255, k = c2*2;
            float2 v = *(const float2*)(W_enc + (size_t)r*512 + k);
            uint32_t hp, lp; cvt_hilo2(v, hp, lp);
            ((uint32_t*)g_Wenc2)[(size_t)r*512 + c2] = hp;
            ((uint32_t*)g_Wenc2)[(size_t)r*512 + 256 + c2] = lp;
            continue;
        }
        x -= P2;
        if (x < P3) {
            int r = x >> 8, c2 = x & 255, k = c2*2;
            float2 v = *(const float2*)(W_ih + (size_t)r*1024 + k);
            uint32_t hp, lp; cvt_hilo2(v, hp, lp);
            ((uint32_t*)g_Wih2)[(size_t)r*512 + c2] = hp;
            ((uint32_t*)g_Wih2)[(size_t)r*512 + 256 + c2] = lp;
            continue;
        }
        x -= P3;
        if (x < P4) {
            int r = x >> 8, c2 = x & 255, k = c2*2;
            float2 v = *(const float2*)(W_score + (size_t)r*512 + k);
            uint32_t hp, lp; cvt_hilo2(v, hp, lp);
            ((uint32_t*)g_Wsc2)[(size_t)r*512 + c2] = hp;
            ((uint32_t*)g_Wsc2)[(size_t)r*512 + 256 + c2] = lp;
            continue;
        }
        x -= P4;
        if (x < Z5) {
            ((float4*)out)[x] = make_float4(0.f, 0.f, 0.f, 0.f);
            continue;
        }
        x -= Z5;
        if (x < Z6) {
            ((float4*)(out + OFF_WEIGHTS))[x] = make_float4(0.f, 0.f, 0.f, 0.f);
            continue;
        }
        x -= Z6;
        if (x < Z7) { g_c[x] = 0.f; continue; }
        x -= Z7;
        if (x < Z7B) {
            uint4 z = make_uint4(0,0,0,0);
            if (x < 131072/16) ((uint4*)g_h2)[x] = z;
            else ((uint4*)g_ctx2)[x - 131072/16] = z;
            continue;
        }
        x -= Z7B;
        g_bars[x] = 0;
    }
}

// ======================= mma.sync bf16x3 GEMM body (ldmatrix + double buffer) ==========
__device__ __forceinline__ void hgemm_body(
    int bm, int bn,
    const __nv_bfloat16* __restrict__ A2, const __nv_bfloat16* __restrict__ B2,
    int M, int N, int ldc,
    const float* __restrict__ bias1, const float* __restrict__ bias2,
    float* __restrict__ C, const int* __restrict__ rowmap, int use_nact,
    __nv_bfloat16 (*As)[128*32], __nv_bfloat16 (*Bs)[128*32])
{
    int tid = threadIdx.x;
    int Ml = use_nact ? g_nact : M;
    if (bm*128 >= Ml) return;

    int lrow = tid >> 1;
    int lc0 = (tid & 1) * 2;
    int gm = bm*128 + lrow;
    const uint4* arow = nullptr;
    if (gm < Ml) { int r = rowmap ? rowmap[gm] : gm; arow = (const uint4*)(A2 + (size_t)r*1024); }
    int gn = bn*128 + lrow;
    const uint4* brow = (gn < N) ? (const uint4*)(B2 + (size_t)gn*1024) : nullptr;

    int swz = (lrow >> 1) & 3;
    uint4* aswp[2] = {(uint4*)(As[0] + lrow*32), (uint4*)(As[1] + lrow*32)};
    uint4* bswp[2] = {(uint4*)(Bs[0] + lrow*32), (uint4*)(Bs[1] + lrow*32)};
    int c0 = lc0 ^ swz, c1 = (lc0+1) ^ swz;

    int lane = tid & 31, wid = tid >> 5;
    int wm = (wid >> 2) * 64;
    int wn = (wid & 3) * 32;
    int gq = lane >> 2, tg = lane & 3;

    int rA = wm + (lane & 15);
    int swzA = (rA >> 1) & 3;
    int hiA = lane >> 4;
    int rB = wn + (lane & 7);
    int swzB = (rB >> 1) & 3;
    int hiB = (lane >> 3) & 1;
    uint32_t aS[2] = {smem_u32(As[0]) + rA*64, smem_u32(As[1]) + rA*64};
    uint32_t bS[2] = {smem_u32(Bs[0]) + rB*64, smem_u32(Bs[1]) + rB*64};

    float acc[4][4][4];
#pragma unroll
    for (int mt = 0; mt < 4; mt++)
#pragma unroll
        for (int nt = 0; nt < 4; nt++)
#pragma unroll
            for (int r = 0; r < 4; r++) acc[mt][nt][r] = 0.f;

    const uint4 z = make_uint4(0,0,0,0);
    const int kau4[3] = {0, 0, 64};
    const int kbu4[3] = {0, 64, 0};
    uint4 pa0 = arow ? arow[lc0]   : z;
    uint4 pa1 = arow ? arow[lc0+1] : z;
    uint4 pb0 = brow ? brow[lc0]   : z;
    uint4 pb1 = brow ? brow[lc0+1] : z;
    aswp[0][c0] = pa0; aswp[0][c1] = pa1;
    bswp[0][c0] = pb0; bswp[0][c1] = pb1;
    __syncthreads();

    for (int ci = 0; ci < 48; ci++) {
        int cur = ci & 1;
        if (ci + 1 < 48) {
            int term = (ci+1) >> 4, kc = (ci+1) & 15;
            int ab = kau4[term] + kc*4, bb = kbu4[term] + kc*4;
            pa0 = arow ? arow[ab + lc0]   : z;
            pa1 = arow ? arow[ab + lc0+1] : z;
            pb0 = brow ? brow[bb + lc0]   : z;
            pb1 = brow ? brow[bb + lc0+1] : z;
        }
#pragma unroll
        for (int kk = 0; kk < 2; kk++) {
            uint32_t cA = (uint32_t)(((2*kk + hiA) ^ swzA) << 4);
            uint32_t cB = (uint32_t)(((2*kk + hiB) ^ swzB) << 4);
            uint32_t afr[4][4];
#pragma unroll
            for (int mt = 0; mt < 4; mt++)
                ldsm_x4(afr[mt], aS[cur] + mt*1024 + cA);
            uint32_t bfr[4][2];
#pragma unroll
            for (int nt = 0; nt < 4; nt++)
                ldsm_x2(bfr[nt], bS[cur] + nt*512 + cB);
#pragma unroll
            for (int mt = 0; mt < 4; mt++)
#pragma unroll
                for (int nt = 0; nt < 4; nt++)
                    mma16816(acc[mt][nt], afr[mt], bfr[nt]);
        }
        if (ci + 1 < 48) {
            int nxt = cur ^ 1;
            aswp[nxt][c0] = pa0; aswp[nxt][c1] = pa1;
            bswp[nxt][c0] = pb0; bswp[nxt][c1] = pb1;
        }
        __syncthreads();
    }

#pragma unroll
    for (int mt = 0; mt < 4; mt++) {
        int m0 = bm*128 + wm + mt*16 + gq;
        int m1 = m0 + 8;
        size_t row0 = 0, row1 = 0;
        bool v0 = m0 < Ml, v1 = m1 < Ml;
        if (v0) row0 = (size_t)(rowmap ? rowmap[m0] : m0);
        if (v1) row1 = (size_t)(rowmap ? rowmap[m1] : m1);
#pragma unroll
        for (int nt = 0; nt < 4; nt++) {
            int col = bn*128 + wn + nt*8 + tg*2;
            if (col >= N) continue;
            float bx = bias1[col], by = bias1[col+1];
            if (bias2) { bx += bias2[col]; by += bias2[col+1]; }
            if (v0) {
                float2 o = make_float2(acc[mt][nt][0] + bx, acc[mt][nt][1] + by);
                *(float2*)(C + row0*(size_t)ldc + col) = o;
            }
            if (v1) {
                float2 o = make_float2(acc[mt][nt][2] + bx, acc[mt][nt][3] + by);
                *(float2*)(C + row1*(size_t)ldc + col) = o;
            }
        }
    }
}

__global__ __launch_bounds__(256)
void k_gemm_pair(const float* __restrict__ b_enc, const float* __restrict__ b_ih,
                 const float* __restrict__ b_hh)
{
    __shared__ __align__(16) __nv_bfloat16 As[2][128*32];
    __shared__ __align__(16) __nv_bfloat16 Bs[2][128*32];
    int idx = blockIdx.x;
    if (idx < 392) {
        hgemm_body(idx >> 2, idx & 3, g_feats2, g_Wenc2, BB*PP, AA, AA,
                   b_enc, nullptr, g_encatt, nullptr, 0, As, Bs);
    } else {
        idx -= 392;
        hgemm_body(idx >> 4, idx & 15, g_embT2, g_Wih2, BB*TT, NG, NG,
                   b_ih, b_hh, g_embg, g_act, 1, As, Bs);
    }
}

__global__ __launch_bounds__(256)
void k_gemm_scores(const float* __restrict__ b_score, float* __restrict__ out)
{
    __shared__ __align__(16) __nv_bfloat16 As[2][128*32];
    __shared__ __align__(16) __nv_bfloat16 Bs[2][128*32];
    hgemm_body(blockIdx.x, blockIdx.y, g_hall2, g_Wsc2, BB*TT, VV, VV,
               b_score, nullptr, out, g_act, 1, As, Bs);
}

// ======================= fused persistent recurrence (1024 threads) =======================
// smem byte offsets
#define WIHC_OFF 0
#define WDEC_OFF 32768
#define WHH_OFF  49152
#define HT_OFF   114688
#define PART_OFF 180224
#define GH_OFF   196608
#define SM_TOTAL 200704

// flat per-slot barrier (replay-safe), tight spin; cnt = arrival count
__device__ __forceinline__ void gridbar_n(int slot, int cnt) {
    __syncthreads();
    if (threadIdx.x == 0) {
        int* p = &g_bars[slot];
        asm volatile("red.release.gpu.global.add.s32 [%0], 1;" :: "l"(p) : "memory");
        int v;
        do {
            asm volatile("ld.acquire.gpu.global.s32 %0, [%1];" : "=r"(v) : "l"(p) : "memory");
        } while (v < cnt);
    }
    __syncthreads();
}

// copy one 64KB tile (pb) from tile-format global to smem HT — pure 16B copies
__device__ __forceinline__ void copy32(const char* __restrict__ srcTiles, int pb,
                                       char* HTp, int tid) {
    const uint4* src = (const uint4*)(srcTiles + pb*65536);
    uint4* dst = (uint4*)HTp;
#pragma unroll
    for (int i = 0; i < 4; i++) {
        int o = tid + i*NTHR_R;
        dst[o] = __ldcg(src + o);
    }
}

// gates_ctx mma (32 warps): M=32, N=16 (slice j), K split 8 -> part[8][32][16]
__device__ __forceinline__ void gates_mma(uint32_t htA, uint32_t wbB, float* part,
                                          int wid, int lane) {
    int gq = lane >> 2, tg = lane & 3;
    int mh = (wid & 1)*16, nh = ((wid >> 1) & 1)*8, ks = wid >> 2;   // ks 0..7
    int rA = mh + (lane & 15);
    int swzA = (rA >> 1) & 3;
    int hiA = lane >> 4;
    int rB = nh + (lane & 7);
    int swzB = (rB >> 1) & 3;
    int hiB = (lane >> 3) & 1;
    uint32_t aL = htA + rA*64;
    uint32_t bL = wbB + rB*64;
    float acc[4] = {0.f, 0.f, 0.f, 0.f};
    for (int kt = ks*2; kt < ks*2 + 2; kt++) {
        uint32_t ah = aL + kt*2048;
        uint32_t bh = bL + kt*1024;
#pragma unroll
        for (int kk = 0; kk < 2; kk++) {
            uint32_t cA = (uint32_t)(((2*kk + hiA) ^ swzA) << 4);
            uint32_t cB = (uint32_t)(((2*kk + hiB) ^ swzB) << 4);
            uint32_t Ah[4], Al[4], Bh[2], Bl[2];
            ldsm_x4(Ah, ah + cA);
            ldsm_x4(Al, ah + 32768 + cA);
            ldsm_x2(Bh, bh + cB);
            ldsm_x2(Bl, bh + 16384 + cB);
            mma16816(acc, Ah, Bh);
            mma16816(acc, Ah, Bl);
            mma16816(acc, Al, Bh);
        }
    }
    int m0 = mh + gq, n0 = nh + tg*2;
    part[ks*512 + m0*16 + n0]       = acc[0];
    part[ks*512 + m0*16 + n0+1]     = acc[1];
    part[ks*512 + (m0+8)*16 + n0]   = acc[2];
    part[ks*512 + (m0+8)*16 + n0+1] = acc[3];
}

// gates_h mma for 2 slices (32 warps): M=32, N=32 rows, K split 4 -> part[4][32][32]
__device__ __forceinline__ void gates_mma32(uint32_t htA, uint32_t whB, float* part,
                                            int wid, int lane) {
    int gq = lane >> 2, tg = lane & 3;
    int mh = (wid & 1)*16, nh = ((wid >> 1) & 3)*8, ks = wid >> 3;   // ks 0..3
    int rA = mh + (lane & 15);
    int swzA = (rA >> 1) & 3;
    int hiA = lane >> 4;
    int rB = nh + (lane & 7);
    int swzB = (rB >> 1) & 3;
    int hiB = (lane >> 3) & 1;
    uint32_t aL = htA + rA*64;
    uint32_t bL = whB + rB*64;
    float acc[4] = {0.f, 0.f, 0.f, 0.f};
    for (int kt = ks*4; kt < ks*4 + 4; kt++) {
        uint32_t ah = aL + kt*2048;
        uint32_t bh = bL + kt*2048;
#pragma unroll
        for (int kk = 0; kk < 2; kk++) {
            uint32_t cA = (uint32_t)(((2*kk + hiA) ^ swzA) << 4);
            uint32_t cB = (uint32_t)(((2*kk + hiB) ^ swzB) << 4);
            uint32_t Ah[4], Al[4], Bh[2], Bl[2];
            ldsm_x4(Ah, ah + cA);
            ldsm_x4(Al, ah + 32768 + cA);
            ldsm_x2(Bh, bh + cB);
            ldsm_x2(Bl, bh + 32768 + cB);
            mma16816(acc, Ah, Bh);
            mma16816(acc, Ah, Bl);
            mma16816(acc, Al, Bh);
        }
    }
    int m0 = mh + gq, n0 = nh + tg*2;
    part[ks*1024 + m0*32 + n0]       = acc[0];
    part[ks*1024 + m0*32 + n0+1]     = acc[1];
    part[ks*1024 + (m0+8)*32 + n0]   = acc[2];
    part[ks*1024 + (m0+8)*32 + n0+1] = acc[3];
}

// att2 mma (32 warps): M=32, N=8 (ALL 8 rows real: slices j and j+64), K split 16
__device__ __forceinline__ void att2_mma(uint32_t htA, uint32_t wdB, float* part2,
                                         int wid, int lane) {
    int gq = lane >> 2, tg = lane & 3;
    int mh = (wid & 1)*16, ks = wid >> 1;   // ks 0..15
    int rA = mh + (lane & 15);
    int swzA = (rA >> 1) & 3;
    int hiA = lane >> 4;
    int rB = lane & 7;
    int swzB = (rB >> 1) & 3;
    int hiB = (lane >> 3) & 1;
    uint32_t aL = htA + rA*64;
    uint32_t bL = wdB + rB*64;
    float acc[4] = {0.f, 0.f, 0.f, 0.f};
    {
        int kt = ks;
        uint32_t ah = aL + kt*2048;
        uint32_t bh = bL + kt*512;
#pragma unroll
        for (int kk = 0; kk < 2; kk++) {
            uint32_t cA = (uint32_t)(((2*kk + hiA) ^ swzA) << 4);
            uint32_t cB = (uint32_t)(((2*kk + hiB) ^ swzB) << 4);
            uint32_t Ah[4], Al[4], Bh[2], Bl[2];
            ldsm_x4(Ah, ah + cA);
            ldsm_x4(Al, ah + 32768 + cA);
            ldsm_x2(Bh, bh + cB);
            ldsm_x2(Bl, bh + 8192 + cB);
            mma16816(acc, Ah, Bh);
            mma16816(acc, Ah, Bl);
            mma16816(acc, Al, Bh);
        }
    }
    int m0 = mh + gq, n0 = tg*2;
    part2[ks*256 + m0*8 + n0]       = acc[0];
    part2[ks*256 + m0*8 + n0+1]     = acc[1];
    part2[ks*256 + (m0+8)*8 + n0]   = acc[2];
    part2[ks*256 + (m0+8)*8 + n0+1] = acc[3];
}

__global__ __launch_bounds__(NTHR_R)
void k_recur(const float* __restrict__ W_dec, const float* __restrict__ W_hh,
             const float* __restrict__ W_ih,
             const float* __restrict__ b_dec, const float* __restrict__ W_full,
             const float* __restrict__ b_full, float* __restrict__ out)
{
    extern __shared__ float sm[];
    char* smc = (char*)sm;
    __shared__ int sdl[BB];
    __shared__ int snb[TT];
    int tid = threadIdx.x, lane = tid & 31, wid = tid >> 5;
    int j = blockIdx.x;

    if (tid < BB) sdl[tid] = g_declen[tid];
    if (tid >= 64 && tid < 64 + TT) snb[tid - 64] = g_nbact[tid - 64];

    // WIHC slice j (all CTAs)
    for (int i = tid; i < 16*256; i += NTHR_R) {
        int r = i >> 8, kp = i & 255, k = kp*2;
        int gr = 512*(r >> 2) + j*4 + (r & 3);
        float2 w2 = *(const float2*)(W_ih + (size_t)gr*1024 + 512 + k);
        uint32_t hp, lp;
        int kt = k >> 5, c = k & 31;
        cvt_hilo2(w2, hp, lp);
        stsw2(smc + WIHC_OFF + kt*1024, r, c, hp);
        stsw2(smc + WIHC_OFF + (16+kt)*1024, r, c, lp);
    }
    // WDEC 8 rows: slices j and j+64 (CTAs 0..63 only)
    if (j < 64) {
        for (int i = tid; i < 8*256; i += NTHR_R) {
            int r = i >> 8, kp = i & 255, k = kp*2;
            int gr = (r < 4) ? (j*4 + r) : ((j+64)*4 + (r-4));
            float2 w = *(const float2*)(W_dec + (size_t)gr*512 + k);
            uint32_t hp, lp;
            cvt_hilo2(w, hp, lp);
            int kt = k >> 5, c = k & 31;
            stsw2(smc + WDEC_OFF + kt*512, r, c, hp);
            stsw2(smc + WDEC_OFF + (16+kt)*512, r, c, lp);
        }
    }
    // WHH 2 slices (CTAs 64..127 only)
    if (j >= 64) {
        int s0 = (j - 64)*2;
        for (int i = tid; i < 32*256; i += NTHR_R) {
            int r = i >> 8, kp = i & 255, k = kp*2;
            int s = s0 + (r >> 4), rr = r & 15;
            int gr = 512*(rr >> 2) + s*4 + (rr & 3);
            float2 w1 = *(const float2*)(W_hh + (size_t)gr*512 + k);
            uint32_t hp, lp;
            int kt = k >> 5, c = k & 31;
            cvt_hilo2(w1, hp, lp);
            stsw2(smc + WHH_OFF + kt*2048, r, c, hp);
            stsw2(smc + WHH_OFF + 32768 + kt*2048, r, c, lp);
        }
    }
    __syncthreads();

    float* part  = (float*)(smc + PART_OFF);
    float* part2 = part;
    float* gh    = (float*)(smc + GH_OFF);
    uint32_t htS  = smem_u32(smc + HT_OFF);
    uint32_t wihS = smem_u32(smc + WIHC_OFF);
    uint32_t whhS = smem_u32(smc + WHH_OFF);
    uint32_t wdS  = smem_u32(smc + WDEC_OFF);

    for (int t = 0; t < TT; t++) {
        int npb = (snb[t] + 31) >> 5;
        // ---- Phase A+B split by CTA role ----
        if (j < 64) {
            // att2 for slices j and j+64
            for (int pb = 0; pb < npb; pb++) {
                int b0 = pb*32;
                copy32(g_h2, pb, smc + HT_OFF, tid);
                __syncthreads();
                att2_mma(htS, wdS, part2, wid, lane);
                __syncthreads();
                if (tid < 256) {
                    int m = tid >> 3, q = tid & 7;
                    float s = 0.f;
#pragma unroll
                    for (int ks = 0; ks < 16; ks++) s += part2[ks*256 + m*8 + q];
                    int col = (q < 4) ? (j*4 + q) : ((j+64)*4 + (q-4));
                    g_att2[(b0+m)*512 + col] = s;
                }
                __syncthreads();
            }
            gridbar_n(98 + t, 64);   // att2 ready among attention CTAs

            // attention
            if (t < sdl[j]) {
                int b = j;
                float* wout = out + OFF_WEIGHTS + (size_t)(b*TT + t)*PP;
                float* att = (float*)(smc + HT_OFF);
                float* s_att2 = att;
                float* s_wf   = att + 512;
                float* s_e    = att + 1024;
                float* s_red  = att + 1248;
                float* rbuf   = att + 1280;
                for (int a = tid; a < AA; a += NTHR_R) {
                    s_att2[a] = __ldcg(&g_att2[b*512 + a]) + b_dec[a];
                    s_wf[a] = W_full[a];
                }
                __syncthreads();
                const float4* s_att2v = (const float4*)s_att2;
                const float4* s_wfv   = (const float4*)s_wf;
                const float* ea = g_encatt + (size_t)b * PP * AA;
                // accumulate rows, defer reductions
                float sums[7];
                int nr = 0;
                for (int p = wid; p < PP; p += 32) {
                    const float4* row4 = (const float4*)(ea + (size_t)p * AA);
                    float sum = 0.f;
#pragma unroll
                    for (int k4 = 0; k4 < 4; k4++) {
                        int idx = lane + 32*k4;
                        float4 v = row4[idx];
                        float4 a2 = s_att2v[idx];
                        float4 wf = s_wfv[idx];
                        sum += fmaxf(v.x + a2.x, 0.f) * wf.x
                             + fmaxf(v.y + a2.y, 0.f) * wf.y
                             + fmaxf(v.z + a2.z, 0.f) * wf.z
                             + fmaxf(v.w + a2.w, 0.f) * wf.w;
                    }
                    sums[nr++] = sum;
                }
#pragma unroll 7
                for (int r = 0; r < nr; r++) {
                    float s = sums[r];
#pragma unroll
                    for (int o = 16; o; o >>= 1) s += __shfl_xor_sync(0xffffffffu, s, o);
                    if (lane == 0) s_e[wid + 32*r] = s + b_full[0];
                }
                __syncthreads();
                float m = -1e30f;
                if (tid < PP) m = s_e[tid];
#pragma unroll
                for (int o = 16; o; o >>= 1) m = fmaxf(m, __shfl_xor_sync(0xffffffffu, m, o));
                if (lane == 0) s_red[wid] = m;
                __syncthreads();
                float mx = s_red[0];
#pragma unroll
                for (int i = 1; i < 7; i++) mx = fmaxf(mx, s_red[i]);
                float ev = 0.f;
                if (tid < PP) ev = expf(s_e[tid] - mx);
                float sv = ev;
#pragma unroll
                for (int o = 16; o; o >>= 1) sv += __shfl_xor_sync(0xffffffffu, sv, o);
                __syncthreads();
                if (lane == 0) s_red[wid] = sv;
                __syncthreads();
                float tot = 0.f;
#pragma unroll
                for (int i = 0; i < 7; i++) tot += s_red[i];
                float inv = 1.f / tot;
                if (tid < PP) {
                    float al = ev * inv;
                    s_e[tid] = al;
                    wout[tid] = al;
                }
                __syncthreads();
                int hq = tid & 63, pc2 = tid >> 6;
                const float4* fb4 = (const float4*)(g_feats + (size_t)b * PP * HH);
                float4 a0 = make_float4(0,0,0,0), a1 = make_float4(0,0,0,0);
                for (int p = pc2; p < PP; p += 16) {
                    float al = s_e[p];
                    float4 v0 = fb4[p*128 + hq*2];
                    float4 v1 = fb4[p*128 + hq*2 + 1];
                    a0.x = fmaf(al, v0.x, a0.x); a0.y = fmaf(al, v0.y, a0.y);
                    a0.z = fmaf(al, v0.z, a0.z); a0.w = fmaf(al, v0.w, a0.w);
                    a1.x = fmaf(al, v1.x, a1.x); a1.y = fmaf(al, v1.y, a1.y);
                    a1.z = fmaf(al, v1.z, a1.z); a1.w = fmaf(al, v1.w, a1.w);
                }
                float* rb = rbuf + pc2*512 + hq*8;
                rb[0]=a0.x; rb[1]=a0.y; rb[2]=a0.z; rb[3]=a0.w;
                rb[4]=a1.x; rb[5]=a1.y; rb[6]=a1.z; rb[7]=a1.w;
                __syncthreads();
                if (tid < 256) {
                    int o = tid*2;
                    float s0v = 0.f, s1v = 0.f;
#pragma unroll
                    for (int q = 0; q < 16; q++) {
                        s0v += rbuf[q*512 + o];
                        s1v += rbuf[q*512 + o + 1];
                    }
                    uint32_t hp, lp;
                    cvt_hilo2(make_float2(s0v, s1v), hp, lp);
                    int pbb = b >> 5, r = b & 31, kt = o >> 5, c = o & 31;
                    char* base = g_ctx2 + pbb*65536;
                    stsw2(base + kt*2048, r, c, hp);
                    stsw2(base + (16+kt)*2048, r, c, lp);
                }
            }
        } else {
            // gates_h (2 slices), starts immediately
            int s0 = (j - 64)*2;
            for (int pb = 0; pb < npb; pb++) {
                int b0 = pb*32;
                copy32(g_h2, pb, smc + HT_OFF, tid);
                __syncthreads();
                gates_mma32(htS, whhS, part, wid, lane);
                __syncthreads();
                {
                    int o = tid;
                    int m = o >> 5, n = o & 31;
                    float s = part[o] + part[1024 + o] + part[2048 + o] + part[3072 + o];
                    int sl = s0 + (n >> 4), rr = n & 15;
                    g_gh[((b0 + m)*128 + sl)*16 + rr] = s;
                }
                __syncthreads();
            }
        }
        gridbar_n(2*t, NCTA);

        // ---- Phase C: gates_ctx (mma) + combine(g_gh, embg) + LSTM ----
        for (int pb = 0; pb < npb; pb++) {
            int b0 = pb*32;
            copy32(g_ctx2, pb, smc + HT_OFF, tid);
            __syncthreads();
            // hoisted global loads (hide under mma)
            float ghv = 0.f, egv = 0.f;
            if (tid < 512) {
                int m = tid >> 4, n = tid & 15;
                int b = b0 + m;
                int gr = 512*(n >> 2) + j*4 + (n & 3);
                ghv = __ldcg(&g_gh[(b*128 + j)*16 + n]);
                egv = g_embg[(size_t)(b*TT + t)*NG + gr];
            }
            gates_mma(htS, wihS, part, wid, lane);
            __syncthreads();
            if (tid < 512) {
                int o = tid;
                float s = 0.f;
#pragma unroll
                for (int ks = 0; ks < 8; ks++) s += part[ks*512 + o];
                int m = o >> 4, n = o & 15;
                gh[(b0 + m)*16 + n] = s + ghv + egv;
            }
            __syncthreads();
        }
        if (tid < 128) {
            int b = tid >> 1, qp = tid & 1;
            if (t < sdl[b]) {
                float hn[2];
#pragma unroll
                for (int e = 0; e < 2; e++) {
                    int q = qp*2 + e;
                    float gi = gh[b*16 + q];
                    float gf = gh[b*16 + 4 + q];
                    float gg = gh[b*16 + 8 + q];
                    float go = gh[b*16 + 12 + q];
                    float ig = 1.f / (1.f + expf(-gi));
                    float fg = 1.f / (1.f + expf(-gf));
                    float gv = tanhf(gg);
                    float og = 1.f / (1.f + expf(-go));
                    int kc = j*4 + q;
                    float c_new = fg * g_c[b*512 + kc] + ig * gv;
                    hn[e] = og * tanhf(c_new);
                    g_c[b*512 + kc] = c_new;
                }
                int kc0 = j*4 + qp*2;
                uint32_t hp, lp;
                cvt_hilo2(make_float2(hn[0], hn[1]), hp, lp);
                int pbb = b >> 5, r = b & 31, kt = kc0 >> 5, c = kc0 & 31;
                char* base = g_h2 + pbb*65536;
                stsw2(base + kt*2048, r, c, hp);
                stsw2(base + (16+kt)*2048, r, c, lp);
                *(uint32_t*)&g_hall2[(size_t)(b*TT + t)*1024 + kc0]       = hp;
                *(uint32_t*)&g_hall2[(size_t)(b*TT + t)*1024 + 512 + kc0] = lp;
            }
        }
        gridbar_n(2*t + 1, NCTA);
    }
}

// ======================= launch =======================
extern "C" void kernel_launch(void* const* d_in, const int* in_sizes, int n_in,
                              void* d_out, int out_size) {
    const float* imf     = (const float*)d_in[0];
    const int*   caps    = (const int*)  d_in[1];
    const int*   caplens = (const int*)  d_in[2];
    const float* emb     = (const float*)d_in[3];
    const float* W_ih    = (const float*)d_in[4];
    const float* W_hh    = (const float*)d_in[5];
    const float* b_ih    = (const float*)d_in[6];
    const float* b_hh    = (const float*)d_in[7];
    const float* W_enc   = (const float*)d_in[8];
    const float* b_enc   = (const float*)d_in[9];
    const float* W_dec   = (const float*)d_in[10];
    const float* b_dec   = (const float*)d_in[11];
    const float* W_full  = (const float*)d_in[12];
    const float* b_full  = (const float*)d_in[13];
    const float* W_score = (const float*)d_in[14];
    const float* b_score = (const float*)d_in[15];
    float* out = (float*)d_out;

    cudaFuncSetAttribute(k_recur, cudaFuncAttributeMaxDynamicSharedMemorySize, SM_TOTAL);

    // 1: sort + caps/declen/sortind outputs
    k_sort<<<1, BB>>>(caplens, caps, out);
    // 2: fused gathers + bf16 hi/lo conversions + zeroing + init
    k_cvt_all<<<1024, 256>>>(imf, caps, emb, W_enc, W_ih, W_score, out);
    // 3: fused enc_att + G_emb tensor-core GEMMs
    k_gemm_pair<<<792, 256>>>(b_enc, b_ih, b_hh);
    // 4: persistent recurrence
    k_recur<<<NCTA, NTHR_R, SM_TOTAL>>>(W_dec, W_hh, W_ih, b_dec, W_full, b_full, out);
    // 5: scores GEMM
    k_gemm_scores<<<dim3((BB*TT + 127)/128, (VV + 127)/128), 256>>>(b_score, out);
}

// round 17
// speedup vs baseline: 2.2620x; 1.0393x over previous
#include <cuda_runtime.h>
#include <cuda_bf16.h>
#include <cstdint>
#include <math.h>

#define BB 64
#define PP 196
#define HH 512
#define EE 512
#define AA 512
#define VV 10000
#define MAXCAP 50
#define TT 49
#define NG 2048   // 4*H

// output layout (float32): scores (B,T,V), caps_s (B,50), decode_lengths (B,), weights (B,T,P), sort_ind (B,)
#define N_SCORES   (BB*TT*VV)
#define OFF_CAPS   (N_SCORES)
#define OFF_DECLEN (OFF_CAPS + BB*MAXCAP)
#define OFF_WEIGHTS (OFF_DECLEN + BB)
#define OFF_SORT   (OFF_WEIGHTS + BB*TT*PP)

#define NCTA 128
#define NTHR 256
#define NTHR_R 1024

// ======================= scratch =======================
__device__ float g_feats[BB*PP*HH];
__device__ float g_encatt[BB*PP*AA];
__device__ float g_embg[BB*TT*NG];
__device__ float g_c[BB*HH];
__device__ float g_att2[BB*AA];
__device__ float g_gh[BB*NG];          // gates_h: [b][slice 0..127][16]
__device__ float g_e[BB*224];          // partner e-partials
__device__ int   g_sortidx[BB];
__device__ int   g_declen[BB];
__device__ int   g_nbact[TT];
__device__ int   g_act[BB*TT];
__device__ int   g_nact;
__device__ int   g_bars[160];
__device__ int   g_pbars[BB*TT];

// h/ctx in MMA-native tile format: [pb 0..1][64KB tile: hi kt 0..15, lo kt 16..31, each 32r x 64B]
__device__ __align__(16) char g_h2[131072];
__device__ __align__(16) char g_ctx2[131072];

// bf16 hi/lo packed [rows][1024]: cols 0-511 hi, 512-1023 lo
__device__ __nv_bfloat16 g_feats2[BB*PP*1024];
__device__ __nv_bfloat16 g_embT2[BB*TT*1024];
__device__ __nv_bfloat16 g_hall2[BB*TT*1024];
__device__ __nv_bfloat16 g_Wenc2[AA*1024];
__device__ __nv_bfloat16 g_Wih2[NG*1024];
__device__ __nv_bfloat16 g_Wsc2[VV*1024];

// ======================= helpers =======================
__device__ __forceinline__ void mma16816(float* d, const uint32_t* a, const uint32_t* b) {
    asm volatile("mma.sync.aligned.m16n8k16.row.col.f32.bf16.bf16.f32 "
        "{%0,%1,%2,%3}, {%4,%5,%6,%7}, {%8,%9}, {%0,%1,%2,%3};"
        : "+f"(d[0]), "+f"(d[1]), "+f"(d[2]), "+f"(d[3])
        : "r"(a[0]), "r"(a[1]), "r"(a[2]), "r"(a[3]), "r"(b[0]), "r"(b[1]));
}
__device__ __forceinline__ void ldsm_x4(uint32_t* r, uint32_t saddr) {
    asm volatile("ldmatrix.sync.aligned.m8n8.x4.shared.b16 {%0,%1,%2,%3}, [%4];"
        : "=r"(r[0]), "=r"(r[1]), "=r"(r[2]), "=r"(r[3]) : "r"(saddr));
}
__device__ __forceinline__ void ldsm_x2(uint32_t* r, uint32_t saddr) {
    asm volatile("ldmatrix.sync.aligned.m8n8.x2.shared.b16 {%0,%1}, [%2];"
        : "=r"(r[0]), "=r"(r[1]) : "r"(saddr));
}
__device__ __forceinline__ uint32_t smem_u32(const void* p) {
    return (uint32_t)__cvta_generic_to_shared(p);
}
// store bf16x2 at (r, c even 0..31) in swizzled tile (64B rows, 16B-chunk XOR)
__device__ __forceinline__ void stsw2(char* s, int r, int c, uint32_t v) {
    int byte = r*64 + ((((c >> 3) ^ ((r >> 1) & 3))) << 4) + (c & 7)*2;
    *(uint32_t*)(s + byte) = v;
}
__device__ __forceinline__ void cvt_hilo2(float2 v, uint32_t& hp, uint32_t& lp) {
    __nv_bfloat16 h0 = __float2bfloat16(v.x), h1 = __float2bfloat16(v.y);
    float l0 = v.x - __bfloat162float(h0), l1 = v.y - __bfloat162float(h1);
    __nv_bfloat16 b0 = __float2bfloat16(l0), b1 = __float2bfloat16(l1);
    hp = (uint32_t)__bfloat16_as_ushort(h0) | ((uint32_t)__bfloat16_as_ushort(h1) << 16);
    lp = (uint32_t)__bfloat16_as_ushort(b0) | ((uint32_t)__bfloat16_as_ushort(b1) << 16);
}

// ======================= prep kernels =======================
__global__ void k_sort(const int* __restrict__ caplens, const int* __restrict__ caps,
                       float* __restrict__ out) {
    __shared__ int s_sort[BB];
    if (threadIdx.x == 0) {
        int cl[BB];
        for (int i = 0; i < BB; i++) cl[i] = caplens[i];
        int r = 0;
        for (int v = MAXCAP; v >= 0 && r < BB; v--)
            for (int i = 0; i < BB; i++)
                if (cl[i] == v) { g_sortidx[r] = i; s_sort[r] = i; r++; }
        int na = 0;
        int dls[BB];
        for (int b = 0; b < BB; b++) {
            int dl = cl[g_sortidx[b]] - 1;
            dls[b] = dl;
            g_declen[b] = dl;
            out[OFF_DECLEN + b] = (float)dl;
            out[OFF_SORT + b]   = (float)g_sortidx[b];
            for (int t = 0; t < dl; t++) g_act[na++] = b*TT + t;
        }
        g_nact = na;
        for (int t = 0; t < TT; t++) {
            int c = 0;
            for (int b = 0; b < BB; b++) if (dls[b] > t) c++;
            g_nbact[t] = c;
        }
    }
    __syncthreads();
    int b = threadIdx.x;
    int src = s_sort[b];
    for (int t = 0; t < MAXCAP; t++)
        out[OFF_CAPS + b*MAXCAP + t] = (float)caps[src*MAXCAP + t];
}

// fused gather + hi/lo conversion (pairwise) + zero + init
#define P0 (BB*PP*256)
#define P1 (BB*TT*256)
#define P2 (AA*256)
#define P3 (NG*256)
#define P4 (VV*256)
#define Z5 (N_SCORES/4)
#define Z6 (BB*TT*PP/4)
#define Z7 (BB*HH)
#define Z7B (2*131072/16)
#define Z8 160
#define Z9 (BB*TT)
__global__ void k_cvt_all(const float* __restrict__ imf, const int* __restrict__ caps,
                          const float* __restrict__ emb, const float* __restrict__ W_enc,
                          const float* __restrict__ W_ih, const float* __restrict__ W_score,
                          float* __restrict__ out)
{
    const int total = P0+P1+P2+P3+P4+Z5+Z6+Z7+Z7B+Z8+Z9;
    for (int i = blockIdx.x*blockDim.x + threadIdx.x; i < total; i += gridDim.x*blockDim.x) {
        int x = i;
        if (x < P0) {
            int r = x >> 8, c2 = x & 255, k = c2*2;
            int b = r / PP, p = r - b*PP;
            float2 v = *(const float2*)(imf + ((size_t)g_sortidx[b]*PP + p)*512 + k);
            *(float2*)(g_feats + (size_t)r*512 + k) = v;
            uint32_t hp, lp; cvt_hilo2(v, hp, lp);
            ((uint32_t*)g_feats2)[(size_t)r*512 + c2] = hp;
            ((uint32_t*)g_feats2)[(size_t)r*512 + 256 + c2] = lp;
            continue;
        }
        x -= P0;
        if (x < P1) {
            int r = x >> 8, c2 = x & 255, k = c2*2;
            int b = r / TT, t = r - b*TT;
            int tok = caps[g_sortidx[b]*MAXCAP + t];
            float2 v = *(const float2*)(emb + (size_t)tok*512 + k);
            uint32_t hp, lp; cvt_hilo2(v, hp, lp);
            ((uint32_t*)g_embT2)[(size_t)r*512 + c2] = hp;
            ((uint32_t*)g_embT2)[(size_t)r*512 + 256 + c2] = lp;
            continue;
        }
        x -= P1;
        if (x < P2) {
            int r = x >> 8, c2 = x & 255, k = c2*2;
            float2 v = *(const float2*)(W_enc + (size_t)r*512 + k);
            uint32_t hp, lp; cvt_hilo2(v, hp, lp);
            ((uint32_t*)g_Wenc2)[(size_t)r*512 + c2] = hp;
            ((uint32_t*)g_Wenc2)[(size_t)r*512 + 256 + c2] = lp;
            continue;
        }
        x -= P2;
        if (x < P3) {
            int r = x >> 8, c2 = x & 255, k = c2*2;
            float2 v = *(const float2*)(W_ih + (size_t)r*1024 + k);
            uint32_t hp, lp; cvt_hilo2(v, hp, lp);
            ((uint32_t*)g_Wih2)[(size_t)r*512 + c2] = hp;
            ((uint32_t*)g_Wih2)[(size_t)r*512 + 256 + c2] = lp;
            continue;
        }
        x -= P3;
        if (x < P4) {
            int r = x >> 8, c2 = x & 255, k = c2*2;
            float2 v = *(const float2*)(W_score + (size_t)r*512 + k);
            uint32_t hp, lp; cvt_hilo2(v, hp, lp);
            ((uint32_t*)g_Wsc2)[(size_t)r*512 + c2] = hp;
            ((uint32_t*)g_Wsc2)[(size_t)r*512 + 256 + c2] = lp;
            continue;
        }
        x -= P4;
        if (x < Z5) {
            // zero only inactive (b,t) score rows; active rows fully overwritten by scores GEMM
            int row = x / (VV/4);
            int b = row / TT, t = row - b*TT;
            if (t >= g_declen[b])
                ((float4*)out)[x] = make_float4(0.f, 0.f, 0.f, 0.f);
            continue;
        }
        x -= Z5;
        if (x < Z6) {
            ((float4*)(out + OFF_WEIGHTS))[x] = make_float4(0.f, 0.f, 0.f, 0.f);
            continue;
        }
        x -= Z6;
        if (x < Z7) { g_c[x] = 0.f; continue; }
        x -= Z7;
        if (x < Z7B) {
            uint4 z = make_uint4(0,0,0,0);
            if (x < 131072/16) ((uint4*)g_h2)[x] = z;
            else ((uint4*)g_ctx2)[x - 131072/16] = z;
            continue;
        }
        x -= Z7B;
        if (x < Z8) { g_bars[x] = 0; continue; }
        x -= Z8;
        g_pbars[x] = 0;
    }
}

// ======================= mma.sync bf16x3 GEMM body (ldmatrix + double buffer) ==========
__device__ __forceinline__ void hgemm_body(
    int bm, int bn,
    const __nv_bfloat16* __restrict__ A2, const __nv_bfloat16* __restrict__ B2,
    int M, int N, int ldc,
    const float* __restrict__ bias1, const float* __restrict__ bias2,
    float* __restrict__ C, const int* __restrict__ rowmap, int use_nact,
    __nv_bfloat16 (*As)[128*32], __nv_bfloat16 (*Bs)[128*32])
{
    int tid = threadIdx.x;
    int Ml = use_nact ? g_nact : M;
    if (bm*128 >= Ml) return;

    int lrow = tid >> 1;
    int lc0 = (tid & 1) * 2;
    int gm = bm*128 + lrow;
    const uint4* arow = nullptr;
    if (gm < Ml) { int r = rowmap ? rowmap[gm] : gm; arow = (const uint4*)(A2 + (size_t)r*1024); }
    int gn = bn*128 + lrow;
    const uint4* brow = (gn < N) ? (const uint4*)(B2 + (size_t)gn*1024) : nullptr;

    int swz = (lrow >> 1) & 3;
    uint4* aswp[2] = {(uint4*)(As[0] + lrow*32), (uint4*)(As[1] + lrow*32)};
    uint4* bswp[2] = {(uint4*)(Bs[0] + lrow*32), (uint4*)(Bs[1] + lrow*32)};
    int c0 = lc0 ^ swz, c1 = (lc0+1) ^ swz;

    int lane = tid & 31, wid = tid >> 5;
    int wm = (wid >> 2) * 64;
    int wn = (wid & 3) * 32;
    int gq = lane >> 2, tg = lane & 3;

    int rA = wm + (lane & 15);
    int swzA = (rA >> 1) & 3;
    int hiA = lane >> 4;
    int rB = wn + (lane & 7);
    int swzB = (rB >> 1) & 3;
    int hiB = (lane >> 3) & 1;
    uint32_t aS[2] = {smem_u32(As[0]) + rA*64, smem_u32(As[1]) + rA*64};
    uint32_t bS[2] = {smem_u32(Bs[0]) + rB*64, smem_u32(Bs[1]) + rB*64};

    float acc[4][4][4];
#pragma unroll
    for (int mt = 0; mt < 4; mt++)
#pragma unroll
        for (int nt = 0; nt < 4; nt++)
#pragma unroll
            for (int r = 0; r < 4; r++) acc[mt][nt][r] = 0.f;

    const uint4 z = make_uint4(0,0,0,0);
    const int kau4[3] = {0, 0, 64};
    const int kbu4[3] = {0, 64, 0};
    uint4 pa0 = arow ? arow[lc0]   : z;
    uint4 pa1 = arow ? arow[lc0+1] : z;
    uint4 pb0 = brow ? brow[lc0]   : z;
    uint4 pb1 = brow ? brow[lc0+1] : z;
    aswp[0][c0] = pa0; aswp[0][c1] = pa1;
    bswp[0][c0] = pb0; bswp[0][c1] = pb1;
    __syncthreads();

    for (int ci = 0; ci < 48; ci++) {
        int cur = ci & 1;
        if (ci + 1 < 48) {
            int term = (ci+1) >> 4, kc = (ci+1) & 15;
            int ab = kau4[term] + kc*4, bb = kbu4[term] + kc*4;
            pa0 = arow ? arow[ab + lc0]   : z;
            pa1 = arow ? arow[ab + lc0+1] : z;
            pb0 = brow ? brow[bb + lc0]   : z;
            pb1 = brow ? brow[bb + lc0+1] : z;
        }
#pragma unroll
        for (int kk = 0; kk < 2; kk++) {
            uint32_t cA = (uint32_t)(((2*kk + hiA) ^ swzA) << 4);
            uint32_t cB = (uint32_t)(((2*kk + hiB) ^ swzB) << 4);
            uint32_t afr[4][4];
#pragma unroll
            for (int mt = 0; mt < 4; mt++)
                ldsm_x4(afr[mt], aS[cur] + mt*1024 + cA);
            uint32_t bfr[4][2];
#pragma unroll
            for (int nt = 0; nt < 4; nt++)
                ldsm_x2(bfr[nt], bS[cur] + nt*512 + cB);
#pragma unroll
            for (int mt = 0; mt < 4; mt++)
#pragma unroll
                for (int nt = 0; nt < 4; nt++)
                    mma16816(acc[mt][nt], afr[mt], bfr[nt]);
        }
        if (ci + 1 < 48) {
            int nxt = cur ^ 1;
            aswp[nxt][c0] = pa0; aswp[nxt][c1] = pa1;
            bswp[nxt][c0] = pb0; bswp[nxt][c1] = pb1;
        }
        __syncthreads();
    }

#pragma unroll
    for (int mt = 0; mt < 4; mt++) {
        int m0 = bm*128 + wm + mt*16 + gq;
        int m1 = m0 + 8;
        size_t row0 = 0, row1 = 0;
        bool v0 = m0 < Ml, v1 = m1 < Ml;
        if (v0) row0 = (size_t)(rowmap ? rowmap[m0] : m0);
        if (v1) row1 = (size_t)(rowmap ? rowmap[m1] : m1);
#pragma unroll
        for (int nt = 0; nt < 4; nt++) {
            int col = bn*128 + wn + nt*8 + tg*2;
            if (col >= N) continue;
            float bx = bias1[col], by = bias1[col+1];
            if (bias2) { bx += bias2[col]; by += bias2[col+1]; }
            if (v0) {
                float2 o = make_float2(acc[mt][nt][0] + bx, acc[mt][nt][1] + by);
                *(float2*)(C + row0*(size_t)ldc + col) = o;
            }
            if (v1) {
                float2 o = make_float2(acc[mt][nt][2] + bx, acc[mt][nt][3] + by);
                *(float2*)(C + row1*(size_t)ldc + col) = o;
            }
        }
    }
}

__global__ __launch_bounds__(256)
void k_gemm_pair(const float* __restrict__ b_enc, const float* __restrict__ b_ih,
                 const float* __restrict__ b_hh)
{
    __shared__ __align__(16) __nv_bfloat16 As[2][128*32];
    __shared__ __align__(16) __nv_bfloat16 Bs[2][128*32];
    int idx = blockIdx.x;
    if (idx < 392) {
        hgemm_body(idx >> 2, idx & 3, g_feats2, g_Wenc2, BB*PP, AA, AA,
                   b_enc, nullptr, g_encatt, nullptr, 0, As, Bs);
    } else {
        idx -= 392;
        hgemm_body(idx >> 4, idx & 15, g_embT2, g_Wih2, BB*TT, NG, NG,
                   b_ih, b_hh, g_embg, g_act, 1, As, Bs);
    }
}

__global__ __launch_bounds__(256)
void k_gemm_scores(const float* __restrict__ b_score, float* __restrict__ out)
{
    __shared__ __align__(16) __nv_bfloat16 As[2][128*32];
    __shared__ __align__(16) __nv_bfloat16 Bs[2][128*32];
    hgemm_body(blockIdx.x, blockIdx.y, g_hall2, g_Wsc2, BB*TT, VV, VV,
               b_score, nullptr, out, g_act, 1, As, Bs);
}

// ======================= fused persistent recurrence (1024 threads) =======================
// smem byte offsets
#define WIHC_OFF 0
#define WDEC_OFF 32768
#define WHH_OFF  49152
#define HT_OFF   114688
#define PART_OFF 180224
#define GH_OFF   196608
#define SM_TOTAL 200704

// flat per-slot barrier (replay-safe), tight spin; cnt = arrival count
__device__ __forceinline__ void gridbar_n(int slot, int cnt) {
    __syncthreads();
    if (threadIdx.x == 0) {
        int* p = &g_bars[slot];
        asm volatile("red.release.gpu.global.add.s32 [%0], 1;" :: "l"(p) : "memory");
        int v;
        do {
            asm volatile("ld.acquire.gpu.global.s32 %0, [%1];" : "=r"(v) : "l"(p) : "memory");
        } while (v < cnt);
    }
    __syncthreads();
}

// copy one 64KB tile (pb) from tile-format global to smem HT — pure 16B copies
__device__ __forceinline__ void copy32(const char* __restrict__ srcTiles, int pb,
                                       char* HTp, int tid) {
    const uint4* src = (const uint4*)(srcTiles + pb*65536);
    uint4* dst = (uint4*)HTp;
#pragma unroll
    for (int i = 0; i < 4; i++) {
        int o = tid + i*NTHR_R;
        dst[o] = __ldcg(src + o);
    }
}

// gates_ctx mma (32 warps): M=32, N=16 (slice j), K split 8 -> part[8][32][16]
__device__ __forceinline__ void gates_mma(uint32_t htA, uint32_t wbB, float* part,
                                          int wid, int lane) {
    int gq = lane >> 2, tg = lane & 3;
    int mh = (wid & 1)*16, nh = ((wid >> 1) & 1)*8, ks = wid >> 2;   // ks 0..7
    int rA = mh + (lane & 15);
    int swzA = (rA >> 1) & 3;
    int hiA = lane >> 4;
    int rB = nh + (lane & 7);
    int swzB = (rB >> 1) & 3;
    int hiB = (lane >> 3) & 1;
    uint32_t aL = htA + rA*64;
    uint32_t bL = wbB + rB*64;
    float acc[4] = {0.f, 0.f, 0.f, 0.f};
    for (int kt = ks*2; kt < ks*2 + 2; kt++) {
        uint32_t ah = aL + kt*2048;
        uint32_t bh = bL + kt*1024;
#pragma unroll
        for (int kk = 0; kk < 2; kk++) {
            uint32_t cA = (uint32_t)(((2*kk + hiA) ^ swzA) << 4);
            uint32_t cB = (uint32_t)(((2*kk + hiB) ^ swzB) << 4);
            uint32_t Ah[4], Al[4], Bh[2], Bl[2];
            ldsm_x4(Ah, ah + cA);
            ldsm_x4(Al, ah + 32768 + cA);
            ldsm_x2(Bh, bh + cB);
            ldsm_x2(Bl, bh + 16384 + cB);
            mma16816(acc, Ah, Bh);
            mma16816(acc, Ah, Bl);
            mma16816(acc, Al, Bh);
        }
    }
    int m0 = mh + gq, n0 = nh + tg*2;
    part[ks*512 + m0*16 + n0]       = acc[0];
    part[ks*512 + m0*16 + n0+1]     = acc[1];
    part[ks*512 + (m0+8)*16 + n0]   = acc[2];
    part[ks*512 + (m0+8)*16 + n0+1] = acc[3];
}

// gates_h mma for 2 slices (32 warps): M=32, N=32 rows, K split 4 -> part[4][32][32]
__device__ __forceinline__ void gates_mma32(uint32_t htA, uint32_t whB, float* part,
                                            int wid, int lane) {
    int gq = lane >> 2, tg = lane & 3;
    int mh = (wid & 1)*16, nh = ((wid >> 1) & 3)*8, ks = wid >> 3;   // ks 0..3
    int rA = mh + (lane & 15);
    int swzA = (rA >> 1) & 3;
    int hiA = lane >> 4;
    int rB = nh + (lane & 7);
    int swzB = (rB >> 1) & 3;
    int hiB = (lane >> 3) & 1;
    uint32_t aL = htA + rA*64;
    uint32_t bL = whB + rB*64;
    float acc[4] = {0.f, 0.f, 0.f, 0.f};
    for (int kt = ks*4; kt < ks*4 + 4; kt++) {
        uint32_t ah = aL + kt*2048;
        uint32_t bh = bL + kt*2048;
#pragma unroll
        for (int kk = 0; kk < 2; kk++) {
            uint32_t cA = (uint32_t)(((2*kk + hiA) ^ swzA) << 4);
            uint32_t cB = (uint32_t)(((2*kk + hiB) ^ swzB) << 4);
            uint32_t Ah[4], Al[4], Bh[2], Bl[2];
            ldsm_x4(Ah, ah + cA);
            ldsm_x4(Al, ah + 32768 + cA);
            ldsm_x2(Bh, bh + cB);
            ldsm_x2(Bl, bh + 32768 + cB);
            mma16816(acc, Ah, Bh);
            mma16816(acc, Ah, Bl);
            mma16816(acc, Al, Bh);
        }
    }
    int m0 = mh + gq, n0 = nh + tg*2;
    part[ks*1024 + m0*32 + n0]       = acc[0];
    part[ks*1024 + m0*32 + n0+1]     = acc[1];
    part[ks*1024 + (m0+8)*32 + n0]   = acc[2];
    part[ks*1024 + (m0+8)*32 + n0+1] = acc[3];
}

// att2 mma (32 warps): M=32, N=8 (ALL 8 rows real: slices j and j+64), K split 16
__device__ __forceinline__ void att2_mma(uint32_t htA, uint32_t wdB, float* part2,
                                         int wid, int lane) {
    int gq = lane >> 2, tg = lane & 3;
    int mh = (wid & 1)*16, ks = wid >> 1;   // ks 0..15
    int rA = mh + (lane & 15);
    int swzA = (rA >> 1) & 3;
    int hiA = lane >> 4;
    int rB = lane & 7;
    int swzB = (rB >> 1) & 3;
    int hiB = (lane >> 3) & 1;
    uint32_t aL = htA + rA*64;
    uint32_t bL = wdB + rB*64;
    float acc[4] = {0.f, 0.f, 0.f, 0.f};
    {
        int kt = ks;
        uint32_t ah = aL + kt*2048;
        uint32_t bh = bL + kt*512;
#pragma unroll
        for (int kk = 0; kk < 2; kk++) {
            uint32_t cA = (uint32_t)(((2*kk + hiA) ^ swzA) << 4);
            uint32_t cB = (uint32_t)(((2*kk + hiB) ^ swzB) << 4);
            uint32_t Ah[4], Al[4], Bh[2], Bl[2];
            ldsm_x4(Ah, ah + cA);
            ldsm_x4(Al, ah + 32768 + cA);
            ldsm_x2(Bh, bh + cB);
            ldsm_x2(Bl, bh + 8192 + cB);
            mma16816(acc, Ah, Bh);
            mma16816(acc, Ah, Bl);
            mma16816(acc, Al, Bh);
        }
    }
    int m0 = mh + gq, n0 = tg*2;
    part2[ks*256 + m0*8 + n0]       = acc[0];
    part2[ks*256 + m0*8 + n0+1]     = acc[1];
    part2[ks*256 + (m0+8)*8 + n0]   = acc[2];
    part2[ks*256 + (m0+8)*8 + n0+1] = acc[3];
}

__global__ __launch_bounds__(NTHR_R)
void k_recur(const float* __restrict__ W_dec, const float* __restrict__ W_hh,
             const float* __restrict__ W_ih,
             const float* __restrict__ b_dec, const float* __restrict__ W_full,
             const float* __restrict__ b_full, float* __restrict__ out)
{
    extern __shared__ float sm[];
    char* smc = (char*)sm;
    __shared__ int sdl[BB];
    __shared__ int snb[TT];
    int tid = threadIdx.x, lane = tid & 31, wid = tid >> 5;
    int j = blockIdx.x;

    if (tid < BB) sdl[tid] = g_declen[tid];
    if (tid >= 64 && tid < 64 + TT) snb[tid - 64] = g_nbact[tid - 64];

    // WIHC slice j (all CTAs)
    for (int i = tid; i < 16*256; i += NTHR_R) {
        int r = i >> 8, kp = i & 255, k = kp*2;
        int gr = 512*(r >> 2) + j*4 + (r & 3);
        float2 w2 = *(const float2*)(W_ih + (size_t)gr*1024 + 512 + k);
        uint32_t hp, lp;
        int kt = k >> 5, c = k & 31;
        cvt_hilo2(w2, hp, lp);
        stsw2(smc + WIHC_OFF + kt*1024, r, c, hp);
        stsw2(smc + WIHC_OFF + (16+kt)*1024, r, c, lp);
    }
    // WDEC 8 rows: slices j and j+64 (CTAs 0..63 only)
    if (j < 64) {
        for (int i = tid; i < 8*256; i += NTHR_R) {
            int r = i >> 8, kp = i & 255, k = kp*2;
            int gr = (r < 4) ? (j*4 + r) : ((j+64)*4 + (r-4));
            float2 w = *(const float2*)(W_dec + (size_t)gr*512 + k);
            uint32_t hp, lp;
            cvt_hilo2(w, hp, lp);
            int kt = k >> 5, c = k & 31;
            stsw2(smc + WDEC_OFF + kt*512, r, c, hp);
            stsw2(smc + WDEC_OFF + (16+kt)*512, r, c, lp);
        }
    }
    // WHH 2 slices (CTAs 64..127 only)
    if (j >= 64) {
        int s0 = (j - 64)*2;
        for (int i = tid; i < 32*256; i += NTHR_R) {
            int r = i >> 8, kp = i & 255, k = kp*2;
            int s = s0 + (r >> 4), rr = r & 15;
            int gr = 512*(rr >> 2) + s*4 + (rr & 3);
            float2 w1 = *(const float2*)(W_hh + (size_t)gr*512 + k);
            uint32_t hp, lp;
            int kt = k >> 5, c = k & 31;
            cvt_hilo2(w1, hp, lp);
            stsw2(smc + WHH_OFF + kt*2048, r, c, hp);
            stsw2(smc + WHH_OFF + 32768 + kt*2048, r, c, lp);
        }
    }
    __syncthreads();

    float* part  = (float*)(smc + PART_OFF);
    float* part2 = part;
    float* gh    = (float*)(smc + GH_OFF);
    uint32_t htS  = smem_u32(smc + HT_OFF);
    uint32_t wihS = smem_u32(smc + WIHC_OFF);
    uint32_t whhS = smem_u32(smc + WHH_OFF);
    uint32_t wdS  = smem_u32(smc + WDEC_OFF);

    for (int t = 0; t < TT; t++) {
        int npb = (snb[t] + 31) >> 5;
        // ---- Phase A: att2 on CTAs 0..63 ----
        if (j < 64) {
            for (int pb = 0; pb < npb; pb++) {
                int b0 = pb*32;
                copy32(g_h2, pb, smc + HT_OFF, tid);
                __syncthreads();
                att2_mma(htS, wdS, part2, wid, lane);
                __syncthreads();
                if (tid < 256) {
                    int m = tid >> 3, q = tid & 7;
                    float s = 0.f;
#pragma unroll
                    for (int ks = 0; ks < 16; ks++) s += part2[ks*256 + m*8 + q];
                    int col = (q < 4) ? (j*4 + q) : ((j+64)*4 + (q-4));
                    g_att2[(b0+m)*512 + col] = s;
                }
                __syncthreads();
            }
        }
        gridbar_n(98 + t, NCTA);   // att2 ready for all

        // ---- Phase B: attention e-split + ctx (j<64) || e-partial then gates_h (j>=64) ----
        if (j < 64) {
            if (t < sdl[j]) {
                int b = j;
                float* wout = out + OFF_WEIGHTS + (size_t)(b*TT + t)*PP;
                float* att = (float*)(smc + HT_OFF);
                float* s_att2 = att;
                float* s_wf   = att + 512;
                float* s_e    = att + 1024;
                float* s_red  = att + 1248;
                float* rbuf   = att + 1280;
                for (int a = tid; a < AA; a += NTHR_R) {
                    s_att2[a] = __ldcg(&g_att2[b*512 + a]) + b_dec[a];
                    s_wf[a] = W_full[a];
                }
                __syncthreads();
                const float4* s_att2v = (const float4*)s_att2;
                const float4* s_wfv   = (const float4*)s_wf;
                const float* ea = g_encatt + (size_t)b * PP * AA;
                // e over features [0,256) only; deferred reductions
                float sums[7];
                int nr = 0;
                for (int p = wid; p < PP; p += 32) {
                    const float4* row4 = (const float4*)(ea + (size_t)p * AA);
                    float sum = 0.f;
#pragma unroll
                    for (int k4 = 0; k4 < 2; k4++) {
                        int idx = lane + 32*k4;
                        float4 v = row4[idx];
                        float4 a2 = s_att2v[idx];
                        float4 wf = s_wfv[idx];
                        sum += fmaxf(v.x + a2.x, 0.f) * wf.x
                             + fmaxf(v.y + a2.y, 0.f) * wf.y
                             + fmaxf(v.z + a2.z, 0.f) * wf.z
                             + fmaxf(v.w + a2.w, 0.f) * wf.w;
                    }
                    sums[nr++] = sum;
                }
#pragma unroll 7
                for (int r = 0; r < nr; r++) {
                    float s = sums[r];
#pragma unroll
                    for (int o = 16; o; o >>= 1) s += __shfl_xor_sync(0xffffffffu, s, o);
                    if (lane == 0) s_e[wid + 32*r] = s;
                }
                __syncthreads();
                // wait for partner's e-partials
                if (tid == 0) {
                    int* pp = &g_pbars[t*BB + b];
                    int v;
                    do {
                        asm volatile("ld.acquire.gpu.global.s32 %0, [%1];" : "=r"(v) : "l"(pp) : "memory");
                    } while (v < 1);
                }
                __syncthreads();
                float m = -1e30f;
                if (tid < PP) {
                    float e = s_e[tid] + __ldcg(&g_e[b*224 + tid]) + b_full[0];
                    s_e[tid] = e;
                    m = e;
                }
#pragma unroll
                for (int o = 16; o; o >>= 1) m = fmaxf(m, __shfl_xor_sync(0xffffffffu, m, o));
                if (lane == 0) s_red[wid] = m;
                __syncthreads();
                float mx = s_red[0];
#pragma unroll
                for (int i = 1; i < 7; i++) mx = fmaxf(mx, s_red[i]);
                float ev = 0.f;
                if (tid < PP) ev = expf(s_e[tid] - mx);
                float sv = ev;
#pragma unroll
                for (int o = 16; o; o >>= 1) sv += __shfl_xor_sync(0xffffffffu, sv, o);
                __syncthreads();
                if (lane == 0) s_red[wid] = sv;
                __syncthreads();
                float tot = 0.f;
#pragma unroll
                for (int i = 0; i < 7; i++) tot += s_red[i];
                float inv = 1.f / tot;
                if (tid < PP) {
                    float al = ev * inv;
                    s_e[tid] = al;
                    wout[tid] = al;
                }
                __syncthreads();
                int hq = tid & 63, pc2 = tid >> 6;
                const float4* fb4 = (const float4*)(g_feats + (size_t)b * PP * HH);
                float4 a0 = make_float4(0,0,0,0), a1 = make_float4(0,0,0,0);
                for (int p = pc2; p < PP; p += 16) {
                    float al = s_e[p];
                    float4 v0 = fb4[p*128 + hq*2];
                    float4 v1 = fb4[p*128 + hq*2 + 1];
                    a0.x = fmaf(al, v0.x, a0.x); a0.y = fmaf(al, v0.y, a0.y);
                    a0.z = fmaf(al, v0.z, a0.z); a0.w = fmaf(al, v0.w, a0.w);
                    a1.x = fmaf(al, v1.x, a1.x); a1.y = fmaf(al, v1.y, a1.y);
                    a1.z = fmaf(al, v1.z, a1.z); a1.w = fmaf(al, v1.w, a1.w);
                }
                float* rb = rbuf + pc2*512 + hq*8;
                rb[0]=a0.x; rb[1]=a0.y; rb[2]=a0.z; rb[3]=a0.w;
                rb[4]=a1.x; rb[5]=a1.y; rb[6]=a1.z; rb[7]=a1.w;
                __syncthreads();
                if (tid < 256) {
                    int o = tid*2;
                    float s0v = 0.f, s1v = 0.f;
#pragma unroll
                    for (int q = 0; q < 16; q++) {
                        s0v += rbuf[q*512 + o];
                        s1v += rbuf[q*512 + o + 1];
                    }
                    uint32_t hp, lp;
                    cvt_hilo2(make_float2(s0v, s1v), hp, lp);
                    int pbb = b >> 5, r = b & 31, kt = o >> 5, c = o & 31;
                    char* base = g_ctx2 + pbb*65536;
                    stsw2(base + kt*2048, r, c, hp);
                    stsw2(base + (16+kt)*2048, r, c, lp);
                }
            }
        } else {
            int b2 = j - 64;
            // e-partial over features [256,512) for partner b2
            if (t < sdl[b2]) {
                float* att = (float*)(smc + HT_OFF);
                float* s_att2 = att;
                float* s_wf   = att + 512;
                for (int a = tid; a < AA; a += NTHR_R) {
                    s_att2[a] = __ldcg(&g_att2[b2*512 + a]) + b_dec[a];
                    s_wf[a] = W_full[a];
                }
                __syncthreads();
                const float4* s_att2v = (const float4*)s_att2;
                const float4* s_wfv   = (const float4*)s_wf;
                const float* ea = g_encatt + (size_t)b2 * PP * AA;
                float sums[7];
                int nr = 0;
                for (int p = wid; p < PP; p += 32) {
                    const float4* row4 = (const float4*)(ea + (size_t)p * AA);
                    float sum = 0.f;
#pragma unroll
                    for (int k4 = 2; k4 < 4; k4++) {
                        int idx = lane + 32*k4;
                        float4 v = row4[idx];
                        float4 a2 = s_att2v[idx];
                        float4 wf = s_wfv[idx];
                        sum += fmaxf(v.x + a2.x, 0.f) * wf.x
                             + fmaxf(v.y + a2.y, 0.f) * wf.y
                             + fmaxf(v.z + a2.z, 0.f) * wf.z
                             + fmaxf(v.w + a2.w, 0.f) * wf.w;
                    }
                    sums[nr++] = sum;
                }
#pragma unroll 7
                for (int r = 0; r < nr; r++) {
                    float s = sums[r];
#pragma unroll
                    for (int o = 16; o; o >>= 1) s += __shfl_xor_sync(0xffffffffu, s, o);
                    if (lane == 0) g_e[b2*224 + wid + 32*r] = s;
                }
                __syncthreads();
                if (tid == 0) {
                    int* pp = &g_pbars[t*BB + b2];
                    asm volatile("red.release.gpu.global.add.s32 [%0], 1;" :: "l"(pp) : "memory");
                }
            }
            // gates_h (2 slices)
            int s0 = (j - 64)*2;
            for (int pb = 0; pb < npb; pb++) {
                int b0 = pb*32;
                copy32(g_h2, pb, smc + HT_OFF, tid);
                __syncthreads();
                gates_mma32(htS, whhS, part, wid, lane);
                __syncthreads();
                {
                    int o = tid;
                    int m = o >> 5, n = o & 31;
                    float s = part[o] + part[1024 + o] + part[2048 + o] + part[3072 + o];
                    int sl = s0 + (n >> 4), rr = n & 15;
                    g_gh[((b0 + m)*128 + sl)*16 + rr] = s;
                }
                __syncthreads();
            }
        }
        gridbar_n(2*t, NCTA);

        // ---- Phase C: gates_ctx (mma) + combine(g_gh, embg) + LSTM ----
        for (int pb = 0; pb < npb; pb++) {
            int b0 = pb*32;
            copy32(g_ctx2, pb, smc + HT_OFF, tid);
            __syncthreads();
            // hoisted global loads (hide under mma)
            float ghv = 0.f, egv = 0.f;
            if (tid < 512) {
                int m = tid >> 4, n = tid & 15;
                int b = b0 + m;
                int gr = 512*(n >> 2) + j*4 + (n & 3);
                ghv = __ldcg(&g_gh[(b*128 + j)*16 + n]);
                egv = g_embg[(size_t)(b*TT + t)*NG + gr];
            }
            gates_mma(htS, wihS, part, wid, lane);
            __syncthreads();
            if (tid < 512) {
                int o = tid;
                float s = 0.f;
#pragma unroll
                for (int ks = 0; ks < 8; ks++) s += part[ks*512 + o];
                int m = o >> 4, n = o & 15;
                gh[(b0 + m)*16 + n] = s + ghv + egv;
            }
            __syncthreads();
        }
        if (tid < 128) {
            int b = tid >> 1, qp = tid & 1;
            if (t < sdl[b]) {
                float hn[2];
#pragma unroll
                for (int e = 0; e < 2; e++) {
                    int q = qp*2 + e;
                    float gi = gh[b*16 + q];
                    float gf = gh[b*16 + 4 + q];
                    float gg = gh[b*16 + 8 + q];
                    float go = gh[b*16 + 12 + q];
                    float ig = 1.f / (1.f + expf(-gi));
                    float fg = 1.f / (1.f + expf(-gf));
                    float gv = tanhf(gg);
                    float og = 1.f / (1.f + expf(-go));
                    int kc = j*4 + q;
                    float c_new = fg * g_c[b*512 + kc] + ig * gv;
                    hn[e] = og * tanhf(c_new);
                    g_c[b*512 + kc] = c_new;
                }
                int kc0 = j*4 + qp*2;
                uint32_t hp, lp;
                cvt_hilo2(make_float2(hn[0], hn[1]), hp, lp);
                int pbb = b >> 5, r = b & 31, kt = kc0 >> 5, c = kc0 & 31;
                char* base = g_h2 + pbb*65536;
                stsw2(base + kt*2048, r, c, hp);
                stsw2(base + (16+kt)*2048, r, c, lp);
                *(uint32_t*)&g_hall2[(size_t)(b*TT + t)*1024 + kc0]       = hp;
                *(uint32_t*)&g_hall2[(size_t)(b*TT + t)*1024 + 512 + kc0] = lp;
            }
        }
        gridbar_n(2*t + 1, NCTA);
    }
}

// ======================= launch =======================
extern "C" void kernel_launch(void* const* d_in, const int* in_sizes, int n_in,
                              void* d_out, int out_size) {
    const float* imf     = (const float*)d_in[0];
    const int*   caps    = (const int*)  d_in[1];
    const int*   caplens = (const int*)  d_in[2];
    const float* emb     = (const float*)d_in[3];
    const float* W_ih    = (const float*)d_in[4];
    const float* W_hh    = (const float*)d_in[5];
    const float* b_ih    = (const float*)d_in[6];
    const float* b_hh    = (const float*)d_in[7];
    const float* W_enc   = (const float*)d_in[8];
    const float* b_enc   = (const float*)d_in[9];
    const float* W_dec   = (const float*)d_in[10];
    const float* b_dec   = (const float*)d_in[11];
    const float* W_full  = (const float*)d_in[12];
    const float* b_full  = (const float*)d_in[13];
    const float* W_score = (const float*)d_in[14];
    const float* b_score = (const float*)d_in[15];
    float* out = (float*)d_out;

    cudaFuncSetAttribute(k_recur, cudaFuncAttributeMaxDynamicSharedMemorySize, SM_TOTAL);

    // 1: sort + caps/declen/sortind outputs
    k_sort<<<1, BB>>>(caplens, caps, out);
    // 2: fused gathers + bf16 hi/lo conversions + zeroing + init
    k_cvt_all<<<1024, 256>>>(imf, caps, emb, W_enc, W_ih, W_score, out);
    // 3: fused enc_att + G_emb tensor-core GEMMs
    k_gemm_pair<<<792, 256>>>(b_enc, b_ih, b_hh);
    // 4: persistent recurrence (pair-split e computation)
    k_recur<<<NCTA, NTHR_R, SM_TOTAL>>>(W_dec, W_hh, W_ih, b_dec, W_full, b_full, out);
    // 5: scores GEMM
    k_gemm_scores<<<dim3((BB*TT + 127)/128, (VV + 127)/128), 256>>>(b_score, out);
}